// round 1
// baseline (speedup 1.0000x reference)
#include <cuda_runtime.h>
#include <math.h>

// ---------------- problem constants ----------------
constexpr int NN   = 32768;    // total nodes layer1
constexpr int ED   = 262144;   // edges
constexpr int FD   = 256;      // feature dim (4 heads x 64)
constexpr int BT   = 32;       // graphs
constexpr int NPG  = 1024;
constexpr int KP1  = 512;
constexpr int KP2  = 256;
constexpr int N2   = BT * KP1; // 16384 pooled nodes after pool1
constexpr int INDIM = 128;

// ---------------- scratch layout (floats) ----------------
constexpr size_t O_H1    = 0;
constexpr size_t O_OUT1  = O_H1   + (size_t)NN * FD;
constexpr size_t O_ASN1  = O_OUT1 + (size_t)NN * FD;
constexpr size_t O_ADN1  = O_ASN1 + (size_t)NN * 4;
constexpr size_t O_DEN1  = O_ADN1 + (size_t)NN * 4;
constexpr size_t O_PE1   = O_DEN1 + (size_t)NN * 4;
constexpr size_t O_BNS1  = O_PE1  + (size_t)(ED + NN) * 4;
constexpr size_t O_SC1   = O_BNS1 + 512;
constexpr size_t O_SH1   = O_SC1  + 256;
constexpr size_t O_PWN1  = O_SH1  + 256;
constexpr size_t O_SCORE1= O_PWN1 + 256;
constexpr size_t O_TANH1 = O_SCORE1 + NN;
constexpr size_t O_XP1   = O_TANH1  + N2;
constexpr size_t O_X1G   = O_XP1    + (size_t)N2 * FD;
constexpr size_t O_H2    = O_X1G    + (size_t)BT * 512;
constexpr size_t O_OUT2  = O_H2     + (size_t)N2 * FD;
constexpr size_t O_ASN2  = O_OUT2   + (size_t)N2 * FD;
constexpr size_t O_ADN2  = O_ASN2   + (size_t)N2 * 4;
constexpr size_t O_DEN2  = O_ADN2   + (size_t)N2 * 4;
constexpr size_t O_PE2   = O_DEN2   + (size_t)N2 * 4;
constexpr size_t O_BNS2  = O_PE2    + (size_t)(ED + N2) * 4;
constexpr size_t O_SC2   = O_BNS2   + 512;
constexpr size_t O_SH2   = O_SC2    + 256;
constexpr size_t O_PWN2  = O_SH2    + 256;
constexpr size_t O_SCORE2= O_PWN2   + 256;
constexpr size_t O_TANH2 = O_SCORE2 + N2;
constexpr size_t O_X2G   = O_TANH2  + (size_t)BT * KP2;
constexpr size_t F_TOTAL = O_X2G    + (size_t)BT * 512;

__device__ float g_f[F_TOTAL];

constexpr size_t IO_GIDX1 = 0;
constexpr size_t IO_INV1  = IO_GIDX1 + N2;
constexpr size_t IO_GIDX2 = IO_INV1  + NN;
constexpr size_t I_TOTAL  = IO_GIDX2 + (size_t)BT * KP2;

__device__ int g_i[I_TOTAL];

// ---------------- helpers ----------------
__device__ __forceinline__ void red_add_v4(float* p, float4 v) {
    asm volatile("red.global.add.v4.f32 [%0], {%1,%2,%3,%4};"
                 :: "l"(p), "f"(v.x), "f"(v.y), "f"(v.z), "f"(v.w) : "memory");
}

// ---------------- SGEMM: C[MxN] = A[MxK] @ B[KxN], 128x128 tile, 8x8/thread ----------------
__global__ __launch_bounds__(256) void sgemm128(const float* __restrict__ A,
                                                const float* __restrict__ B,
                                                float* __restrict__ C,
                                                int M, int N, int K) {
    __shared__ float As[8][132];
    __shared__ float Bs[8][132];
    int tid = threadIdx.x;
    int tx = tid & 15, ty = tid >> 4;
    int m0 = blockIdx.y * 128, n0 = blockIdx.x * 128;
    int arow = tid >> 1, ac4 = (tid & 1) * 4;
    int brow = tid >> 5, bc4 = (tid & 31) * 4;
    float acc[8][8];
#pragma unroll
    for (int i = 0; i < 8; i++)
#pragma unroll
        for (int j = 0; j < 8; j++) acc[i][j] = 0.f;

    for (int k0 = 0; k0 < K; k0 += 8) {
        float4 a = *(const float4*)(A + (size_t)(m0 + arow) * K + k0 + ac4);
        As[ac4 + 0][arow] = a.x; As[ac4 + 1][arow] = a.y;
        As[ac4 + 2][arow] = a.z; As[ac4 + 3][arow] = a.w;
        *(float4*)&Bs[brow][bc4] = *(const float4*)(B + (size_t)(k0 + brow) * N + n0 + bc4);
        __syncthreads();
#pragma unroll
        for (int kk = 0; kk < 8; kk++) {
            float4 a0 = *(float4*)&As[kk][ty * 8], a1 = *(float4*)&As[kk][ty * 8 + 4];
            float4 b0 = *(float4*)&Bs[kk][tx * 8], b1 = *(float4*)&Bs[kk][tx * 8 + 4];
            float av[8] = {a0.x, a0.y, a0.z, a0.w, a1.x, a1.y, a1.z, a1.w};
            float bv[8] = {b0.x, b0.y, b0.z, b0.w, b1.x, b1.y, b1.z, b1.w};
#pragma unroll
            for (int i = 0; i < 8; i++)
#pragma unroll
                for (int j = 0; j < 8; j++) acc[i][j] += av[i] * bv[j];
        }
        __syncthreads();
    }
#pragma unroll
    for (int i = 0; i < 8; i++) {
        float* c = C + (size_t)(m0 + ty * 8 + i) * N + n0 + tx * 8;
        *(float4*)c = make_float4(acc[i][0], acc[i][1], acc[i][2], acc[i][3]);
        *(float4*)(c + 4) = make_float4(acc[i][4], acc[i][5], acc[i][6], acc[i][7]);
    }
}

// ---------------- attention scores per node: asn/adn [n][4] ----------------
__global__ void attn_scores(const float* __restrict__ h, const float* __restrict__ a_s,
                            const float* __restrict__ a_d, float* __restrict__ asn,
                            float* __restrict__ adn, int n) {
    int warp = (blockIdx.x * blockDim.x + threadIdx.x) >> 5;
    int lane = threadIdx.x & 31;
    if (warp >= n) return;
    const float* row = h + (size_t)warp * FD;
#pragma unroll
    for (int hd = 0; hd < 4; hd++) {
        float x0 = row[hd * 64 + lane], x1 = row[hd * 64 + 32 + lane];
        float v1 = x0 * a_s[hd * 64 + lane] + x1 * a_s[hd * 64 + 32 + lane];
        float v2 = x0 * a_d[hd * 64 + lane] + x1 * a_d[hd * 64 + 32 + lane];
#pragma unroll
        for (int o = 16; o; o >>= 1) {
            v1 += __shfl_down_sync(~0u, v1, o);
            v2 += __shfl_down_sync(~0u, v2, o);
        }
        if (lane == 0) { asn[warp * 4 + hd] = v1; adn[warp * 4 + hd] = v2; }
    }
}

// ---------------- edge softmax numerator + denominator ----------------
__global__ void edge_softmax(const int* __restrict__ src, const int* __restrict__ dst,
                             const int* __restrict__ inv,
                             const float* __restrict__ asn, const float* __restrict__ adn,
                             float* __restrict__ pe, float* __restrict__ denom,
                             int nE, int nN) {
    int idx = blockIdx.x * blockDim.x + threadIdx.x;
    if (idx >= nE + nN) return;
    int s, d;
    if (idx < nE) {
        s = src[idx]; d = dst[idx];
        if (inv) { s = inv[s]; d = inv[d]; if (s < 0 || d < 0) return; }
    } else {
        s = d = idx - nE;
    }
    float4 a = *(const float4*)&asn[(size_t)s * 4];
    float4 b = *(const float4*)&adn[(size_t)d * 4];
    float l0 = a.x + b.x, l1 = a.y + b.y, l2 = a.z + b.z, l3 = a.w + b.w;
    l0 = l0 > 0.f ? l0 : 0.2f * l0;
    l1 = l1 > 0.f ? l1 : 0.2f * l1;
    l2 = l2 > 0.f ? l2 : 0.2f * l2;
    l3 = l3 > 0.f ? l3 : 0.2f * l3;
    float4 p = make_float4(__expf(l0), __expf(l1), __expf(l2), __expf(l3));
    *(float4*)&pe[(size_t)idx * 4] = p;
    red_add_v4(&denom[(size_t)d * 4], p);
}

// ---------------- edge aggregation: out[d] += alpha * h[s] (warp per edge) ----------------
__global__ void edge_aggr(const int* __restrict__ src, const int* __restrict__ dst,
                          const int* __restrict__ inv,
                          const float* __restrict__ pe, const float* __restrict__ denom,
                          const float* __restrict__ h, float* __restrict__ out,
                          int nE, int nN) {
    int gw = (blockIdx.x * blockDim.x + threadIdx.x) >> 5;
    int lane = threadIdx.x & 31;
    if (gw >= nE + nN) return;
    int s, d;
    if (gw < nE) {
        s = src[gw]; d = dst[gw];
        if (inv) { s = inv[s]; d = inv[d]; if (s < 0 || d < 0) return; }
    } else {
        s = d = gw - nE;
    }
    float4 p4 = *(const float4*)&pe[(size_t)gw * 4];
    float4 dn = *(const float4*)&denom[(size_t)d * 4];
    float al[4] = {p4.x / dn.x, p4.y / dn.y, p4.z / dn.z, p4.w / dn.w};
    const float4* hrow = (const float4*)(h + (size_t)s * FD);
    float* orow = out + (size_t)d * FD;
#pragma unroll
    for (int j = 0; j < 2; j++) {
        int f4 = j * 32 + lane;            // 0..63 float4 index
        float4 v = hrow[f4];
        float a = al[f4 >> 4];
        v.x *= a; v.y *= a; v.z *= a; v.w *= a;
        red_add_v4(orow + f4 * 4, v);
    }
}

// ---------------- bias + exact GELU + BN stats ----------------
__global__ void bias_gelu_stats(float* __restrict__ x, const float* __restrict__ bias,
                                float* __restrict__ sums, int rowsPerBlock) {
    int col = threadIdx.x;
    int r0 = blockIdx.x * rowsPerBlock;
    float b = bias[col];
    float s = 0.f, s2 = 0.f;
    for (int r = 0; r < rowsPerBlock; r++) {
        size_t i = (size_t)(r0 + r) * FD + col;
        float v = x[i] + b;
        v = 0.5f * v * (1.0f + erff(v * 0.70710678118654752f));
        x[i] = v;
        s += v; s2 += v * v;
    }
    atomicAdd(&sums[col], s);
    atomicAdd(&sums[256 + col], s2);
}

// ---------------- BN finalize: scale/shift + normalized pool weight ----------------
__global__ void bn_finalize(const float* __restrict__ sums, const float* __restrict__ g,
                            const float* __restrict__ be, const float* __restrict__ pw,
                            float* __restrict__ scale, float* __restrict__ shift,
                            float* __restrict__ pwn, float invn) {
    __shared__ float red[256];
    int f = threadIdx.x;
    float mean = sums[f] * invn;
    float var = sums[256 + f] * invn - mean * mean;
    float sc = g[f] * rsqrtf(var + 1e-5f);
    scale[f] = sc;
    shift[f] = be[f] - mean * sc;
    float w = pw[f];
    red[f] = w * w;
    __syncthreads();
    for (int st = 128; st; st >>= 1) {
        if (f < st) red[f] += red[f + st];
        __syncthreads();
    }
    pwn[f] = w * rsqrtf(red[0]);
}

// ---------------- BN apply ----------------
__global__ void bn_apply(float* __restrict__ x, const float* __restrict__ scale,
                         const float* __restrict__ shift, int n4) {
    int i = blockIdx.x * blockDim.x + threadIdx.x;
    if (i >= n4) return;
    int c4 = (i & 63) * 4;
    float4 v = ((float4*)x)[i];
    float4 sc = *(const float4*)&scale[c4];
    float4 sh = *(const float4*)&shift[c4];
    v.x = v.x * sc.x + sh.x; v.y = v.y * sc.y + sh.y;
    v.z = v.z * sc.z + sh.z; v.w = v.w * sc.w + sh.w;
    ((float4*)x)[i] = v;
}

// ---------------- node score (warp per node) ----------------
__global__ void node_score(const float* __restrict__ x, const float* __restrict__ pwn,
                           float* __restrict__ score, int n) {
    int warp = (blockIdx.x * blockDim.x + threadIdx.x) >> 5;
    int lane = threadIdx.x & 31;
    if (warp >= n) return;
    const float* row = x + (size_t)warp * FD;
    float s = 0.f;
#pragma unroll
    for (int j = 0; j < 8; j++) {
        int c = j * 32 + lane;
        s += row[c] * pwn[c];
    }
#pragma unroll
    for (int o = 16; o; o >>= 1) s += __shfl_down_sync(~0u, s, o);
    if (lane == 0) score[warp] = s;
}

// ---------------- per-graph top-k via bitonic sort (block per graph) ----------------
__global__ void topk_sort(const float* __restrict__ score, int npg, int k,
                          int* __restrict__ gidx, float* __restrict__ tv,
                          int* __restrict__ inv) {
    __shared__ float sv[1024];
    __shared__ int si[1024];
    int g = blockIdx.x, t = threadIdx.x, nt = blockDim.x;
    for (int e = t; e < npg; e += nt) { sv[e] = score[(size_t)g * npg + e]; si[e] = e; }
    __syncthreads();
    for (int kk = 2; kk <= npg; kk <<= 1) {
        for (int j = kk >> 1; j > 0; j >>= 1) {
            for (int e = t; e < npg; e += nt) {
                int p = e ^ j;
                if (p > e) {
                    bool desc = ((e & kk) == 0);
                    float ve = sv[e], vp = sv[p];
                    if (desc ? (ve < vp) : (ve > vp)) {
                        sv[e] = vp; sv[p] = ve;
                        int tmp = si[e]; si[e] = si[p]; si[p] = tmp;
                    }
                }
            }
            __syncthreads();
        }
    }
    for (int e = t; e < k; e += nt) {
        int pos = g * k + e;
        int node = g * npg + si[e];
        gidx[pos] = node;
        tv[pos] = tanhf(sv[e]);
        if (inv) inv[node] = pos;
    }
}

// ---------------- gather pooled rows scaled by tanh(score) ----------------
__global__ void pool_gather(const float* __restrict__ x, const int* __restrict__ gidx,
                            const float* __restrict__ tv, float* __restrict__ xp, int n2) {
    int i = blockIdx.x * blockDim.x + threadIdx.x;
    if (i >= n2 * 64) return;
    int row = i >> 6, c4 = i & 63;
    float t = tv[row];
    int node = gidx[row];
    float4 v = *(const float4*)&x[(size_t)node * FD + c4 * 4];
    v.x *= t; v.y *= t; v.z *= t; v.w *= t;
    *(float4*)&xp[(size_t)row * FD + c4 * 4] = v;
}

// ---------------- readout (max & mean) from contiguous pooled matrix ----------------
__global__ void readout_xp(const float* __restrict__ xp, int k, float* __restrict__ xg) {
    int g = blockIdx.x, f = threadIdx.x;
    float mx = -1e30f, sm = 0.f;
    for (int j = 0; j < k; j++) {
        float v = xp[((size_t)g * k + j) * FD + f];
        mx = fmaxf(mx, v);
        sm += v;
    }
    xg[(size_t)g * 512 + f] = mx;
    xg[(size_t)g * 512 + 256 + f] = sm / (float)k;
}

// ---------------- readout via gather (layer 2, no xp buffer) ----------------
__global__ void readout_gather(const float* __restrict__ x, const int* __restrict__ gidx,
                               const float* __restrict__ tv, int k, float* __restrict__ xg) {
    int g = blockIdx.x, f = threadIdx.x;
    float mx = -1e30f, sm = 0.f;
    for (int j = 0; j < k; j++) {
        int node = gidx[g * k + j];
        float v = x[(size_t)node * FD + f] * tv[g * k + j];
        mx = fmaxf(mx, v);
        sm += v;
    }
    xg[(size_t)g * 512 + f] = mx;
    xg[(size_t)g * 512 + 256 + f] = sm / (float)k;
}

// ---------------- final linear: out = (x1+x2) @ Wl^T + bl ----------------
__global__ void final_linear(const float* __restrict__ x1g, const float* __restrict__ x2g,
                             const float* __restrict__ Wl, const float* __restrict__ bl,
                             float* __restrict__ out) {
    __shared__ float xr[512];
    int b = blockIdx.x, t = threadIdx.x;
    xr[t] = x1g[(size_t)b * 512 + t] + x2g[(size_t)b * 512 + t];
    xr[t + 256] = x1g[(size_t)b * 512 + 256 + t] + x2g[(size_t)b * 512 + 256 + t];
    __syncthreads();
    float acc = bl[t];
    const float* w = Wl + (size_t)t * 512;
    for (int kk = 0; kk < 512; kk++) acc += xr[kk] * w[kk];
    out[(size_t)b * 256 + t] = acc;
}

// ---------------- host launcher ----------------
extern "C" void kernel_launch(void* const* d_in, const int* in_sizes, int n_in,
                              void* d_out, int out_size) {
    const float* x    = (const float*)d_in[0];
    const int*   ei   = (const int*)d_in[1];
    const int*   src  = ei;
    const int*   dst  = ei + ED;
    const float* W1   = (const float*)d_in[3];
    const float* as1  = (const float*)d_in[4];
    const float* ad1  = (const float*)d_in[5];
    const float* b1   = (const float*)d_in[6];
    const float* g1   = (const float*)d_in[7];
    const float* be1  = (const float*)d_in[8];
    const float* pw1  = (const float*)d_in[9];
    const float* W2   = (const float*)d_in[10];
    const float* as2  = (const float*)d_in[11];
    const float* ad2  = (const float*)d_in[12];
    const float* b2   = (const float*)d_in[13];
    const float* g2   = (const float*)d_in[14];
    const float* be2  = (const float*)d_in[15];
    const float* pw2  = (const float*)d_in[16];
    const float* Wl   = (const float*)d_in[17];
    const float* bl   = (const float*)d_in[18];
    float* out = (float*)d_out;

    float* fb = nullptr;
    int*   ib = nullptr;
    cudaGetSymbolAddress((void**)&fb, g_f);
    cudaGetSymbolAddress((void**)&ib, g_i);

    float* h1    = fb + O_H1;
    float* out1  = fb + O_OUT1;
    float* asn1  = fb + O_ASN1;
    float* adn1  = fb + O_ADN1;
    float* den1  = fb + O_DEN1;
    float* pe1   = fb + O_PE1;
    float* bns1  = fb + O_BNS1;
    float* sc1   = fb + O_SC1;
    float* sh1   = fb + O_SH1;
    float* pwn1  = fb + O_PWN1;
    float* score1= fb + O_SCORE1;
    float* tanh1 = fb + O_TANH1;
    float* xp1   = fb + O_XP1;
    float* x1g   = fb + O_X1G;
    float* h2    = fb + O_H2;
    float* out2  = fb + O_OUT2;
    float* asn2  = fb + O_ASN2;
    float* adn2  = fb + O_ADN2;
    float* den2  = fb + O_DEN2;
    float* pe2   = fb + O_PE2;
    float* bns2  = fb + O_BNS2;
    float* sc2   = fb + O_SC2;
    float* sh2   = fb + O_SH2;
    float* pwn2  = fb + O_PWN2;
    float* score2= fb + O_SCORE2;
    float* tanh2 = fb + O_TANH2;
    float* x2g   = fb + O_X2G;
    int* gidx1 = ib + IO_GIDX1;
    int* inv1  = ib + IO_INV1;
    int* gidx2 = ib + IO_GIDX2;

    // zero accumulators
    cudaMemsetAsync(out1, 0, (size_t)NN * FD * sizeof(float));
    cudaMemsetAsync(den1, 0, (size_t)NN * 4 * sizeof(float));
    cudaMemsetAsync(bns1, 0, 512 * sizeof(float));
    cudaMemsetAsync(out2, 0, (size_t)N2 * FD * sizeof(float));
    cudaMemsetAsync(den2, 0, (size_t)N2 * 4 * sizeof(float));
    cudaMemsetAsync(bns2, 0, 512 * sizeof(float));
    cudaMemsetAsync(inv1, 0xFF, (size_t)NN * sizeof(int));

    // ---- layer 1 ----
    sgemm128<<<dim3(FD / 128, NN / 128), 256>>>(x, W1, h1, NN, FD, INDIM);
    attn_scores<<<NN / 8, 256>>>(h1, as1, ad1, asn1, adn1, NN);
    {
        int tot = ED + NN;
        edge_softmax<<<(tot + 255) / 256, 256>>>(src, dst, nullptr, asn1, adn1, pe1, den1, ED, NN);
        edge_aggr<<<(tot + 7) / 8, 256>>>(src, dst, nullptr, pe1, den1, h1, out1, ED, NN);
    }
    bias_gelu_stats<<<NN / 128, 256>>>(out1, b1, bns1, 128);
    bn_finalize<<<1, 256>>>(bns1, g1, be1, pw1, sc1, sh1, pwn1, 1.0f / NN);
    bn_apply<<<(NN * 64 + 255) / 256, 256>>>(out1, sc1, sh1, NN * 64);
    node_score<<<NN / 8, 256>>>(out1, pwn1, score1, NN);
    topk_sort<<<BT, NPG / 2>>>(score1, NPG, KP1, gidx1, tanh1, inv1);
    pool_gather<<<(N2 * 64 + 255) / 256, 256>>>(out1, gidx1, tanh1, xp1, N2);
    readout_xp<<<BT, 256>>>(xp1, KP1, x1g);

    // ---- layer 2 ----
    sgemm128<<<dim3(FD / 128, N2 / 128), 256>>>(xp1, W2, h2, N2, FD, FD);
    attn_scores<<<N2 / 8, 256>>>(h2, as2, ad2, asn2, adn2, N2);
    {
        int tot = ED + N2;
        edge_softmax<<<(tot + 255) / 256, 256>>>(src, dst, inv1, asn2, adn2, pe2, den2, ED, N2);
        edge_aggr<<<(tot + 7) / 8, 256>>>(src, dst, inv1, pe2, den2, h2, out2, ED, N2);
    }
    bias_gelu_stats<<<N2 / 128, 256>>>(out2, b2, bns2, 128);
    bn_finalize<<<1, 256>>>(bns2, g2, be2, pw2, sc2, sh2, pwn2, 1.0f / N2);
    bn_apply<<<(N2 * 64 + 255) / 256, 256>>>(out2, sc2, sh2, N2 * 64);
    node_score<<<N2 / 8, 256>>>(out2, pwn2, score2, N2);
    topk_sort<<<BT, KP1 / 2>>>(score2, KP1, KP2, gidx2, tanh2, nullptr);
    readout_gather<<<BT, 256>>>(out2, gidx2, tanh2, KP2, x2g);

    // ---- final ----
    final_linear<<<BT, 256>>>(x1g, x2g, Wl, bl, out);
}

// round 2
// speedup vs baseline: 1.3063x; 1.3063x over previous
#include <cuda_runtime.h>
#include <math.h>

// ---------------- problem constants ----------------
constexpr int NN   = 32768;    // total nodes layer1
constexpr int ED   = 262144;   // edges
constexpr int FD   = 256;      // feature dim (4 heads x 64)
constexpr int BT   = 32;       // graphs
constexpr int NPG  = 1024;
constexpr int KP1  = 512;
constexpr int KP2  = 256;
constexpr int N2   = BT * KP1; // 16384 pooled nodes after pool1
constexpr int INDIM = 128;
constexpr int MAXDEG = 64;     // padded CSR width (Poisson(8) max deg << 64)

// ---------------- scratch layout (floats) ----------------
constexpr size_t O_H1    = 0;
constexpr size_t O_OUT1  = O_H1   + (size_t)NN * FD;
constexpr size_t O_ASN1  = O_OUT1 + (size_t)NN * FD;
constexpr size_t O_ADN1  = O_ASN1 + (size_t)NN * 4;
constexpr size_t O_BNS1  = O_ADN1 + (size_t)NN * 4;
constexpr size_t O_SC1   = O_BNS1 + 512;
constexpr size_t O_SH1   = O_SC1  + 256;
constexpr size_t O_PWN1  = O_SH1  + 256;
constexpr size_t O_SCORE1= O_PWN1 + 256;
constexpr size_t O_TANH1 = O_SCORE1 + NN;
constexpr size_t O_XP1   = O_TANH1  + N2;
constexpr size_t O_X1G   = O_XP1    + (size_t)N2 * FD;
constexpr size_t O_PART  = O_X1G    + (size_t)BT * 512;
constexpr size_t O_H2    = O_PART   + (size_t)BT * 8 * 512;
constexpr size_t O_OUT2  = O_H2     + (size_t)N2 * FD;
constexpr size_t O_ASN2  = O_OUT2   + (size_t)N2 * FD;
constexpr size_t O_ADN2  = O_ASN2   + (size_t)N2 * 4;
constexpr size_t O_BNS2  = O_ADN2   + (size_t)N2 * 4;
constexpr size_t O_SC2   = O_BNS2   + 512;
constexpr size_t O_SH2   = O_SC2    + 256;
constexpr size_t O_PWN2  = O_SH2    + 256;
constexpr size_t O_SCORE2= O_PWN2   + 256;
constexpr size_t O_TANH2 = O_SCORE2 + N2;
constexpr size_t O_X2G   = O_TANH2  + (size_t)BT * KP2;
constexpr size_t F_TOTAL = O_X2G    + (size_t)BT * 512;

__device__ float g_f[F_TOTAL];

constexpr size_t IO_GIDX1 = 0;
constexpr size_t IO_INV1  = IO_GIDX1 + N2;
constexpr size_t IO_GIDX2 = IO_INV1  + NN;
constexpr size_t IO_DEG1  = IO_GIDX2 + (size_t)BT * KP2;
constexpr size_t IO_CSR1  = IO_DEG1  + NN;
constexpr size_t IO_DEG2  = IO_CSR1  + (size_t)NN * MAXDEG;
constexpr size_t IO_CSR2  = IO_DEG2  + N2;
constexpr size_t I_TOTAL  = IO_CSR2  + (size_t)N2 * MAXDEG;

__device__ int g_i[I_TOTAL];

// ---------------- SGEMM: C[MxN] = A[MxK] @ B[KxN], 128x128 tile, 8x8/thread ----------------
__global__ __launch_bounds__(256) void sgemm128(const float* __restrict__ A,
                                                const float* __restrict__ B,
                                                float* __restrict__ C,
                                                int M, int N, int K) {
    __shared__ float As[8][132];
    __shared__ float Bs[8][132];
    int tid = threadIdx.x;
    int tx = tid & 15, ty = tid >> 4;
    int m0 = blockIdx.y * 128, n0 = blockIdx.x * 128;
    int arow = tid >> 1, ac4 = (tid & 1) * 4;
    int brow = tid >> 5, bc4 = (tid & 31) * 4;
    float acc[8][8];
#pragma unroll
    for (int i = 0; i < 8; i++)
#pragma unroll
        for (int j = 0; j < 8; j++) acc[i][j] = 0.f;

    for (int k0 = 0; k0 < K; k0 += 8) {
        float4 a = *(const float4*)(A + (size_t)(m0 + arow) * K + k0 + ac4);
        As[ac4 + 0][arow] = a.x; As[ac4 + 1][arow] = a.y;
        As[ac4 + 2][arow] = a.z; As[ac4 + 3][arow] = a.w;
        *(float4*)&Bs[brow][bc4] = *(const float4*)(B + (size_t)(k0 + brow) * N + n0 + bc4);
        __syncthreads();
#pragma unroll
        for (int kk = 0; kk < 8; kk++) {
            float4 a0 = *(float4*)&As[kk][ty * 8], a1 = *(float4*)&As[kk][ty * 8 + 4];
            float4 b0 = *(float4*)&Bs[kk][tx * 8], b1 = *(float4*)&Bs[kk][tx * 8 + 4];
            float av[8] = {a0.x, a0.y, a0.z, a0.w, a1.x, a1.y, a1.z, a1.w};
            float bv[8] = {b0.x, b0.y, b0.z, b0.w, b1.x, b1.y, b1.z, b1.w};
#pragma unroll
            for (int i = 0; i < 8; i++)
#pragma unroll
                for (int j = 0; j < 8; j++) acc[i][j] += av[i] * bv[j];
        }
        __syncthreads();
    }
#pragma unroll
    for (int i = 0; i < 8; i++) {
        float* c = C + (size_t)(m0 + ty * 8 + i) * N + n0 + tx * 8;
        *(float4*)c = make_float4(acc[i][0], acc[i][1], acc[i][2], acc[i][3]);
        *(float4*)(c + 4) = make_float4(acc[i][4], acc[i][5], acc[i][6], acc[i][7]);
    }
}

// ---------------- attention scores per node: asn/adn [n][4] ----------------
__global__ void attn_scores(const float* __restrict__ h, const float* __restrict__ a_s,
                            const float* __restrict__ a_d, float* __restrict__ asn,
                            float* __restrict__ adn, int n) {
    int warp = (blockIdx.x * blockDim.x + threadIdx.x) >> 5;
    int lane = threadIdx.x & 31;
    if (warp >= n) return;
    const float* row = h + (size_t)warp * FD;
#pragma unroll
    for (int hd = 0; hd < 4; hd++) {
        float x0 = row[hd * 64 + lane], x1 = row[hd * 64 + 32 + lane];
        float v1 = x0 * a_s[hd * 64 + lane] + x1 * a_s[hd * 64 + 32 + lane];
        float v2 = x0 * a_d[hd * 64 + lane] + x1 * a_d[hd * 64 + 32 + lane];
#pragma unroll
        for (int o = 16; o; o >>= 1) {
            v1 += __shfl_down_sync(~0u, v1, o);
            v2 += __shfl_down_sync(~0u, v2, o);
        }
        if (lane == 0) { asn[warp * 4 + hd] = v1; adn[warp * 4 + hd] = v2; }
    }
}

// ---------------- padded-CSR build: deg histogram + scatter in one kernel ----------------
__global__ void csr_build(const int* __restrict__ src, const int* __restrict__ dst,
                          const int* __restrict__ inv, int* __restrict__ deg,
                          int* __restrict__ csr, int nE) {
    int i = blockIdx.x * blockDim.x + threadIdx.x;
    if (i >= nE) return;
    int s = src[i], d = dst[i];
    if (inv) { s = inv[s]; d = inv[d]; if (s < 0 || d < 0) return; }
    int p = atomicAdd(&deg[d], 1);
    if (p < MAXDEG) csr[(size_t)d * MAXDEG + p] = s;
}

// ---------------- fused GAT gather: softmax + aggregate + bias + GELU + BN stats ----------------
__global__ __launch_bounds__(256) void gat_gather(
    const int* __restrict__ csr, const int* __restrict__ deg,
    const float* __restrict__ asn, const float* __restrict__ adn,
    const float* __restrict__ h, const float* __restrict__ bias,
    float* __restrict__ out, float* __restrict__ sums, int n, int npb) {
    __shared__ float ssum[512];
    int t = threadIdx.x;
    ssum[t] = 0.f; ssum[t + 256] = 0.f;
    __syncthreads();
    int lane = t & 31, w = t >> 5;
    int c0 = lane * 4, c1 = c0 + 128;
    float4 bb0 = *(const float4*)&bias[c0];
    float4 bb1 = *(const float4*)&bias[c1];
    bool hsel = (lane & 16) != 0;     // head of first chunk: 0/1; second: 2/3
    float st[16];
#pragma unroll
    for (int i = 0; i < 16; i++) st[i] = 0.f;

    int base = blockIdx.x * npb;
    for (int nd = base + w; nd < base + npb && nd < n; nd += 8) {
        float4 ad = *(const float4*)&adn[(size_t)nd * 4];
        float4 a0 = make_float4(0, 0, 0, 0), a1 = make_float4(0, 0, 0, 0);
        float d0 = 0, d1 = 0, d2 = 0, d3 = 0;
        int dg = deg[nd]; if (dg > MAXDEG) dg = MAXDEG;
        const int* row = csr + (size_t)nd * MAXDEG;
        for (int e = 0; e <= dg; e++) {
            int s = (e == dg) ? nd : row[e];
            float4 as = *(const float4*)&asn[(size_t)s * 4];
            float l0 = as.x + ad.x, l1 = as.y + ad.y, l2 = as.z + ad.z, l3 = as.w + ad.w;
            l0 = l0 > 0.f ? l0 : 0.2f * l0;
            l1 = l1 > 0.f ? l1 : 0.2f * l1;
            l2 = l2 > 0.f ? l2 : 0.2f * l2;
            l3 = l3 > 0.f ? l3 : 0.2f * l3;
            float p0 = __expf(l0), p1 = __expf(l1), p2 = __expf(l2), p3 = __expf(l3);
            d0 += p0; d1 += p1; d2 += p2; d3 += p3;
            const float4* hr = (const float4*)(h + (size_t)s * FD);
            float4 v0 = hr[lane], v1 = hr[lane + 32];
            float pa = hsel ? p1 : p0;
            float pb = hsel ? p3 : p2;
            a0.x += pa * v0.x; a0.y += pa * v0.y; a0.z += pa * v0.z; a0.w += pa * v0.w;
            a1.x += pb * v1.x; a1.y += pb * v1.y; a1.z += pb * v1.z; a1.w += pb * v1.w;
        }
        float ra = 1.f / (hsel ? d1 : d0);
        float rb = 1.f / (hsel ? d3 : d2);
        float o[8];
        o[0] = a0.x * ra + bb0.x; o[1] = a0.y * ra + bb0.y;
        o[2] = a0.z * ra + bb0.z; o[3] = a0.w * ra + bb0.w;
        o[4] = a1.x * rb + bb1.x; o[5] = a1.y * rb + bb1.y;
        o[6] = a1.z * rb + bb1.z; o[7] = a1.w * rb + bb1.w;
#pragma unroll
        for (int i = 0; i < 8; i++) {
            float v = o[i];
            v = 0.5f * v * (1.0f + erff(v * 0.70710678118654752f));
            o[i] = v;
            st[i] += v; st[8 + i] += v * v;
        }
        float* op = out + (size_t)nd * FD;
        *(float4*)(op + c0) = make_float4(o[0], o[1], o[2], o[3]);
        *(float4*)(op + c1) = make_float4(o[4], o[5], o[6], o[7]);
    }
    // per-warp stats -> smem
#pragma unroll
    for (int i = 0; i < 4; i++) {
        atomicAdd(&ssum[c0 + i],       st[i]);
        atomicAdd(&ssum[c1 + i],       st[4 + i]);
        atomicAdd(&ssum[256 + c0 + i], st[8 + i]);
        atomicAdd(&ssum[256 + c1 + i], st[12 + i]);
    }
    __syncthreads();
    atomicAdd(&sums[t],       ssum[t]);
    atomicAdd(&sums[t + 256], ssum[t + 256]);
}

// ---------------- BN finalize: scale/shift + normalized pool weight ----------------
__global__ void bn_finalize(const float* __restrict__ sums, const float* __restrict__ g,
                            const float* __restrict__ be, const float* __restrict__ pw,
                            float* __restrict__ scale, float* __restrict__ shift,
                            float* __restrict__ pwn, float invn) {
    __shared__ float red[256];
    int f = threadIdx.x;
    float mean = sums[f] * invn;
    float var = sums[256 + f] * invn - mean * mean;
    float sc = g[f] * rsqrtf(var + 1e-5f);
    scale[f] = sc;
    shift[f] = be[f] - mean * sc;
    float w = pw[f];
    red[f] = w * w;
    __syncthreads();
    for (int st = 128; st; st >>= 1) {
        if (f < st) red[f] += red[f + st];
        __syncthreads();
    }
    pwn[f] = w * rsqrtf(red[0]);
}

// ---------------- fused BN apply + pool score (warp per node) ----------------
__global__ void bn_score(float* __restrict__ x, const float* __restrict__ sc,
                         const float* __restrict__ sh, const float* __restrict__ pwn,
                         float* __restrict__ score, int n) {
    int gw = (blockIdx.x * blockDim.x + threadIdx.x) >> 5;
    int lane = threadIdx.x & 31;
    if (gw >= n) return;
    float* row = x + (size_t)gw * FD;
    int c0 = lane * 4, c1 = c0 + 128;
    float4 v0 = *(float4*)(row + c0), v1 = *(float4*)(row + c1);
    float4 s0 = *(const float4*)&sc[c0], s1 = *(const float4*)&sc[c1];
    float4 h0 = *(const float4*)&sh[c0], h1 = *(const float4*)&sh[c1];
    v0.x = v0.x * s0.x + h0.x; v0.y = v0.y * s0.y + h0.y;
    v0.z = v0.z * s0.z + h0.z; v0.w = v0.w * s0.w + h0.w;
    v1.x = v1.x * s1.x + h1.x; v1.y = v1.y * s1.y + h1.y;
    v1.z = v1.z * s1.z + h1.z; v1.w = v1.w * s1.w + h1.w;
    *(float4*)(row + c0) = v0; *(float4*)(row + c1) = v1;
    float4 p0 = *(const float4*)&pwn[c0], p1 = *(const float4*)&pwn[c1];
    float s = v0.x * p0.x + v0.y * p0.y + v0.z * p0.z + v0.w * p0.w
            + v1.x * p1.x + v1.y * p1.y + v1.z * p1.z + v1.w * p1.w;
#pragma unroll
    for (int o = 16; o; o >>= 1) s += __shfl_down_sync(~0u, s, o);
    if (lane == 0) score[gw] = s;
}

// ---------------- per-graph top-k via bitonic sort (block per graph) ----------------
__global__ void topk_sort(const float* __restrict__ score, int npg, int k,
                          int* __restrict__ gidx, float* __restrict__ tv,
                          int* __restrict__ inv) {
    __shared__ float sv[1024];
    __shared__ int si[1024];
    int g = blockIdx.x, t = threadIdx.x, nt = blockDim.x;
    for (int e = t; e < npg; e += nt) { sv[e] = score[(size_t)g * npg + e]; si[e] = e; }
    __syncthreads();
    for (int kk = 2; kk <= npg; kk <<= 1) {
        for (int j = kk >> 1; j > 0; j >>= 1) {
            for (int e = t; e < npg; e += nt) {
                int p = e ^ j;
                if (p > e) {
                    bool desc = ((e & kk) == 0);
                    float ve = sv[e], vp = sv[p];
                    if (desc ? (ve < vp) : (ve > vp)) {
                        sv[e] = vp; sv[p] = ve;
                        int tmp = si[e]; si[e] = si[p]; si[p] = tmp;
                    }
                }
            }
            __syncthreads();
        }
    }
    for (int e = t; e < k; e += nt) {
        int pos = g * k + e;
        int node = g * npg + si[e];
        gidx[pos] = node;
        tv[pos] = tanhf(sv[e]);
        if (inv) inv[node] = pos;
    }
}

// ---------------- gather pooled rows scaled by tanh(score) ----------------
__global__ void pool_gather(const float* __restrict__ x, const int* __restrict__ gidx,
                            const float* __restrict__ tv, float* __restrict__ xp, int n2) {
    int i = blockIdx.x * blockDim.x + threadIdx.x;
    if (i >= n2 * 64) return;
    int row = i >> 6, c4 = i & 63;
    float t = tv[row];
    int node = gidx[row];
    float4 v = *(const float4*)&x[(size_t)node * FD + c4 * 4];
    v.x *= t; v.y *= t; v.z *= t; v.w *= t;
    *(float4*)&xp[(size_t)row * FD + c4 * 4] = v;
}

// ---------------- readout stage 1: per (graph, row-chunk) partial max/sum ----------------
__global__ void readout_s1(const float* __restrict__ x, const int* __restrict__ gidx,
                           const float* __restrict__ tv, int k, float* __restrict__ partial) {
    int g = blockIdx.x, c = blockIdx.y, f = threadIdx.x;
    int chunk = k / 8;
    int j0 = c * chunk;
    float mx = -1e30f, sm = 0.f;
    for (int j = j0; j < j0 + chunk; j++) {
        float v;
        if (gidx) {
            int node = gidx[g * k + j];
            v = x[(size_t)node * FD + f] * tv[g * k + j];
        } else {
            v = x[((size_t)g * k + j) * FD + f];
        }
        mx = fmaxf(mx, v);
        sm += v;
    }
    partial[((size_t)(g * 8 + c)) * 512 + f] = mx;
    partial[((size_t)(g * 8 + c)) * 512 + 256 + f] = sm;
}

// ---------------- readout stage 2: reduce 8 partials ----------------
__global__ void readout_s2(const float* __restrict__ partial, int k, float* __restrict__ xg) {
    int g = blockIdx.x, f = threadIdx.x;
    float mx = -1e30f, sm = 0.f;
    for (int c = 0; c < 8; c++) {
        mx = fmaxf(mx, partial[((size_t)(g * 8 + c)) * 512 + f]);
        sm += partial[((size_t)(g * 8 + c)) * 512 + 256 + f];
    }
    xg[(size_t)g * 512 + f] = mx;
    xg[(size_t)g * 512 + 256 + f] = sm / (float)k;
}

// ---------------- final linear: out = (x1+x2) @ Wl^T + bl ----------------
__global__ void final_linear(const float* __restrict__ x1g, const float* __restrict__ x2g,
                             const float* __restrict__ Wl, const float* __restrict__ bl,
                             float* __restrict__ out) {
    __shared__ float xr[512];
    int b = blockIdx.x, t = threadIdx.x;
    xr[t] = x1g[(size_t)b * 512 + t] + x2g[(size_t)b * 512 + t];
    xr[t + 256] = x1g[(size_t)b * 512 + 256 + t] + x2g[(size_t)b * 512 + 256 + t];
    __syncthreads();
    float acc = bl[t];
    const float* w = Wl + (size_t)t * 512;
    for (int kk = 0; kk < 512; kk++) acc += xr[kk] * w[kk];
    out[(size_t)b * 256 + t] = acc;
}

// ---------------- host launcher ----------------
extern "C" void kernel_launch(void* const* d_in, const int* in_sizes, int n_in,
                              void* d_out, int out_size) {
    const float* x    = (const float*)d_in[0];
    const int*   ei   = (const int*)d_in[1];
    const int*   src  = ei;
    const int*   dst  = ei + ED;
    const float* W1   = (const float*)d_in[3];
    const float* as1  = (const float*)d_in[4];
    const float* ad1  = (const float*)d_in[5];
    const float* b1   = (const float*)d_in[6];
    const float* g1   = (const float*)d_in[7];
    const float* be1  = (const float*)d_in[8];
    const float* pw1  = (const float*)d_in[9];
    const float* W2   = (const float*)d_in[10];
    const float* as2  = (const float*)d_in[11];
    const float* ad2  = (const float*)d_in[12];
    const float* b2   = (const float*)d_in[13];
    const float* g2   = (const float*)d_in[14];
    const float* be2  = (const float*)d_in[15];
    const float* pw2  = (const float*)d_in[16];
    const float* Wl   = (const float*)d_in[17];
    const float* bl   = (const float*)d_in[18];
    float* out = (float*)d_out;

    float* fb = nullptr;
    int*   ib = nullptr;
    cudaGetSymbolAddress((void**)&fb, g_f);
    cudaGetSymbolAddress((void**)&ib, g_i);

    float* h1    = fb + O_H1;
    float* out1  = fb + O_OUT1;
    float* asn1  = fb + O_ASN1;
    float* adn1  = fb + O_ADN1;
    float* bns1  = fb + O_BNS1;
    float* sc1   = fb + O_SC1;
    float* sh1   = fb + O_SH1;
    float* pwn1  = fb + O_PWN1;
    float* score1= fb + O_SCORE1;
    float* tanh1 = fb + O_TANH1;
    float* xp1   = fb + O_XP1;
    float* x1g   = fb + O_X1G;
    float* part  = fb + O_PART;
    float* h2    = fb + O_H2;
    float* out2  = fb + O_OUT2;
    float* asn2  = fb + O_ASN2;
    float* adn2  = fb + O_ADN2;
    float* bns2  = fb + O_BNS2;
    float* sc2   = fb + O_SC2;
    float* sh2   = fb + O_SH2;
    float* pwn2  = fb + O_PWN2;
    float* score2= fb + O_SCORE2;
    float* tanh2 = fb + O_TANH2;
    float* x2g   = fb + O_X2G;
    int* gidx1 = ib + IO_GIDX1;
    int* inv1  = ib + IO_INV1;
    int* gidx2 = ib + IO_GIDX2;
    int* deg1  = ib + IO_DEG1;
    int* csr1  = ib + IO_CSR1;
    int* deg2  = ib + IO_DEG2;
    int* csr2  = ib + IO_CSR2;

    // zero small accumulators
    cudaMemsetAsync(bns1, 0, 512 * sizeof(float));
    cudaMemsetAsync(bns2, 0, 512 * sizeof(float));
    cudaMemsetAsync(deg1, 0, (size_t)NN * sizeof(int));
    cudaMemsetAsync(deg2, 0, (size_t)N2 * sizeof(int));
    cudaMemsetAsync(inv1, 0xFF, (size_t)NN * sizeof(int));

    // ---- layer 1 ----
    sgemm128<<<dim3(FD / 128, NN / 128), 256>>>(x, W1, h1, NN, FD, INDIM);
    attn_scores<<<NN / 8, 256>>>(h1, as1, ad1, asn1, adn1, NN);
    csr_build<<<(ED + 255) / 256, 256>>>(src, dst, nullptr, deg1, csr1, ED);
    gat_gather<<<1024, 256>>>(csr1, deg1, asn1, adn1, h1, b1, out1, bns1, NN, NN / 1024);
    bn_finalize<<<1, 256>>>(bns1, g1, be1, pw1, sc1, sh1, pwn1, 1.0f / NN);
    bn_score<<<NN / 8, 256>>>(out1, sc1, sh1, pwn1, score1, NN);
    topk_sort<<<BT, NPG / 2>>>(score1, NPG, KP1, gidx1, tanh1, inv1);
    pool_gather<<<(N2 * 64 + 255) / 256, 256>>>(out1, gidx1, tanh1, xp1, N2);
    readout_s1<<<dim3(BT, 8), 256>>>(xp1, nullptr, nullptr, KP1, part);
    readout_s2<<<BT, 256>>>(part, KP1, x1g);

    // ---- layer 2 ----
    sgemm128<<<dim3(FD / 128, N2 / 128), 256>>>(xp1, W2, h2, N2, FD, FD);
    attn_scores<<<N2 / 8, 256>>>(h2, as2, ad2, asn2, adn2, N2);
    csr_build<<<(ED + 255) / 256, 256>>>(src, dst, inv1, deg2, csr2, ED);
    gat_gather<<<512, 256>>>(csr2, deg2, asn2, adn2, h2, b2, out2, bns2, N2, N2 / 512);
    bn_finalize<<<1, 256>>>(bns2, g2, be2, pw2, sc2, sh2, pwn2, 1.0f / N2);
    bn_score<<<N2 / 8, 256>>>(out2, sc2, sh2, pwn2, score2, N2);
    topk_sort<<<BT, KP1 / 2>>>(score2, KP1, KP2, gidx2, tanh2, nullptr);
    readout_s1<<<dim3(BT, 8), 256>>>(out2, gidx2, tanh2, KP2, part);
    readout_s2<<<BT, 256>>>(part, KP2, x2g);

    // ---- final ----
    final_linear<<<BT, 256>>>(x1g, x2g, Wl, bl, out);
}

// round 3
// speedup vs baseline: 1.3070x; 1.0005x over previous
#include <cuda_runtime.h>
#include <math.h>

// ---------------- problem constants ----------------
constexpr int NN   = 32768;    // total nodes layer1
constexpr int ED   = 262144;   // edges
constexpr int FD   = 256;      // feature dim (4 heads x 64)
constexpr int BT   = 32;       // graphs
constexpr int NPG  = 1024;
constexpr int KP1  = 512;
constexpr int KP2  = 256;
constexpr int N2   = BT * KP1; // 16384 pooled nodes after pool1
constexpr int INDIM = 128;
constexpr int MAXDEG = 64;     // padded CSR width (Poisson(8) max deg << 64)

// ---------------- scratch layout (floats) ----------------
constexpr size_t O_H1    = 0;
constexpr size_t O_OUT1  = O_H1   + (size_t)NN * FD;
constexpr size_t O_ASN1  = O_OUT1 + (size_t)NN * FD;
constexpr size_t O_ADN1  = O_ASN1 + (size_t)NN * 4;
constexpr size_t O_BNS1  = O_ADN1 + (size_t)NN * 4;
constexpr size_t O_SC1   = O_BNS1 + 512;
constexpr size_t O_SH1   = O_SC1  + 256;
constexpr size_t O_W1A   = O_SH1  + 256;   // 256 + 1 (w1 vector, w0 scalar)
constexpr size_t O_SCORE1= O_W1A  + 260;
constexpr size_t O_TANH1 = O_SCORE1 + NN;
constexpr size_t O_XP1   = O_TANH1  + N2;
constexpr size_t O_X1G   = O_XP1    + (size_t)N2 * FD;
constexpr size_t O_PART  = O_X1G    + (size_t)BT * 512;
constexpr size_t O_PART2 = O_PART   + (size_t)BT * 8 * 512;
constexpr size_t O_H2    = O_PART2  + (size_t)BT * 8 * 512;
constexpr size_t O_OUT2  = O_H2     + (size_t)N2 * FD;
constexpr size_t O_ASN2  = O_OUT2   + (size_t)N2 * FD;
constexpr size_t O_ADN2  = O_ASN2   + (size_t)N2 * 4;
constexpr size_t O_BNS2  = O_ADN2   + (size_t)N2 * 4;
constexpr size_t O_SC2   = O_BNS2   + 512;
constexpr size_t O_SH2   = O_SC2    + 256;
constexpr size_t O_W2A   = O_SH2    + 256;
constexpr size_t O_SCORE2= O_W2A    + 260;
constexpr size_t O_TANH2 = O_SCORE2 + N2;
constexpr size_t O_X2G   = O_TANH2  + (size_t)BT * KP2;
constexpr size_t F_TOTAL = O_X2G    + (size_t)BT * 512;

__device__ float g_f[F_TOTAL];

constexpr size_t IO_GIDX1 = 0;
constexpr size_t IO_INV1  = IO_GIDX1 + N2;
constexpr size_t IO_GIDX2 = IO_INV1  + NN;
constexpr size_t IO_DEG1  = IO_GIDX2 + (size_t)BT * KP2;
constexpr size_t IO_CSR1  = IO_DEG1  + NN;
constexpr size_t IO_DEG2  = IO_CSR1  + (size_t)NN * MAXDEG;
constexpr size_t IO_CSR2  = IO_DEG2  + N2;
constexpr size_t I_TOTAL  = IO_CSR2  + (size_t)N2 * MAXDEG;

__device__ int g_i[I_TOTAL];

// ---------------- SGEMM: C[MxN] = A[MxK] @ B[KxN], 128x128 tile, 8x8/thread ----------------
__global__ __launch_bounds__(256) void sgemm128(const float* __restrict__ A,
                                                const float* __restrict__ B,
                                                float* __restrict__ C,
                                                int M, int N, int K) {
    __shared__ float As[8][132];
    __shared__ float Bs[8][132];
    int tid = threadIdx.x;
    int tx = tid & 15, ty = tid >> 4;
    int m0 = blockIdx.y * 128, n0 = blockIdx.x * 128;
    int arow = tid >> 1, ac4 = (tid & 1) * 4;
    int brow = tid >> 5, bc4 = (tid & 31) * 4;
    float acc[8][8];
#pragma unroll
    for (int i = 0; i < 8; i++)
#pragma unroll
        for (int j = 0; j < 8; j++) acc[i][j] = 0.f;

    for (int k0 = 0; k0 < K; k0 += 8) {
        float4 a = *(const float4*)(A + (size_t)(m0 + arow) * K + k0 + ac4);
        As[ac4 + 0][arow] = a.x; As[ac4 + 1][arow] = a.y;
        As[ac4 + 2][arow] = a.z; As[ac4 + 3][arow] = a.w;
        *(float4*)&Bs[brow][bc4] = *(const float4*)(B + (size_t)(k0 + brow) * N + n0 + bc4);
        __syncthreads();
#pragma unroll
        for (int kk = 0; kk < 8; kk++) {
            float4 a0 = *(float4*)&As[kk][ty * 8], a1 = *(float4*)&As[kk][ty * 8 + 4];
            float4 b0 = *(float4*)&Bs[kk][tx * 8], b1 = *(float4*)&Bs[kk][tx * 8 + 4];
            float av[8] = {a0.x, a0.y, a0.z, a0.w, a1.x, a1.y, a1.z, a1.w};
            float bv[8] = {b0.x, b0.y, b0.z, b0.w, b1.x, b1.y, b1.z, b1.w};
#pragma unroll
            for (int i = 0; i < 8; i++)
#pragma unroll
                for (int j = 0; j < 8; j++) acc[i][j] += av[i] * bv[j];
        }
        __syncthreads();
    }
#pragma unroll
    for (int i = 0; i < 8; i++) {
        float* c = C + (size_t)(m0 + ty * 8 + i) * N + n0 + tx * 8;
        *(float4*)c = make_float4(acc[i][0], acc[i][1], acc[i][2], acc[i][3]);
        *(float4*)(c + 4) = make_float4(acc[i][4], acc[i][5], acc[i][6], acc[i][7]);
    }
}

// ---------------- attention scores per node: asn/adn [n][4] ----------------
__global__ void attn_scores(const float* __restrict__ h, const float* __restrict__ a_s,
                            const float* __restrict__ a_d, float* __restrict__ asn,
                            float* __restrict__ adn, int n) {
    int warp = (blockIdx.x * blockDim.x + threadIdx.x) >> 5;
    int lane = threadIdx.x & 31;
    if (warp >= n) return;
    const float* row = h + (size_t)warp * FD;
#pragma unroll
    for (int hd = 0; hd < 4; hd++) {
        float x0 = row[hd * 64 + lane], x1 = row[hd * 64 + 32 + lane];
        float v1 = x0 * a_s[hd * 64 + lane] + x1 * a_s[hd * 64 + 32 + lane];
        float v2 = x0 * a_d[hd * 64 + lane] + x1 * a_d[hd * 64 + 32 + lane];
#pragma unroll
        for (int o = 16; o; o >>= 1) {
            v1 += __shfl_down_sync(~0u, v1, o);
            v2 += __shfl_down_sync(~0u, v2, o);
        }
        if (lane == 0) { asn[warp * 4 + hd] = v1; adn[warp * 4 + hd] = v2; }
    }
}

// ---------------- padded-CSR build ----------------
__global__ void csr_build(const int* __restrict__ src, const int* __restrict__ dst,
                          const int* __restrict__ inv, int* __restrict__ deg,
                          int* __restrict__ csr, int nE) {
    int i = blockIdx.x * blockDim.x + threadIdx.x;
    if (i >= nE) return;
    int s = src[i], d = dst[i];
    if (inv) { s = inv[s]; d = inv[d]; if (s < 0 || d < 0) return; }
    int p = atomicAdd(&deg[d], 1);
    if (p < MAXDEG) csr[(size_t)d * MAXDEG + p] = s;
}

// ---------------- fused GAT gather: softmax + aggregate + bias + GELU + BN stats ----------------
__global__ __launch_bounds__(256) void gat_gather(
    const int* __restrict__ csr, const int* __restrict__ deg,
    const float* __restrict__ asn, const float* __restrict__ adn,
    const float* __restrict__ h, const float* __restrict__ bias,
    float* __restrict__ out, float* __restrict__ sums, int n, int npb) {
    __shared__ float ssum[512];
    int t = threadIdx.x;
    ssum[t] = 0.f; ssum[t + 256] = 0.f;
    __syncthreads();
    int lane = t & 31, w = t >> 5;
    int c0 = lane * 4, c1 = c0 + 128;
    float4 bb0 = *(const float4*)&bias[c0];
    float4 bb1 = *(const float4*)&bias[c1];
    bool hsel = (lane & 16) != 0;     // head of first chunk: 0/1; second: 2/3
    float st[16];
#pragma unroll
    for (int i = 0; i < 16; i++) st[i] = 0.f;

    int base = blockIdx.x * npb;
    int end = base + npb; if (end > n) end = n;
    for (int nd = base + w; nd < end; nd += 8) {
        float4 ad = *(const float4*)&adn[(size_t)nd * 4];
        float4 a0 = make_float4(0, 0, 0, 0), a1 = make_float4(0, 0, 0, 0);
        float d0 = 0, d1 = 0, d2 = 0, d3 = 0;
        int dg = deg[nd]; if (dg > MAXDEG) dg = MAXDEG;
        const int* row = csr + (size_t)nd * MAXDEG;
        // preload neighbor indices into registers (shfl-broadcast later)
        int r0 = (lane < dg) ? row[lane] : nd;
        int r1 = (lane + 32 < dg) ? row[lane + 32] : nd;
#pragma unroll 2
        for (int e = 0; e <= dg; e++) {
            int s = (e == dg) ? nd : __shfl_sync(~0u, (e < 32) ? r0 : r1, e & 31);
            float4 as = *(const float4*)&asn[(size_t)s * 4];
            float l0 = as.x + ad.x, l1 = as.y + ad.y, l2 = as.z + ad.z, l3 = as.w + ad.w;
            l0 = l0 > 0.f ? l0 : 0.2f * l0;
            l1 = l1 > 0.f ? l1 : 0.2f * l1;
            l2 = l2 > 0.f ? l2 : 0.2f * l2;
            l3 = l3 > 0.f ? l3 : 0.2f * l3;
            float p0 = __expf(l0), p1 = __expf(l1), p2 = __expf(l2), p3 = __expf(l3);
            d0 += p0; d1 += p1; d2 += p2; d3 += p3;
            const float4* hr = (const float4*)(h + (size_t)s * FD);
            float4 v0 = hr[lane], v1 = hr[lane + 32];
            float pa = hsel ? p1 : p0;
            float pb = hsel ? p3 : p2;
            a0.x += pa * v0.x; a0.y += pa * v0.y; a0.z += pa * v0.z; a0.w += pa * v0.w;
            a1.x += pb * v1.x; a1.y += pb * v1.y; a1.z += pb * v1.z; a1.w += pb * v1.w;
        }
        float ra = 1.f / (hsel ? d1 : d0);
        float rb = 1.f / (hsel ? d3 : d2);
        float o[8];
        o[0] = a0.x * ra + bb0.x; o[1] = a0.y * ra + bb0.y;
        o[2] = a0.z * ra + bb0.z; o[3] = a0.w * ra + bb0.w;
        o[4] = a1.x * rb + bb1.x; o[5] = a1.y * rb + bb1.y;
        o[6] = a1.z * rb + bb1.z; o[7] = a1.w * rb + bb1.w;
#pragma unroll
        for (int i = 0; i < 8; i++) {
            float v = o[i];
            v = 0.5f * v * (1.0f + erff(v * 0.70710678118654752f));
            o[i] = v;
            st[i] += v; st[8 + i] += v * v;
        }
        float* op = out + (size_t)nd * FD;
        *(float4*)(op + c0) = make_float4(o[0], o[1], o[2], o[3]);
        *(float4*)(op + c1) = make_float4(o[4], o[5], o[6], o[7]);
    }
#pragma unroll
    for (int i = 0; i < 4; i++) {
        atomicAdd(&ssum[c0 + i],       st[i]);
        atomicAdd(&ssum[c1 + i],       st[4 + i]);
        atomicAdd(&ssum[256 + c0 + i], st[8 + i]);
        atomicAdd(&ssum[256 + c1 + i], st[12 + i]);
    }
    __syncthreads();
    atomicAdd(&sums[t],       ssum[t]);
    atomicAdd(&sums[t + 256], ssum[t + 256]);
}

// ---------------- BN finalize: scale/shift + fused score weights ----------------
__global__ void bn_finalize(const float* __restrict__ sums, const float* __restrict__ g,
                            const float* __restrict__ be, const float* __restrict__ pw,
                            float* __restrict__ scale, float* __restrict__ shift,
                            float* __restrict__ w1a, float invn) {
    __shared__ float red[256];
    __shared__ float sc_s[256], sh_s[256];
    int f = threadIdx.x;
    float mean = sums[f] * invn;
    float var = sums[256 + f] * invn - mean * mean;
    float sc = g[f] * rsqrtf(var + 1e-5f);
    float sh = be[f] - mean * sc;
    scale[f] = sc; shift[f] = sh;
    sc_s[f] = sc; sh_s[f] = sh;
    float w = pw[f];
    red[f] = w * w;
    __syncthreads();
    for (int st = 128; st; st >>= 1) {
        if (f < st) red[f] += red[f + st];
        __syncthreads();
    }
    float pwn = w * rsqrtf(red[0]);
    w1a[f] = sc_s[f] * pwn;        // score weight on raw x
    __syncthreads();
    red[f] = sh_s[f] * pwn;        // score constant offset terms
    __syncthreads();
    for (int st = 128; st; st >>= 1) {
        if (f < st) red[f] += red[f + st];
        __syncthreads();
    }
    if (f == 0) w1a[256] = red[0];
}

// ---------------- pool score: dot(x, w1) + w0 (warp per node, no writeback) ----------------
__global__ void pool_score(const float* __restrict__ x, const float* __restrict__ w1a,
                           float* __restrict__ score, int n) {
    int gw = (blockIdx.x * blockDim.x + threadIdx.x) >> 5;
    int lane = threadIdx.x & 31;
    if (gw >= n) return;
    const float* row = x + (size_t)gw * FD;
    int c0 = lane * 4, c1 = c0 + 128;
    float4 v0 = *(const float4*)(row + c0), v1 = *(const float4*)(row + c1);
    float4 p0 = *(const float4*)&w1a[c0], p1 = *(const float4*)&w1a[c1];
    float s = v0.x * p0.x + v0.y * p0.y + v0.z * p0.z + v0.w * p0.w
            + v1.x * p1.x + v1.y * p1.y + v1.z * p1.z + v1.w * p1.w;
#pragma unroll
    for (int o = 16; o; o >>= 1) s += __shfl_down_sync(~0u, s, o);
    if (lane == 0) score[gw] = s + w1a[256];
}

// ---------------- per-graph top-k via bitonic sort (block per graph) ----------------
__global__ void topk_sort(const float* __restrict__ score, int npg, int k,
                          int* __restrict__ gidx, float* __restrict__ tv,
                          int* __restrict__ inv) {
    __shared__ float sv[1024];
    __shared__ int si[1024];
    int g = blockIdx.x, t = threadIdx.x, nt = blockDim.x;
    for (int e = t; e < npg; e += nt) { sv[e] = score[(size_t)g * npg + e]; si[e] = e; }
    __syncthreads();
    for (int kk = 2; kk <= npg; kk <<= 1) {
        for (int j = kk >> 1; j > 0; j >>= 1) {
            for (int e = t; e < npg; e += nt) {
                int p = e ^ j;
                if (p > e) {
                    bool desc = ((e & kk) == 0);
                    float ve = sv[e], vp = sv[p];
                    if (desc ? (ve < vp) : (ve > vp)) {
                        sv[e] = vp; sv[p] = ve;
                        int tmp = si[e]; si[e] = si[p]; si[p] = tmp;
                    }
                }
            }
            __syncthreads();
        }
    }
    for (int e = t; e < k; e += nt) {
        int pos = g * k + e;
        int node = g * npg + si[e];
        gidx[pos] = node;
        tv[pos] = tanhf(sv[e]);
        if (inv) inv[node] = pos;
    }
}

// ---------------- gather pooled rows, BN applied inline, scaled by tanh ----------------
__global__ void pool_gather(const float* __restrict__ x, const float* __restrict__ sc,
                            const float* __restrict__ sh, const int* __restrict__ gidx,
                            const float* __restrict__ tv, float* __restrict__ xp, int n2) {
    int i = blockIdx.x * blockDim.x + threadIdx.x;
    if (i >= n2 * 64) return;
    int row = i >> 6, c4 = (i & 63) * 4;
    float t = tv[row];
    int node = gidx[row];
    float4 v = *(const float4*)&x[(size_t)node * FD + c4];
    float4 s = *(const float4*)&sc[c4];
    float4 h = *(const float4*)&sh[c4];
    v.x = (v.x * s.x + h.x) * t; v.y = (v.y * s.y + h.y) * t;
    v.z = (v.z * s.z + h.z) * t; v.w = (v.w * s.w + h.w) * t;
    *(float4*)&xp[(size_t)row * FD + c4] = v;
}

// ---------------- readout stage 1: per (graph, chunk) partial max/sum ----------------
__global__ void readout_s1(const float* __restrict__ x, const float* __restrict__ sc,
                           const float* __restrict__ sh, const int* __restrict__ gidx,
                           const float* __restrict__ tv, int k, float* __restrict__ partial) {
    int g = blockIdx.x, c = blockIdx.y, f = threadIdx.x;
    int chunk = k / 8;
    int j0 = c * chunk;
    float mx = -1e30f, sm = 0.f;
    if (gidx) {
        float scf = sc[f], shf = sh[f];
        for (int j = j0; j < j0 + chunk; j++) {
            int node = gidx[g * k + j];
            float v = (x[(size_t)node * FD + f] * scf + shf) * tv[g * k + j];
            mx = fmaxf(mx, v);
            sm += v;
        }
    } else {
        for (int j = j0; j < j0 + chunk; j++) {
            float v = x[((size_t)g * k + j) * FD + f];
            mx = fmaxf(mx, v);
            sm += v;
        }
    }
    partial[((size_t)(g * 8 + c)) * 512 + f] = mx;
    partial[((size_t)(g * 8 + c)) * 512 + 256 + f] = sm;
}

// ---------------- readout stage 2 ----------------
__global__ void readout_s2(const float* __restrict__ partial, int k, float* __restrict__ xg) {
    int g = blockIdx.x, f = threadIdx.x;
    float mx = -1e30f, sm = 0.f;
    for (int c = 0; c < 8; c++) {
        mx = fmaxf(mx, partial[((size_t)(g * 8 + c)) * 512 + f]);
        sm += partial[((size_t)(g * 8 + c)) * 512 + 256 + f];
    }
    xg[(size_t)g * 512 + f] = mx;
    xg[(size_t)g * 512 + 256 + f] = sm / (float)k;
}

// ---------------- final linear: out = (x1+x2) @ Wl^T + bl ----------------
__global__ void final_linear(const float* __restrict__ x1g, const float* __restrict__ x2g,
                             const float* __restrict__ Wl, const float* __restrict__ bl,
                             float* __restrict__ out) {
    __shared__ float xr[512];
    int b = blockIdx.x, t = threadIdx.x;
    xr[t] = x1g[(size_t)b * 512 + t] + x2g[(size_t)b * 512 + t];
    xr[t + 256] = x1g[(size_t)b * 512 + 256 + t] + x2g[(size_t)b * 512 + 256 + t];
    __syncthreads();
    float acc = bl[t];
    const float* w = Wl + (size_t)t * 512;
    for (int kk = 0; kk < 512; kk++) acc += xr[kk] * w[kk];
    out[(size_t)b * 256 + t] = acc;
}

// ---------------- host launcher ----------------
extern "C" void kernel_launch(void* const* d_in, const int* in_sizes, int n_in,
                              void* d_out, int out_size) {
    const float* x    = (const float*)d_in[0];
    const int*   ei   = (const int*)d_in[1];
    const int*   src  = ei;
    const int*   dst  = ei + ED;
    const float* W1   = (const float*)d_in[3];
    const float* as1  = (const float*)d_in[4];
    const float* ad1  = (const float*)d_in[5];
    const float* b1   = (const float*)d_in[6];
    const float* g1   = (const float*)d_in[7];
    const float* be1  = (const float*)d_in[8];
    const float* pw1  = (const float*)d_in[9];
    const float* W2   = (const float*)d_in[10];
    const float* as2  = (const float*)d_in[11];
    const float* ad2  = (const float*)d_in[12];
    const float* b2   = (const float*)d_in[13];
    const float* g2   = (const float*)d_in[14];
    const float* be2  = (const float*)d_in[15];
    const float* pw2  = (const float*)d_in[16];
    const float* Wl   = (const float*)d_in[17];
    const float* bl   = (const float*)d_in[18];
    float* out = (float*)d_out;

    float* fb = nullptr;
    int*   ib = nullptr;
    cudaGetSymbolAddress((void**)&fb, g_f);
    cudaGetSymbolAddress((void**)&ib, g_i);

    float* h1    = fb + O_H1;
    float* out1  = fb + O_OUT1;
    float* asn1  = fb + O_ASN1;
    float* adn1  = fb + O_ADN1;
    float* bns1  = fb + O_BNS1;
    float* sc1   = fb + O_SC1;
    float* sh1   = fb + O_SH1;
    float* w1a   = fb + O_W1A;
    float* score1= fb + O_SCORE1;
    float* tanh1 = fb + O_TANH1;
    float* xp1   = fb + O_XP1;
    float* x1g   = fb + O_X1G;
    float* part  = fb + O_PART;
    float* part2 = fb + O_PART2;
    float* h2    = fb + O_H2;
    float* out2  = fb + O_OUT2;
    float* asn2  = fb + O_ASN2;
    float* adn2  = fb + O_ADN2;
    float* bns2  = fb + O_BNS2;
    float* sc2   = fb + O_SC2;
    float* sh2   = fb + O_SH2;
    float* w2a   = fb + O_W2A;
    float* score2= fb + O_SCORE2;
    float* tanh2 = fb + O_TANH2;
    float* x2g   = fb + O_X2G;
    int* gidx1 = ib + IO_GIDX1;
    int* inv1  = ib + IO_INV1;
    int* gidx2 = ib + IO_GIDX2;
    int* deg1  = ib + IO_DEG1;
    int* csr1  = ib + IO_CSR1;
    int* deg2  = ib + IO_DEG2;
    int* csr2  = ib + IO_CSR2;

    static cudaStream_t s2 = nullptr;
    static cudaEvent_t ev0, ev1, ev2, ev3, ev4, ev5;
    if (!s2) {
        cudaStreamCreateWithFlags(&s2, cudaStreamNonBlocking);
        cudaEventCreateWithFlags(&ev0, cudaEventDisableTiming);
        cudaEventCreateWithFlags(&ev1, cudaEventDisableTiming);
        cudaEventCreateWithFlags(&ev2, cudaEventDisableTiming);
        cudaEventCreateWithFlags(&ev3, cudaEventDisableTiming);
        cudaEventCreateWithFlags(&ev4, cudaEventDisableTiming);
        cudaEventCreateWithFlags(&ev5, cudaEventDisableTiming);
    }

    // fork: side stream does memsets + csr_build1 while main does sgemm1+attn1
    cudaEventRecord(ev0, 0);
    cudaStreamWaitEvent(s2, ev0, 0);
    cudaMemsetAsync(bns1, 0, 512 * sizeof(float), s2);
    cudaMemsetAsync(bns2, 0, 512 * sizeof(float), s2);
    cudaMemsetAsync(deg1, 0, (size_t)NN * sizeof(int), s2);
    cudaMemsetAsync(deg2, 0, (size_t)N2 * sizeof(int), s2);
    cudaMemsetAsync(inv1, 0xFF, (size_t)NN * sizeof(int), s2);
    csr_build<<<(ED + 255) / 256, 256, 0, s2>>>(src, dst, nullptr, deg1, csr1, ED);
    cudaEventRecord(ev1, s2);

    // ---- layer 1 (main stream) ----
    sgemm128<<<dim3(FD / 128, NN / 128), 256>>>(x, W1, h1, NN, FD, INDIM);
    attn_scores<<<NN / 8, 256>>>(h1, as1, ad1, asn1, adn1, NN);
    cudaStreamWaitEvent(0, ev1, 0);
    gat_gather<<<1024, 256>>>(csr1, deg1, asn1, adn1, h1, b1, out1, bns1, NN, NN / 1024);
    bn_finalize<<<1, 256>>>(bns1, g1, be1, pw1, sc1, sh1, w1a, 1.0f / NN);
    pool_score<<<NN / 8, 256>>>(out1, w1a, score1, NN);
    topk_sort<<<BT, NPG / 2>>>(score1, NPG, KP1, gidx1, tanh1, inv1);
    cudaEventRecord(ev2, 0);

    // side stream: csr_build2 (needs inv1 only)
    cudaStreamWaitEvent(s2, ev2, 0);
    csr_build<<<(ED + 255) / 256, 256, 0, s2>>>(src, dst, inv1, deg2, csr2, ED);
    cudaEventRecord(ev3, s2);

    pool_gather<<<(N2 * 64 + 255) / 256, 256>>>(out1, sc1, sh1, gidx1, tanh1, xp1, N2);
    cudaEventRecord(ev4, 0);

    // side stream: layer-1 readout (needs xp1)
    cudaStreamWaitEvent(s2, ev4, 0);
    readout_s1<<<dim3(BT, 8), 256, 0, s2>>>(xp1, nullptr, nullptr, nullptr, nullptr, KP1, part);
    readout_s2<<<BT, 256, 0, s2>>>(part, KP1, x1g);
    cudaEventRecord(ev5, s2);

    // ---- layer 2 (main stream) ----
    sgemm128<<<dim3(FD / 128, N2 / 128), 256>>>(xp1, W2, h2, N2, FD, FD);
    attn_scores<<<N2 / 8, 256>>>(h2, as2, ad2, asn2, adn2, N2);
    cudaStreamWaitEvent(0, ev3, 0);
    gat_gather<<<512, 256>>>(csr2, deg2, asn2, adn2, h2, b2, out2, bns2, N2, N2 / 512);
    bn_finalize<<<1, 256>>>(bns2, g2, be2, pw2, sc2, sh2, w2a, 1.0f / N2);
    pool_score<<<N2 / 8, 256>>>(out2, w2a, score2, N2);
    topk_sort<<<BT, KP1 / 2>>>(score2, KP1, KP2, gidx2, tanh2, nullptr);
    readout_s1<<<dim3(BT, 8), 256>>>(out2, sc2, sh2, gidx2, tanh2, KP2, part2);
    readout_s2<<<BT, 256>>>(part2, KP2, x2g);

    // ---- final (join side stream) ----
    cudaStreamWaitEvent(0, ev5, 0);
    final_linear<<<BT, 256>>>(x1g, x2g, Wl, bl, out);
}

// round 4
// speedup vs baseline: 1.4378x; 1.1001x over previous
#include <cuda_runtime.h>
#include <math.h>

// ---------------- problem constants ----------------
constexpr int NN   = 32768;    // total nodes layer1
constexpr int ED   = 262144;   // edges
constexpr int FD   = 256;      // feature dim (4 heads x 64)
constexpr int BT   = 32;       // graphs
constexpr int NPG  = 1024;
constexpr int KP1  = 512;
constexpr int KP2  = 256;
constexpr int N2   = BT * KP1; // 16384 pooled nodes after pool1
constexpr int INDIM = 128;
constexpr int MAXDEG = 64;     // padded CSR width (Poisson(8) max deg << 64)

// ---------------- scratch layout (floats) ----------------
constexpr size_t O_H1    = 0;
constexpr size_t O_OUT1  = O_H1   + (size_t)NN * FD;
constexpr size_t O_ASN1  = O_OUT1 + (size_t)NN * FD;
constexpr size_t O_ADN1  = O_ASN1 + (size_t)NN * 4;
constexpr size_t O_BNS1  = O_ADN1 + (size_t)NN * 4;
constexpr size_t O_SC1   = O_BNS1 + 512;
constexpr size_t O_SH1   = O_SC1  + 256;
constexpr size_t O_W1A   = O_SH1  + 256;   // 256 + 1 (w1 vector, w0 scalar)
constexpr size_t O_SCORE1= O_W1A  + 260;
constexpr size_t O_TANH1 = O_SCORE1 + NN;
constexpr size_t O_XP1   = O_TANH1  + N2;
constexpr size_t O_X1G   = O_XP1    + (size_t)N2 * FD;
constexpr size_t O_PART  = O_X1G    + (size_t)BT * 512;
constexpr size_t O_PART2 = O_PART   + (size_t)BT * 8 * 512;
constexpr size_t O_H2    = O_PART2  + (size_t)BT * 8 * 512;
constexpr size_t O_OUT2  = O_H2     + (size_t)N2 * FD;
constexpr size_t O_ASN2  = O_OUT2   + (size_t)N2 * FD;
constexpr size_t O_ADN2  = O_ASN2   + (size_t)N2 * 4;
constexpr size_t O_BNS2  = O_ADN2   + (size_t)N2 * 4;
constexpr size_t O_SC2   = O_BNS2   + 512;
constexpr size_t O_SH2   = O_SC2    + 256;
constexpr size_t O_W2A   = O_SH2    + 256;
constexpr size_t O_SCORE2= O_W2A    + 260;
constexpr size_t O_TANH2 = O_SCORE2 + N2;
constexpr size_t O_X2G   = O_TANH2  + (size_t)BT * KP2;
constexpr size_t F_TOTAL = O_X2G    + (size_t)BT * 512;

__device__ float g_f[F_TOTAL];

constexpr size_t IO_GIDX1 = 0;
constexpr size_t IO_INV1  = IO_GIDX1 + N2;
constexpr size_t IO_GIDX2 = IO_INV1  + NN;
constexpr size_t IO_DEG1  = IO_GIDX2 + (size_t)BT * KP2;
constexpr size_t IO_CSR1  = IO_DEG1  + NN;
constexpr size_t IO_DEG2  = IO_CSR1  + (size_t)NN * MAXDEG;
constexpr size_t IO_CSR2  = IO_DEG2  + N2;
constexpr size_t I_TOTAL  = IO_CSR2  + (size_t)N2 * MAXDEG;

__device__ int g_i[I_TOTAL];

// ---------------- SGEMM: C[MxN] = A[MxK] @ B[KxN], 128x128 tile, 8x8/thread ----------------
__global__ __launch_bounds__(256) void sgemm128(const float* __restrict__ A,
                                                const float* __restrict__ B,
                                                float* __restrict__ C,
                                                int M, int N, int K) {
    __shared__ float As[8][132];
    __shared__ float Bs[8][132];
    int tid = threadIdx.x;
    int tx = tid & 15, ty = tid >> 4;
    int m0 = blockIdx.y * 128, n0 = blockIdx.x * 128;
    int arow = tid >> 1, ac4 = (tid & 1) * 4;
    int brow = tid >> 5, bc4 = (tid & 31) * 4;
    float acc[8][8];
#pragma unroll
    for (int i = 0; i < 8; i++)
#pragma unroll
        for (int j = 0; j < 8; j++) acc[i][j] = 0.f;

    for (int k0 = 0; k0 < K; k0 += 8) {
        float4 a = *(const float4*)(A + (size_t)(m0 + arow) * K + k0 + ac4);
        As[ac4 + 0][arow] = a.x; As[ac4 + 1][arow] = a.y;
        As[ac4 + 2][arow] = a.z; As[ac4 + 3][arow] = a.w;
        *(float4*)&Bs[brow][bc4] = *(const float4*)(B + (size_t)(k0 + brow) * N + n0 + bc4);
        __syncthreads();
#pragma unroll
        for (int kk = 0; kk < 8; kk++) {
            float4 a0 = *(float4*)&As[kk][ty * 8], a1 = *(float4*)&As[kk][ty * 8 + 4];
            float4 b0 = *(float4*)&Bs[kk][tx * 8], b1 = *(float4*)&Bs[kk][tx * 8 + 4];
            float av[8] = {a0.x, a0.y, a0.z, a0.w, a1.x, a1.y, a1.z, a1.w};
            float bv[8] = {b0.x, b0.y, b0.z, b0.w, b1.x, b1.y, b1.z, b1.w};
#pragma unroll
            for (int i = 0; i < 8; i++)
#pragma unroll
                for (int j = 0; j < 8; j++) acc[i][j] += av[i] * bv[j];
        }
        __syncthreads();
    }
#pragma unroll
    for (int i = 0; i < 8; i++) {
        float* c = C + (size_t)(m0 + ty * 8 + i) * N + n0 + tx * 8;
        *(float4*)c = make_float4(acc[i][0], acc[i][1], acc[i][2], acc[i][3]);
        *(float4*)(c + 4) = make_float4(acc[i][4], acc[i][5], acc[i][6], acc[i][7]);
    }
}

// ---------------- attention scores per node: asn/adn [n][4] ----------------
__global__ void attn_scores(const float* __restrict__ h, const float* __restrict__ a_s,
                            const float* __restrict__ a_d, float* __restrict__ asn,
                            float* __restrict__ adn, int n) {
    int warp = (blockIdx.x * blockDim.x + threadIdx.x) >> 5;
    int lane = threadIdx.x & 31;
    if (warp >= n) return;
    const float* row = h + (size_t)warp * FD;
#pragma unroll
    for (int hd = 0; hd < 4; hd++) {
        float x0 = row[hd * 64 + lane], x1 = row[hd * 64 + 32 + lane];
        float v1 = x0 * a_s[hd * 64 + lane] + x1 * a_s[hd * 64 + 32 + lane];
        float v2 = x0 * a_d[hd * 64 + lane] + x1 * a_d[hd * 64 + 32 + lane];
#pragma unroll
        for (int o = 16; o; o >>= 1) {
            v1 += __shfl_down_sync(~0u, v1, o);
            v2 += __shfl_down_sync(~0u, v2, o);
        }
        if (lane == 0) { asn[warp * 4 + hd] = v1; adn[warp * 4 + hd] = v2; }
    }
}

// ---------------- padded-CSR build ----------------
__global__ void csr_build(const int* __restrict__ src, const int* __restrict__ dst,
                          const int* __restrict__ inv, int* __restrict__ deg,
                          int* __restrict__ csr, int nE) {
    int i = blockIdx.x * blockDim.x + threadIdx.x;
    if (i >= nE) return;
    int s = src[i], d = dst[i];
    if (inv) { s = inv[s]; d = inv[d]; if (s < 0 || d < 0) return; }
    int p = atomicAdd(&deg[d], 1);
    if (p < MAXDEG) csr[(size_t)d * MAXDEG + p] = s;
}

// ---------------- fused GAT gather: 2-phase (alpha precompute, then feature gather) ----------------
__global__ __launch_bounds__(256) void gat_gather(
    const int* __restrict__ csr, const int* __restrict__ deg,
    const float* __restrict__ asn, const float* __restrict__ adn,
    const float* __restrict__ h, const float* __restrict__ bias,
    float* __restrict__ out, float* __restrict__ sums, int n, int npb) {
    __shared__ float ssum[512];
    __shared__ float sal[8][64][4];   // per-warp normalized alphas
    __shared__ int   sid[8][64];      // per-warp source indices
    int t = threadIdx.x;
    ssum[t] = 0.f; ssum[t + 256] = 0.f;
    __syncthreads();
    int lane = t & 31, w = t >> 5;
    int c0 = lane * 4, c1 = c0 + 128;
    float4 bb0 = *(const float4*)&bias[c0];
    float4 bb1 = *(const float4*)&bias[c1];
    bool hsel = (lane & 16) != 0;     // chunk0 head 0/1; chunk1 head 2/3
    float st[16];
#pragma unroll
    for (int i = 0; i < 16; i++) st[i] = 0.f;

    int base = blockIdx.x * npb;
    int end = base + npb; if (end > n) end = n;
    for (int nd = base + w; nd < end; nd += 8) {
        float4 ad = *(const float4*)&adn[(size_t)nd * 4];
        int dg = deg[nd]; if (dg > 63) dg = 63;   // slot dg = self loop
        const int* row = csr + (size_t)nd * MAXDEG;
        // --- phase 1: per-lane slot -> parallel asn loads + exp ---
        int sA = (lane < dg) ? row[lane] : nd;
        int sB = (lane + 32 < dg) ? row[lane + 32] : nd;
        bool vA = (lane <= dg);
        bool vB = (lane + 32 <= dg);
        float4 aA = *(const float4*)&asn[(size_t)sA * 4];
        float4 aB = *(const float4*)&asn[(size_t)sB * 4];
        float lA0 = aA.x + ad.x, lA1 = aA.y + ad.y, lA2 = aA.z + ad.z, lA3 = aA.w + ad.w;
        float lB0 = aB.x + ad.x, lB1 = aB.y + ad.y, lB2 = aB.z + ad.z, lB3 = aB.w + ad.w;
        lA0 = lA0 > 0.f ? lA0 : 0.2f * lA0;  lB0 = lB0 > 0.f ? lB0 : 0.2f * lB0;
        lA1 = lA1 > 0.f ? lA1 : 0.2f * lA1;  lB1 = lB1 > 0.f ? lB1 : 0.2f * lB1;
        lA2 = lA2 > 0.f ? lA2 : 0.2f * lA2;  lB2 = lB2 > 0.f ? lB2 : 0.2f * lB2;
        lA3 = lA3 > 0.f ? lA3 : 0.2f * lA3;  lB3 = lB3 > 0.f ? lB3 : 0.2f * lB3;
        float pA0 = vA ? __expf(lA0) : 0.f, pA1 = vA ? __expf(lA1) : 0.f;
        float pA2 = vA ? __expf(lA2) : 0.f, pA3 = vA ? __expf(lA3) : 0.f;
        float pB0 = vB ? __expf(lB0) : 0.f, pB1 = vB ? __expf(lB1) : 0.f;
        float pB2 = vB ? __expf(lB2) : 0.f, pB3 = vB ? __expf(lB3) : 0.f;
        // --- butterfly reduce denominators ---
        float d0 = pA0 + pB0, d1 = pA1 + pB1, d2 = pA2 + pB2, d3 = pA3 + pB3;
#pragma unroll
        for (int o = 16; o; o >>= 1) {
            d0 += __shfl_xor_sync(~0u, d0, o);
            d1 += __shfl_xor_sync(~0u, d1, o);
            d2 += __shfl_xor_sync(~0u, d2, o);
            d3 += __shfl_xor_sync(~0u, d3, o);
        }
        float r0 = 1.f / d0, r1 = 1.f / d1, r2 = 1.f / d2, r3 = 1.f / d3;
        __syncwarp();
        sid[w][lane] = sA; sid[w][lane + 32] = sB;
        *(float4*)&sal[w][lane][0]      = make_float4(pA0 * r0, pA1 * r1, pA2 * r2, pA3 * r3);
        *(float4*)&sal[w][lane + 32][0] = make_float4(pB0 * r0, pB1 * r1, pB2 * r2, pB3 * r3);
        __syncwarp();
        // --- phase 2: pipelined feature gather ---
        float4 a0 = make_float4(0, 0, 0, 0), a1 = make_float4(0, 0, 0, 0);
        int ne = dg + 1;
#pragma unroll 4
        for (int e = 0; e < ne; e++) {
            int s = sid[w][e];
            float4 al = *(const float4*)&sal[w][e][0];
            const float4* hr = (const float4*)(h + (size_t)s * FD);
            float4 v0 = hr[lane], v1 = hr[lane + 32];
            float pa = hsel ? al.y : al.x;
            float pb = hsel ? al.w : al.z;
            a0.x += pa * v0.x; a0.y += pa * v0.y; a0.z += pa * v0.z; a0.w += pa * v0.w;
            a1.x += pb * v1.x; a1.y += pb * v1.y; a1.z += pb * v1.z; a1.w += pb * v1.w;
        }
        float o[8];
        o[0] = a0.x + bb0.x; o[1] = a0.y + bb0.y;
        o[2] = a0.z + bb0.z; o[3] = a0.w + bb0.w;
        o[4] = a1.x + bb1.x; o[5] = a1.y + bb1.y;
        o[6] = a1.z + bb1.z; o[7] = a1.w + bb1.w;
#pragma unroll
        for (int i = 0; i < 8; i++) {
            float v = o[i];
            v = 0.5f * v * (1.0f + erff(v * 0.70710678118654752f));
            o[i] = v;
            st[i] += v; st[8 + i] += v * v;
        }
        float* op = out + (size_t)nd * FD;
        *(float4*)(op + c0) = make_float4(o[0], o[1], o[2], o[3]);
        *(float4*)(op + c1) = make_float4(o[4], o[5], o[6], o[7]);
    }
#pragma unroll
    for (int i = 0; i < 4; i++) {
        atomicAdd(&ssum[c0 + i],       st[i]);
        atomicAdd(&ssum[c1 + i],       st[4 + i]);
        atomicAdd(&ssum[256 + c0 + i], st[8 + i]);
        atomicAdd(&ssum[256 + c1 + i], st[12 + i]);
    }
    __syncthreads();
    atomicAdd(&sums[t],       ssum[t]);
    atomicAdd(&sums[t + 256], ssum[t + 256]);
}

// ---------------- BN finalize: scale/shift + fused score weights ----------------
__global__ void bn_finalize(const float* __restrict__ sums, const float* __restrict__ g,
                            const float* __restrict__ be, const float* __restrict__ pw,
                            float* __restrict__ scale, float* __restrict__ shift,
                            float* __restrict__ w1a, float invn) {
    __shared__ float red[256];
    __shared__ float sc_s[256], sh_s[256];
    int f = threadIdx.x;
    float mean = sums[f] * invn;
    float var = sums[256 + f] * invn - mean * mean;
    float sc = g[f] * rsqrtf(var + 1e-5f);
    float sh = be[f] - mean * sc;
    scale[f] = sc; shift[f] = sh;
    sc_s[f] = sc; sh_s[f] = sh;
    float w = pw[f];
    red[f] = w * w;
    __syncthreads();
    for (int st = 128; st; st >>= 1) {
        if (f < st) red[f] += red[f + st];
        __syncthreads();
    }
    float pwn = w * rsqrtf(red[0]);
    w1a[f] = sc_s[f] * pwn;        // score weight on raw x
    __syncthreads();
    red[f] = sh_s[f] * pwn;        // score constant offset terms
    __syncthreads();
    for (int st = 128; st; st >>= 1) {
        if (f < st) red[f] += red[f + st];
        __syncthreads();
    }
    if (f == 0) w1a[256] = red[0];
}

// ---------------- pool score: dot(x, w1) + w0 (warp per node, no writeback) ----------------
__global__ void pool_score(const float* __restrict__ x, const float* __restrict__ w1a,
                           float* __restrict__ score, int n) {
    int gw = (blockIdx.x * blockDim.x + threadIdx.x) >> 5;
    int lane = threadIdx.x & 31;
    if (gw >= n) return;
    const float* row = x + (size_t)gw * FD;
    int c0 = lane * 4, c1 = c0 + 128;
    float4 v0 = *(const float4*)(row + c0), v1 = *(const float4*)(row + c1);
    float4 p0 = *(const float4*)&w1a[c0], p1 = *(const float4*)&w1a[c1];
    float s = v0.x * p0.x + v0.y * p0.y + v0.z * p0.z + v0.w * p0.w
            + v1.x * p1.x + v1.y * p1.y + v1.z * p1.z + v1.w * p1.w;
#pragma unroll
    for (int o = 16; o; o >>= 1) s += __shfl_down_sync(~0u, s, o);
    if (lane == 0) score[gw] = s + w1a[256];
}

// ---------------- per-graph top-k via bitonic sort (block per graph) ----------------
__global__ void topk_sort(const float* __restrict__ score, int npg, int k,
                          int* __restrict__ gidx, float* __restrict__ tv,
                          int* __restrict__ inv) {
    __shared__ float sv[1024];
    __shared__ int si[1024];
    int g = blockIdx.x, t = threadIdx.x, nt = blockDim.x;
    for (int e = t; e < npg; e += nt) { sv[e] = score[(size_t)g * npg + e]; si[e] = e; }
    __syncthreads();
    for (int kk = 2; kk <= npg; kk <<= 1) {
        for (int j = kk >> 1; j > 0; j >>= 1) {
            for (int e = t; e < npg; e += nt) {
                int p = e ^ j;
                if (p > e) {
                    bool desc = ((e & kk) == 0);
                    float ve = sv[e], vp = sv[p];
                    if (desc ? (ve < vp) : (ve > vp)) {
                        sv[e] = vp; sv[p] = ve;
                        int tmp = si[e]; si[e] = si[p]; si[p] = tmp;
                    }
                }
            }
            __syncthreads();
        }
    }
    for (int e = t; e < k; e += nt) {
        int pos = g * k + e;
        int node = g * npg + si[e];
        gidx[pos] = node;
        tv[pos] = tanhf(sv[e]);
        if (inv) inv[node] = pos;
    }
}

// ---------------- gather pooled rows, BN applied inline, scaled by tanh ----------------
__global__ void pool_gather(const float* __restrict__ x, const float* __restrict__ sc,
                            const float* __restrict__ sh, const int* __restrict__ gidx,
                            const float* __restrict__ tv, float* __restrict__ xp, int n2) {
    int i = blockIdx.x * blockDim.x + threadIdx.x;
    if (i >= n2 * 64) return;
    int row = i >> 6, c4 = (i & 63) * 4;
    float t = tv[row];
    int node = gidx[row];
    float4 v = *(const float4*)&x[(size_t)node * FD + c4];
    float4 s = *(const float4*)&sc[c4];
    float4 h = *(const float4*)&sh[c4];
    v.x = (v.x * s.x + h.x) * t; v.y = (v.y * s.y + h.y) * t;
    v.z = (v.z * s.z + h.z) * t; v.w = (v.w * s.w + h.w) * t;
    *(float4*)&xp[(size_t)row * FD + c4] = v;
}

// ---------------- readout stage 1: per (graph, chunk) partial max/sum ----------------
__global__ void readout_s1(const float* __restrict__ x, const float* __restrict__ sc,
                           const float* __restrict__ sh, const int* __restrict__ gidx,
                           const float* __restrict__ tv, int k, float* __restrict__ partial) {
    int g = blockIdx.x, c = blockIdx.y, f = threadIdx.x;
    int chunk = k / 8;
    int j0 = c * chunk;
    float mx = -1e30f, sm = 0.f;
    if (gidx) {
        float scf = sc[f], shf = sh[f];
        for (int j = j0; j < j0 + chunk; j++) {
            int node = gidx[g * k + j];
            float v = (x[(size_t)node * FD + f] * scf + shf) * tv[g * k + j];
            mx = fmaxf(mx, v);
            sm += v;
        }
    } else {
        for (int j = j0; j < j0 + chunk; j++) {
            float v = x[((size_t)g * k + j) * FD + f];
            mx = fmaxf(mx, v);
            sm += v;
        }
    }
    partial[((size_t)(g * 8 + c)) * 512 + f] = mx;
    partial[((size_t)(g * 8 + c)) * 512 + 256 + f] = sm;
}

// ---------------- readout stage 2 ----------------
__global__ void readout_s2(const float* __restrict__ partial, int k, float* __restrict__ xg) {
    int g = blockIdx.x, f = threadIdx.x;
    float mx = -1e30f, sm = 0.f;
    for (int c = 0; c < 8; c++) {
        mx = fmaxf(mx, partial[((size_t)(g * 8 + c)) * 512 + f]);
        sm += partial[((size_t)(g * 8 + c)) * 512 + 256 + f];
    }
    xg[(size_t)g * 512 + f] = mx;
    xg[(size_t)g * 512 + 256 + f] = sm / (float)k;
}

// ---------------- final linear: out = (x1+x2) @ Wl^T + bl ----------------
__global__ void final_linear(const float* __restrict__ x1g, const float* __restrict__ x2g,
                             const float* __restrict__ Wl, const float* __restrict__ bl,
                             float* __restrict__ out) {
    __shared__ float xr[512];
    int b = blockIdx.x, t = threadIdx.x;
    xr[t] = x1g[(size_t)b * 512 + t] + x2g[(size_t)b * 512 + t];
    xr[t + 256] = x1g[(size_t)b * 512 + 256 + t] + x2g[(size_t)b * 512 + 256 + t];
    __syncthreads();
    float acc = bl[t];
    const float* w = Wl + (size_t)t * 512;
    for (int kk = 0; kk < 512; kk++) acc += xr[kk] * w[kk];
    out[(size_t)b * 256 + t] = acc;
}

// ---------------- host launcher ----------------
extern "C" void kernel_launch(void* const* d_in, const int* in_sizes, int n_in,
                              void* d_out, int out_size) {
    const float* x    = (const float*)d_in[0];
    const int*   ei   = (const int*)d_in[1];
    const int*   src  = ei;
    const int*   dst  = ei + ED;
    const float* W1   = (const float*)d_in[3];
    const float* as1  = (const float*)d_in[4];
    const float* ad1  = (const float*)d_in[5];
    const float* b1   = (const float*)d_in[6];
    const float* g1   = (const float*)d_in[7];
    const float* be1  = (const float*)d_in[8];
    const float* pw1  = (const float*)d_in[9];
    const float* W2   = (const float*)d_in[10];
    const float* as2  = (const float*)d_in[11];
    const float* ad2  = (const float*)d_in[12];
    const float* b2   = (const float*)d_in[13];
    const float* g2   = (const float*)d_in[14];
    const float* be2  = (const float*)d_in[15];
    const float* pw2  = (const float*)d_in[16];
    const float* Wl   = (const float*)d_in[17];
    const float* bl   = (const float*)d_in[18];
    float* out = (float*)d_out;

    float* fb = nullptr;
    int*   ib = nullptr;
    cudaGetSymbolAddress((void**)&fb, g_f);
    cudaGetSymbolAddress((void**)&ib, g_i);

    float* h1    = fb + O_H1;
    float* out1  = fb + O_OUT1;
    float* asn1  = fb + O_ASN1;
    float* adn1  = fb + O_ADN1;
    float* bns1  = fb + O_BNS1;
    float* sc1   = fb + O_SC1;
    float* sh1   = fb + O_SH1;
    float* w1a   = fb + O_W1A;
    float* score1= fb + O_SCORE1;
    float* tanh1 = fb + O_TANH1;
    float* xp1   = fb + O_XP1;
    float* x1g   = fb + O_X1G;
    float* part  = fb + O_PART;
    float* part2 = fb + O_PART2;
    float* h2    = fb + O_H2;
    float* out2  = fb + O_OUT2;
    float* asn2  = fb + O_ASN2;
    float* adn2  = fb + O_ADN2;
    float* bns2  = fb + O_BNS2;
    float* sc2   = fb + O_SC2;
    float* sh2   = fb + O_SH2;
    float* w2a   = fb + O_W2A;
    float* score2= fb + O_SCORE2;
    float* tanh2 = fb + O_TANH2;
    float* x2g   = fb + O_X2G;
    int* gidx1 = ib + IO_GIDX1;
    int* inv1  = ib + IO_INV1;
    int* gidx2 = ib + IO_GIDX2;
    int* deg1  = ib + IO_DEG1;
    int* csr1  = ib + IO_CSR1;
    int* deg2  = ib + IO_DEG2;
    int* csr2  = ib + IO_CSR2;

    static cudaStream_t s2 = nullptr;
    static cudaEvent_t ev0, ev1, ev2, ev3, ev4, ev5;
    if (!s2) {
        cudaStreamCreateWithFlags(&s2, cudaStreamNonBlocking);
        cudaEventCreateWithFlags(&ev0, cudaEventDisableTiming);
        cudaEventCreateWithFlags(&ev1, cudaEventDisableTiming);
        cudaEventCreateWithFlags(&ev2, cudaEventDisableTiming);
        cudaEventCreateWithFlags(&ev3, cudaEventDisableTiming);
        cudaEventCreateWithFlags(&ev4, cudaEventDisableTiming);
        cudaEventCreateWithFlags(&ev5, cudaEventDisableTiming);
    }

    // fork: side stream does memsets + csr_build1 while main does sgemm1+attn1
    cudaEventRecord(ev0, 0);
    cudaStreamWaitEvent(s2, ev0, 0);
    cudaMemsetAsync(bns1, 0, 512 * sizeof(float), s2);
    cudaMemsetAsync(bns2, 0, 512 * sizeof(float), s2);
    cudaMemsetAsync(deg1, 0, (size_t)NN * sizeof(int), s2);
    cudaMemsetAsync(deg2, 0, (size_t)N2 * sizeof(int), s2);
    cudaMemsetAsync(inv1, 0xFF, (size_t)NN * sizeof(int), s2);
    csr_build<<<(ED + 255) / 256, 256, 0, s2>>>(src, dst, nullptr, deg1, csr1, ED);
    cudaEventRecord(ev1, s2);

    // ---- layer 1 (main stream) ----
    sgemm128<<<dim3(FD / 128, NN / 128), 256>>>(x, W1, h1, NN, FD, INDIM);
    attn_scores<<<NN / 8, 256>>>(h1, as1, ad1, asn1, adn1, NN);
    cudaStreamWaitEvent(0, ev1, 0);
    gat_gather<<<2048, 256>>>(csr1, deg1, asn1, adn1, h1, b1, out1, bns1, NN, NN / 2048);
    bn_finalize<<<1, 256>>>(bns1, g1, be1, pw1, sc1, sh1, w1a, 1.0f / NN);
    pool_score<<<NN / 8, 256>>>(out1, w1a, score1, NN);
    topk_sort<<<BT, NPG / 2>>>(score1, NPG, KP1, gidx1, tanh1, inv1);
    cudaEventRecord(ev2, 0);

    // side stream: csr_build2 (needs inv1 only)
    cudaStreamWaitEvent(s2, ev2, 0);
    csr_build<<<(ED + 255) / 256, 256, 0, s2>>>(src, dst, inv1, deg2, csr2, ED);
    cudaEventRecord(ev3, s2);

    pool_gather<<<(N2 * 64 + 255) / 256, 256>>>(out1, sc1, sh1, gidx1, tanh1, xp1, N2);
    cudaEventRecord(ev4, 0);

    // side stream: layer-1 readout (needs xp1)
    cudaStreamWaitEvent(s2, ev4, 0);
    readout_s1<<<dim3(BT, 8), 256, 0, s2>>>(xp1, nullptr, nullptr, nullptr, nullptr, KP1, part);
    readout_s2<<<BT, 256, 0, s2>>>(part, KP1, x1g);
    cudaEventRecord(ev5, s2);

    // ---- layer 2 (main stream) ----
    sgemm128<<<dim3(FD / 128, N2 / 128), 256>>>(xp1, W2, h2, N2, FD, FD);
    attn_scores<<<N2 / 8, 256>>>(h2, as2, ad2, asn2, adn2, N2);
    cudaStreamWaitEvent(0, ev3, 0);
    gat_gather<<<1024, 256>>>(csr2, deg2, asn2, adn2, h2, b2, out2, bns2, N2, N2 / 1024);
    bn_finalize<<<1, 256>>>(bns2, g2, be2, pw2, sc2, sh2, w2a, 1.0f / N2);
    pool_score<<<N2 / 8, 256>>>(out2, w2a, score2, N2);
    topk_sort<<<BT, KP1 / 2>>>(score2, KP1, KP2, gidx2, tanh2, nullptr);
    readout_s1<<<dim3(BT, 8), 256>>>(out2, sc2, sh2, gidx2, tanh2, KP2, part2);
    readout_s2<<<BT, 256>>>(part2, KP2, x2g);

    // ---- final (join side stream) ----
    cudaStreamWaitEvent(0, ev5, 0);
    final_linear<<<BT, 256>>>(x1g, x2g, Wl, bl, out);
}

// round 5
// speedup vs baseline: 1.4937x; 1.0389x over previous
#include <cuda_runtime.h>
#include <math.h>

// ---------------- problem constants ----------------
constexpr int NN   = 32768;    // total nodes layer1
constexpr int ED   = 262144;   // edges
constexpr int FD   = 256;      // feature dim (4 heads x 64)
constexpr int BT   = 32;       // graphs
constexpr int NPG  = 1024;
constexpr int KP1  = 512;
constexpr int KP2  = 256;
constexpr int N2   = BT * KP1; // 16384 pooled nodes after pool1
constexpr int INDIM = 128;
constexpr int MAXDEG = 64;     // padded CSR width (Poisson(8) max deg << 64)

// ---------------- scratch layout (floats) ----------------
constexpr size_t O_H1    = 0;
constexpr size_t O_OUT1  = O_H1   + (size_t)NN * FD;
constexpr size_t O_ASN1  = O_OUT1 + (size_t)NN * FD;
constexpr size_t O_ADN1  = O_ASN1 + (size_t)NN * 4;
constexpr size_t O_BNS1  = O_ADN1 + (size_t)NN * 4;
constexpr size_t O_SC1   = O_BNS1 + 512;
constexpr size_t O_SH1   = O_SC1  + 256;
constexpr size_t O_W1A   = O_SH1  + 256;   // 256 + 1 (w1 vector, w0 scalar)
constexpr size_t O_SCORE1= O_W1A  + 260;
constexpr size_t O_TANH1 = O_SCORE1 + NN;
constexpr size_t O_XP1   = O_TANH1  + N2;
constexpr size_t O_X1G   = O_XP1    + (size_t)N2 * FD;
constexpr size_t O_PART  = O_X1G    + (size_t)BT * 512;
constexpr size_t O_PART2 = O_PART   + (size_t)BT * 8 * 512;
constexpr size_t O_H2    = O_PART2  + (size_t)BT * 8 * 512;
constexpr size_t O_OUT2  = O_H2     + (size_t)N2 * FD;
constexpr size_t O_ASN2  = O_OUT2   + (size_t)N2 * FD;
constexpr size_t O_ADN2  = O_ASN2   + (size_t)N2 * 4;
constexpr size_t O_BNS2  = O_ADN2   + (size_t)N2 * 4;
constexpr size_t O_SC2   = O_BNS2   + 512;
constexpr size_t O_SH2   = O_SC2    + 256;
constexpr size_t O_W2A   = O_SH2    + 256;
constexpr size_t O_SCORE2= O_W2A    + 260;
constexpr size_t O_TANH2 = O_SCORE2 + N2;
constexpr size_t O_X2G   = O_TANH2  + (size_t)BT * KP2;
constexpr size_t F_TOTAL = O_X2G    + (size_t)BT * 512;

__device__ float g_f[F_TOTAL];

constexpr size_t IO_GIDX1 = 0;
constexpr size_t IO_INV1  = IO_GIDX1 + N2;
constexpr size_t IO_GIDX2 = IO_INV1  + NN;
constexpr size_t IO_DEG1  = IO_GIDX2 + (size_t)BT * KP2;
constexpr size_t IO_CSR1  = IO_DEG1  + NN;
constexpr size_t IO_DEG2  = IO_CSR1  + (size_t)NN * MAXDEG;
constexpr size_t IO_CSR2  = IO_DEG2  + N2;
constexpr size_t I_TOTAL  = IO_CSR2  + (size_t)N2 * MAXDEG;

__device__ int g_i[I_TOTAL];

// ---------------- SGEMM: C[MxN] = A[MxK] @ B[KxN], 128x128 tile, 8x8/thread ----------------
// register-prefetch software pipeline
__global__ __launch_bounds__(256) void sgemm128(const float* __restrict__ A,
                                                const float* __restrict__ B,
                                                float* __restrict__ C,
                                                int M, int N, int K) {
    __shared__ float As[8][132];
    __shared__ float Bs[8][132];
    int tid = threadIdx.x;
    int tx = tid & 15, ty = tid >> 4;
    int m0 = blockIdx.y * 128, n0 = blockIdx.x * 128;
    int arow = tid >> 1, ac4 = (tid & 1) * 4;
    int brow = tid >> 5, bc4 = (tid & 31) * 4;
    float acc[8][8];
#pragma unroll
    for (int i = 0; i < 8; i++)
#pragma unroll
        for (int j = 0; j < 8; j++) acc[i][j] = 0.f;

    const float* Aptr = A + (size_t)(m0 + arow) * K + ac4;
    const float* Bptr = B + (size_t)brow * N + n0 + bc4;

    float4 pa = *(const float4*)(Aptr);
    float4 pb = *(const float4*)(Bptr);

    for (int k0 = 0; k0 < K; k0 += 8) {
        As[ac4 + 0][arow] = pa.x; As[ac4 + 1][arow] = pa.y;
        As[ac4 + 2][arow] = pa.z; As[ac4 + 3][arow] = pa.w;
        *(float4*)&Bs[brow][bc4] = pb;
        __syncthreads();
        if (k0 + 8 < K) {
            pa = *(const float4*)(Aptr + k0 + 8);
            pb = *(const float4*)(Bptr + (size_t)(k0 + 8) * N);
        }
#pragma unroll
        for (int kk = 0; kk < 8; kk++) {
            float4 a0 = *(float4*)&As[kk][ty * 8], a1 = *(float4*)&As[kk][ty * 8 + 4];
            float4 b0 = *(float4*)&Bs[kk][tx * 8], b1 = *(float4*)&Bs[kk][tx * 8 + 4];
            float av[8] = {a0.x, a0.y, a0.z, a0.w, a1.x, a1.y, a1.z, a1.w};
            float bv[8] = {b0.x, b0.y, b0.z, b0.w, b1.x, b1.y, b1.z, b1.w};
#pragma unroll
            for (int i = 0; i < 8; i++)
#pragma unroll
                for (int j = 0; j < 8; j++) acc[i][j] += av[i] * bv[j];
        }
        __syncthreads();
    }
#pragma unroll
    for (int i = 0; i < 8; i++) {
        float* c = C + (size_t)(m0 + ty * 8 + i) * N + n0 + tx * 8;
        *(float4*)c = make_float4(acc[i][0], acc[i][1], acc[i][2], acc[i][3]);
        *(float4*)(c + 4) = make_float4(acc[i][4], acc[i][5], acc[i][6], acc[i][7]);
    }
}

// ---------------- attention scores per node: asn/adn [n][4] ----------------
__global__ void attn_scores(const float* __restrict__ h, const float* __restrict__ a_s,
                            const float* __restrict__ a_d, float* __restrict__ asn,
                            float* __restrict__ adn, int n) {
    int warp = (blockIdx.x * blockDim.x + threadIdx.x) >> 5;
    int lane = threadIdx.x & 31;
    if (warp >= n) return;
    const float* row = h + (size_t)warp * FD;
#pragma unroll
    for (int hd = 0; hd < 4; hd++) {
        float x0 = row[hd * 64 + lane], x1 = row[hd * 64 + 32 + lane];
        float v1 = x0 * a_s[hd * 64 + lane] + x1 * a_s[hd * 64 + 32 + lane];
        float v2 = x0 * a_d[hd * 64 + lane] + x1 * a_d[hd * 64 + 32 + lane];
#pragma unroll
        for (int o = 16; o; o >>= 1) {
            v1 += __shfl_down_sync(~0u, v1, o);
            v2 += __shfl_down_sync(~0u, v2, o);
        }
        if (lane == 0) { asn[warp * 4 + hd] = v1; adn[warp * 4 + hd] = v2; }
    }
}

// ---------------- padded-CSR build ----------------
__global__ void csr_build(const int* __restrict__ src, const int* __restrict__ dst,
                          const int* __restrict__ inv, int* __restrict__ deg,
                          int* __restrict__ csr, int nE) {
    int i = blockIdx.x * blockDim.x + threadIdx.x;
    if (i >= nE) return;
    int s = src[i], d = dst[i];
    if (inv) { s = inv[s]; d = inv[d]; if (s < 0 || d < 0) return; }
    int p = atomicAdd(&deg[d], 1);
    if (p < MAXDEG) csr[(size_t)d * MAXDEG + p] = s;
}

// ---------------- fused GAT gather v3: warp = (node, 128-feature half) ----------------
// upb MUST be even so each warp keeps a fixed half (feature chunk).
__global__ __launch_bounds__(256) void gat_gather(
    const int* __restrict__ csr, const int* __restrict__ deg,
    const float* __restrict__ asn, const float* __restrict__ adn,
    const float* __restrict__ h, const float* __restrict__ bias,
    float* __restrict__ out, float* __restrict__ sums, int n, int upb) {
    __shared__ float ssum[512];
    __shared__ float2 sal[8][64];   // per-warp normalized alphas (2 heads)
    __shared__ int    sid[8][64];   // per-warp source indices
    int t = threadIdx.x;
    ssum[t] = 0.f; ssum[t + 256] = 0.f;
    __syncthreads();
    int lane = t & 31, w = t >> 5;
    int half = (blockIdx.x * upb + w) & 1;   // invariant across iterations (upb even)
    int c = half * 128 + lane * 4;           // this lane's 4 features
    float4 bb = *(const float4*)&bias[c];
    float st[8];
#pragma unroll
    for (int i = 0; i < 8; i++) st[i] = 0.f;

    int base = blockIdx.x * upb;
    int end = base + upb; if (end > 2 * n) end = 2 * n;
    for (int u = base + w; u < end; u += 8) {
        int nd = u >> 1;
        float2 ad = *(const float2*)&adn[(size_t)nd * 4 + half * 2];
        int dg = deg[nd]; if (dg > 63) dg = 63;   // slot dg = self loop
        const int* row = csr + (size_t)nd * MAXDEG;
        // --- phase 1: per-lane slot -> parallel asn loads + exp (2 heads) ---
        int sA = (lane < dg) ? row[lane] : nd;
        int sB = (lane + 32 < dg) ? row[lane + 32] : nd;
        bool vA = (lane <= dg);
        bool vB = (lane + 32 <= dg);
        float2 aA = *(const float2*)&asn[(size_t)sA * 4 + half * 2];
        float2 aB = *(const float2*)&asn[(size_t)sB * 4 + half * 2];
        float lA0 = aA.x + ad.x, lA1 = aA.y + ad.y;
        float lB0 = aB.x + ad.x, lB1 = aB.y + ad.y;
        lA0 = lA0 > 0.f ? lA0 : 0.2f * lA0;  lB0 = lB0 > 0.f ? lB0 : 0.2f * lB0;
        lA1 = lA1 > 0.f ? lA1 : 0.2f * lA1;  lB1 = lB1 > 0.f ? lB1 : 0.2f * lB1;
        float pA0 = vA ? __expf(lA0) : 0.f, pA1 = vA ? __expf(lA1) : 0.f;
        float pB0 = vB ? __expf(lB0) : 0.f, pB1 = vB ? __expf(lB1) : 0.f;
        float d0 = pA0 + pB0, d1 = pA1 + pB1;
#pragma unroll
        for (int o = 16; o; o >>= 1) {
            d0 += __shfl_xor_sync(~0u, d0, o);
            d1 += __shfl_xor_sync(~0u, d1, o);
        }
        float r0 = 1.f / d0, r1 = 1.f / d1;
        __syncwarp();
        sid[w][lane] = sA; sid[w][lane + 32] = sB;
        sal[w][lane]      = make_float2(pA0 * r0, pA1 * r1);
        sal[w][lane + 32] = make_float2(pB0 * r0, pB1 * r1);
        __syncwarp();
        // --- phase 2: pipelined feature gather (1 LDG.128 per lane per edge) ---
        float4 a0 = make_float4(0, 0, 0, 0);
        int ne = dg + 1;
#pragma unroll 4
        for (int e = 0; e < ne; e++) {
            int s = sid[w][e];
            float2 al = sal[w][e];
            float4 v = *(const float4*)(h + (size_t)s * FD + c);
            float p = (lane & 16) ? al.y : al.x;
            a0.x += p * v.x; a0.y += p * v.y; a0.z += p * v.z; a0.w += p * v.w;
        }
        float o[4];
        o[0] = a0.x + bb.x; o[1] = a0.y + bb.y;
        o[2] = a0.z + bb.z; o[3] = a0.w + bb.w;
#pragma unroll
        for (int i = 0; i < 4; i++) {
            float v = o[i];
            v = 0.5f * v * (1.0f + erff(v * 0.70710678118654752f));
            o[i] = v;
            st[i] += v; st[4 + i] += v * v;
        }
        *(float4*)(out + (size_t)nd * FD + c) = make_float4(o[0], o[1], o[2], o[3]);
    }
#pragma unroll
    for (int i = 0; i < 4; i++) {
        atomicAdd(&ssum[c + i],       st[i]);
        atomicAdd(&ssum[256 + c + i], st[4 + i]);
    }
    __syncthreads();
    atomicAdd(&sums[t],       ssum[t]);
    atomicAdd(&sums[t + 256], ssum[t + 256]);
}

// ---------------- BN finalize: scale/shift + fused score weights ----------------
__global__ void bn_finalize(const float* __restrict__ sums, const float* __restrict__ g,
                            const float* __restrict__ be, const float* __restrict__ pw,
                            float* __restrict__ scale, float* __restrict__ shift,
                            float* __restrict__ w1a, float invn) {
    __shared__ float red[256];
    __shared__ float sc_s[256], sh_s[256];
    int f = threadIdx.x;
    float mean = sums[f] * invn;
    float var = sums[256 + f] * invn - mean * mean;
    float sc = g[f] * rsqrtf(var + 1e-5f);
    float sh = be[f] - mean * sc;
    scale[f] = sc; shift[f] = sh;
    sc_s[f] = sc; sh_s[f] = sh;
    float w = pw[f];
    red[f] = w * w;
    __syncthreads();
    for (int st = 128; st; st >>= 1) {
        if (f < st) red[f] += red[f + st];
        __syncthreads();
    }
    float pwn = w * rsqrtf(red[0]);
    w1a[f] = sc_s[f] * pwn;        // score weight on raw x
    __syncthreads();
    red[f] = sh_s[f] * pwn;        // score constant offset terms
    __syncthreads();
    for (int st = 128; st; st >>= 1) {
        if (f < st) red[f] += red[f + st];
        __syncthreads();
    }
    if (f == 0) w1a[256] = red[0];
}

// ---------------- pool score: dot(x, w1) + w0 (warp per node, no writeback) ----------------
__global__ void pool_score(const float* __restrict__ x, const float* __restrict__ w1a,
                           float* __restrict__ score, int n) {
    int gw = (blockIdx.x * blockDim.x + threadIdx.x) >> 5;
    int lane = threadIdx.x & 31;
    if (gw >= n) return;
    const float* row = x + (size_t)gw * FD;
    int c0 = lane * 4, c1 = c0 + 128;
    float4 v0 = *(const float4*)(row + c0), v1 = *(const float4*)(row + c1);
    float4 p0 = *(const float4*)&w1a[c0], p1 = *(const float4*)&w1a[c1];
    float s = v0.x * p0.x + v0.y * p0.y + v0.z * p0.z + v0.w * p0.w
            + v1.x * p1.x + v1.y * p1.y + v1.z * p1.z + v1.w * p1.w;
#pragma unroll
    for (int o = 16; o; o >>= 1) s += __shfl_down_sync(~0u, s, o);
    if (lane == 0) score[gw] = s + w1a[256];
}

// ---------------- per-graph top-k via bitonic sort (block per graph) ----------------
__global__ void topk_sort(const float* __restrict__ score, int npg, int k,
                          int* __restrict__ gidx, float* __restrict__ tv,
                          int* __restrict__ inv) {
    __shared__ float sv[1024];
    __shared__ int si[1024];
    int g = blockIdx.x, t = threadIdx.x, nt = blockDim.x;
    for (int e = t; e < npg; e += nt) { sv[e] = score[(size_t)g * npg + e]; si[e] = e; }
    __syncthreads();
    for (int kk = 2; kk <= npg; kk <<= 1) {
        for (int j = kk >> 1; j > 0; j >>= 1) {
            for (int e = t; e < npg; e += nt) {
                int p = e ^ j;
                if (p > e) {
                    bool desc = ((e & kk) == 0);
                    float ve = sv[e], vp = sv[p];
                    if (desc ? (ve < vp) : (ve > vp)) {
                        sv[e] = vp; sv[p] = ve;
                        int tmp = si[e]; si[e] = si[p]; si[p] = tmp;
                    }
                }
            }
            __syncthreads();
        }
    }
    for (int e = t; e < k; e += nt) {
        int pos = g * k + e;
        int node = g * npg + si[e];
        gidx[pos] = node;
        tv[pos] = tanhf(sv[e]);
        if (inv) inv[node] = pos;
    }
}

// ---------------- gather pooled rows, BN applied inline, scaled by tanh ----------------
__global__ void pool_gather(const float* __restrict__ x, const float* __restrict__ sc,
                            const float* __restrict__ sh, const int* __restrict__ gidx,
                            const float* __restrict__ tv, float* __restrict__ xp, int n2) {
    int i = blockIdx.x * blockDim.x + threadIdx.x;
    if (i >= n2 * 64) return;
    int row = i >> 6, c4 = (i & 63) * 4;
    float t = tv[row];
    int node = gidx[row];
    float4 v = *(const float4*)&x[(size_t)node * FD + c4];
    float4 s = *(const float4*)&sc[c4];
    float4 h = *(const float4*)&sh[c4];
    v.x = (v.x * s.x + h.x) * t; v.y = (v.y * s.y + h.y) * t;
    v.z = (v.z * s.z + h.z) * t; v.w = (v.w * s.w + h.w) * t;
    *(float4*)&xp[(size_t)row * FD + c4] = v;
}

// ---------------- readout stage 1: per (graph, chunk) partial max/sum ----------------
__global__ void readout_s1(const float* __restrict__ x, const float* __restrict__ sc,
                           const float* __restrict__ sh, const int* __restrict__ gidx,
                           const float* __restrict__ tv, int k, float* __restrict__ partial) {
    int g = blockIdx.x, c = blockIdx.y, f = threadIdx.x;
    int chunk = k / 8;
    int j0 = c * chunk;
    float mx = -1e30f, sm = 0.f;
    if (gidx) {
        float scf = sc[f], shf = sh[f];
        for (int j = j0; j < j0 + chunk; j++) {
            int node = gidx[g * k + j];
            float v = (x[(size_t)node * FD + f] * scf + shf) * tv[g * k + j];
            mx = fmaxf(mx, v);
            sm += v;
        }
    } else {
        for (int j = j0; j < j0 + chunk; j++) {
            float v = x[((size_t)g * k + j) * FD + f];
            mx = fmaxf(mx, v);
            sm += v;
        }
    }
    partial[((size_t)(g * 8 + c)) * 512 + f] = mx;
    partial[((size_t)(g * 8 + c)) * 512 + 256 + f] = sm;
}

// ---------------- readout stage 2 ----------------
__global__ void readout_s2(const float* __restrict__ partial, int k, float* __restrict__ xg) {
    int g = blockIdx.x, f = threadIdx.x;
    float mx = -1e30f, sm = 0.f;
    for (int c = 0; c < 8; c++) {
        mx = fmaxf(mx, partial[((size_t)(g * 8 + c)) * 512 + f]);
        sm += partial[((size_t)(g * 8 + c)) * 512 + 256 + f];
    }
    xg[(size_t)g * 512 + f] = mx;
    xg[(size_t)g * 512 + 256 + f] = sm / (float)k;
}

// ---------------- final linear: out = (x1+x2) @ Wl^T + bl ----------------
__global__ void final_linear(const float* __restrict__ x1g, const float* __restrict__ x2g,
                             const float* __restrict__ Wl, const float* __restrict__ bl,
                             float* __restrict__ out) {
    __shared__ float xr[512];
    int b = blockIdx.x, t = threadIdx.x;
    xr[t] = x1g[(size_t)b * 512 + t] + x2g[(size_t)b * 512 + t];
    xr[t + 256] = x1g[(size_t)b * 512 + 256 + t] + x2g[(size_t)b * 512 + 256 + t];
    __syncthreads();
    float acc = bl[t];
    const float* w = Wl + (size_t)t * 512;
    for (int kk = 0; kk < 512; kk++) acc += xr[kk] * w[kk];
    out[(size_t)b * 256 + t] = acc;
}

// ---------------- host launcher ----------------
extern "C" void kernel_launch(void* const* d_in, const int* in_sizes, int n_in,
                              void* d_out, int out_size) {
    const float* x    = (const float*)d_in[0];
    const int*   ei   = (const int*)d_in[1];
    const int*   src  = ei;
    const int*   dst  = ei + ED;
    const float* W1   = (const float*)d_in[3];
    const float* as1  = (const float*)d_in[4];
    const float* ad1  = (const float*)d_in[5];
    const float* b1   = (const float*)d_in[6];
    const float* g1   = (const float*)d_in[7];
    const float* be1  = (const float*)d_in[8];
    const float* pw1  = (const float*)d_in[9];
    const float* W2   = (const float*)d_in[10];
    const float* as2  = (const float*)d_in[11];
    const float* ad2  = (const float*)d_in[12];
    const float* b2   = (const float*)d_in[13];
    const float* g2   = (const float*)d_in[14];
    const float* be2  = (const float*)d_in[15];
    const float* pw2  = (const float*)d_in[16];
    const float* Wl   = (const float*)d_in[17];
    const float* bl   = (const float*)d_in[18];
    float* out = (float*)d_out;

    float* fb = nullptr;
    int*   ib = nullptr;
    cudaGetSymbolAddress((void**)&fb, g_f);
    cudaGetSymbolAddress((void**)&ib, g_i);

    float* h1    = fb + O_H1;
    float* out1  = fb + O_OUT1;
    float* asn1  = fb + O_ASN1;
    float* adn1  = fb + O_ADN1;
    float* bns1  = fb + O_BNS1;
    float* sc1   = fb + O_SC1;
    float* sh1   = fb + O_SH1;
    float* w1a   = fb + O_W1A;
    float* score1= fb + O_SCORE1;
    float* tanh1 = fb + O_TANH1;
    float* xp1   = fb + O_XP1;
    float* x1g   = fb + O_X1G;
    float* part  = fb + O_PART;
    float* part2 = fb + O_PART2;
    float* h2    = fb + O_H2;
    float* out2  = fb + O_OUT2;
    float* asn2  = fb + O_ASN2;
    float* adn2  = fb + O_ADN2;
    float* bns2  = fb + O_BNS2;
    float* sc2   = fb + O_SC2;
    float* sh2   = fb + O_SH2;
    float* w2a   = fb + O_W2A;
    float* score2= fb + O_SCORE2;
    float* tanh2 = fb + O_TANH2;
    float* x2g   = fb + O_X2G;
    int* gidx1 = ib + IO_GIDX1;
    int* inv1  = ib + IO_INV1;
    int* gidx2 = ib + IO_GIDX2;
    int* deg1  = ib + IO_DEG1;
    int* csr1  = ib + IO_CSR1;
    int* deg2  = ib + IO_DEG2;
    int* csr2  = ib + IO_CSR2;

    static cudaStream_t s2 = nullptr;
    static cudaEvent_t ev0, ev1, ev2, ev3, ev4, ev5;
    if (!s2) {
        cudaStreamCreateWithFlags(&s2, cudaStreamNonBlocking);
        cudaEventCreateWithFlags(&ev0, cudaEventDisableTiming);
        cudaEventCreateWithFlags(&ev1, cudaEventDisableTiming);
        cudaEventCreateWithFlags(&ev2, cudaEventDisableTiming);
        cudaEventCreateWithFlags(&ev3, cudaEventDisableTiming);
        cudaEventCreateWithFlags(&ev4, cudaEventDisableTiming);
        cudaEventCreateWithFlags(&ev5, cudaEventDisableTiming);
    }

    // fork: side stream does memsets + csr_build1 while main does sgemm1+attn1
    cudaEventRecord(ev0, 0);
    cudaStreamWaitEvent(s2, ev0, 0);
    cudaMemsetAsync(bns1, 0, 512 * sizeof(float), s2);
    cudaMemsetAsync(bns2, 0, 512 * sizeof(float), s2);
    cudaMemsetAsync(deg1, 0, (size_t)NN * sizeof(int), s2);
    cudaMemsetAsync(deg2, 0, (size_t)N2 * sizeof(int), s2);
    cudaMemsetAsync(inv1, 0xFF, (size_t)NN * sizeof(int), s2);
    csr_build<<<(ED + 255) / 256, 256, 0, s2>>>(src, dst, nullptr, deg1, csr1, ED);
    cudaEventRecord(ev1, s2);

    // ---- layer 1 (main stream) ----
    sgemm128<<<dim3(FD / 128, NN / 128), 256>>>(x, W1, h1, NN, FD, INDIM);
    attn_scores<<<NN / 8, 256>>>(h1, as1, ad1, asn1, adn1, NN);
    cudaStreamWaitEvent(0, ev1, 0);
    gat_gather<<<2048, 256>>>(csr1, deg1, asn1, adn1, h1, b1, out1, bns1, NN, (2 * NN) / 2048);
    bn_finalize<<<1, 256>>>(bns1, g1, be1, pw1, sc1, sh1, w1a, 1.0f / NN);
    pool_score<<<NN / 8, 256>>>(out1, w1a, score1, NN);
    topk_sort<<<BT, NPG / 2>>>(score1, NPG, KP1, gidx1, tanh1, inv1);
    cudaEventRecord(ev2, 0);

    // side stream: csr_build2 (needs inv1 only)
    cudaStreamWaitEvent(s2, ev2, 0);
    csr_build<<<(ED + 255) / 256, 256, 0, s2>>>(src, dst, inv1, deg2, csr2, ED);
    cudaEventRecord(ev3, s2);

    pool_gather<<<(N2 * 64 + 255) / 256, 256>>>(out1, sc1, sh1, gidx1, tanh1, xp1, N2);
    cudaEventRecord(ev4, 0);

    // side stream: layer-1 readout (needs xp1)
    cudaStreamWaitEvent(s2, ev4, 0);
    readout_s1<<<dim3(BT, 8), 256, 0, s2>>>(xp1, nullptr, nullptr, nullptr, nullptr, KP1, part);
    readout_s2<<<BT, 256, 0, s2>>>(part, KP1, x1g);
    cudaEventRecord(ev5, s2);

    // ---- layer 2 (main stream) ----
    sgemm128<<<dim3(FD / 128, N2 / 128), 256>>>(xp1, W2, h2, N2, FD, FD);
    attn_scores<<<N2 / 8, 256>>>(h2, as2, ad2, asn2, adn2, N2);
    cudaStreamWaitEvent(0, ev3, 0);
    gat_gather<<<1024, 256>>>(csr2, deg2, asn2, adn2, h2, b2, out2, bns2, N2, (2 * N2) / 1024);
    bn_finalize<<<1, 256>>>(bns2, g2, be2, pw2, sc2, sh2, w2a, 1.0f / N2);
    pool_score<<<N2 / 8, 256>>>(out2, w2a, score2, N2);
    topk_sort<<<BT, KP1 / 2>>>(score2, KP1, KP2, gidx2, tanh2, nullptr);
    readout_s1<<<dim3(BT, 8), 256>>>(out2, sc2, sh2, gidx2, tanh2, KP2, part2);
    readout_s2<<<BT, 256>>>(part2, KP2, x2g);

    // ---- final (join side stream) ----
    cudaStreamWaitEvent(0, ev5, 0);
    final_linear<<<BT, 256>>>(x1g, x2g, Wl, bl, out);
}

// round 6
// speedup vs baseline: 1.4959x; 1.0015x over previous
#include <cuda_runtime.h>
#include <math.h>

// ---------------- problem constants ----------------
constexpr int NN   = 32768;    // total nodes layer1
constexpr int ED   = 262144;   // edges
constexpr int FD   = 256;      // feature dim (4 heads x 64)
constexpr int BT   = 32;       // graphs
constexpr int NPG  = 1024;
constexpr int KP1  = 512;
constexpr int KP2  = 256;
constexpr int N2   = BT * KP1; // 16384 pooled nodes after pool1
constexpr int INDIM = 128;
constexpr int MAXDEG = 64;     // padded CSR width (Poisson(8) max deg << 64)

// ---------------- scratch layout (floats) ----------------
constexpr size_t O_H1    = 0;
constexpr size_t O_OUT1  = O_H1   + (size_t)NN * FD;
constexpr size_t O_ASN1  = O_OUT1 + (size_t)NN * FD;
constexpr size_t O_ADN1  = O_ASN1 + (size_t)NN * 4;
constexpr size_t O_BNS1  = O_ADN1 + (size_t)NN * 4;
constexpr size_t O_SC1   = O_BNS1 + 512;
constexpr size_t O_SH1   = O_SC1  + 256;
constexpr size_t O_W1A   = O_SH1  + 256;   // 256 + 1 (w1 vector, w0 scalar)
constexpr size_t O_SCORE1= O_W1A  + 260;
constexpr size_t O_TANH1 = O_SCORE1 + NN;
constexpr size_t O_XP1   = O_TANH1  + N2;
constexpr size_t O_X1G   = O_XP1    + (size_t)N2 * FD;
constexpr size_t O_PART  = O_X1G    + (size_t)BT * 512;
constexpr size_t O_PART2 = O_PART   + (size_t)BT * 8 * 512;
constexpr size_t O_H2    = O_PART2  + (size_t)BT * 8 * 512;
constexpr size_t O_OUT2  = O_H2     + (size_t)N2 * FD;
constexpr size_t O_ASN2  = O_OUT2   + (size_t)N2 * FD;
constexpr size_t O_ADN2  = O_ASN2   + (size_t)N2 * 4;
constexpr size_t O_BNS2  = O_ADN2   + (size_t)N2 * 4;
constexpr size_t O_SC2   = O_BNS2   + 512;
constexpr size_t O_SH2   = O_SC2    + 256;
constexpr size_t O_W2A   = O_SH2    + 256;
constexpr size_t O_SCORE2= O_W2A    + 260;
constexpr size_t O_TANH2 = O_SCORE2 + N2;
constexpr size_t O_X2G   = O_TANH2  + (size_t)BT * KP2;
constexpr size_t F_TOTAL = O_X2G    + (size_t)BT * 512;

__device__ float g_f[F_TOTAL];

constexpr size_t IO_GIDX1 = 0;
constexpr size_t IO_INV1  = IO_GIDX1 + N2;
constexpr size_t IO_GIDX2 = IO_INV1  + NN;
constexpr size_t IO_DEG1  = IO_GIDX2 + (size_t)BT * KP2;
constexpr size_t IO_CSR1  = IO_DEG1  + NN;
constexpr size_t IO_DEG2  = IO_CSR1  + (size_t)NN * MAXDEG;
constexpr size_t IO_CSR2  = IO_DEG2  + N2;
constexpr size_t I_TOTAL  = IO_CSR2  + (size_t)N2 * MAXDEG;

__device__ int g_i[I_TOTAL];

// ---------------- SGEMM + fused attention-score epilogue ----------------
// C[MxN] = A[MxK] @ B[KxN]; N-tile of 128 covers exactly 2 heads (64 cols each),
// so per-row asn/adn head dots are computed from register acc with no atomics.
__global__ __launch_bounds__(256) void sgemm_attn(const float* __restrict__ A,
                                                  const float* __restrict__ B,
                                                  float* __restrict__ C,
                                                  const float* __restrict__ a_s,
                                                  const float* __restrict__ a_d,
                                                  float* __restrict__ asn,
                                                  float* __restrict__ adn,
                                                  int M, int N, int K) {
    __shared__ float As[8][132];
    __shared__ float Bs[8][132];
    int tid = threadIdx.x;
    int tx = tid & 15, ty = tid >> 4;
    int m0 = blockIdx.y * 128, n0 = blockIdx.x * 128;
    int arow = tid >> 1, ac4 = (tid & 1) * 4;
    int brow = tid >> 5, bc4 = (tid & 31) * 4;
    float acc[8][8];
#pragma unroll
    for (int i = 0; i < 8; i++)
#pragma unroll
        for (int j = 0; j < 8; j++) acc[i][j] = 0.f;

    const float* Aptr = A + (size_t)(m0 + arow) * K + ac4;
    const float* Bptr = B + (size_t)brow * N + n0 + bc4;

    float4 pa4 = *(const float4*)(Aptr);
    float4 pb4 = *(const float4*)(Bptr);

    for (int k0 = 0; k0 < K; k0 += 8) {
        As[ac4 + 0][arow] = pa4.x; As[ac4 + 1][arow] = pa4.y;
        As[ac4 + 2][arow] = pa4.z; As[ac4 + 3][arow] = pa4.w;
        *(float4*)&Bs[brow][bc4] = pb4;
        __syncthreads();
        if (k0 + 8 < K) {
            pa4 = *(const float4*)(Aptr + k0 + 8);
            pb4 = *(const float4*)(Bptr + (size_t)(k0 + 8) * N);
        }
#pragma unroll
        for (int kk = 0; kk < 8; kk++) {
            float4 a0 = *(float4*)&As[kk][ty * 8], a1 = *(float4*)&As[kk][ty * 8 + 4];
            float4 b0 = *(float4*)&Bs[kk][tx * 8], b1 = *(float4*)&Bs[kk][tx * 8 + 4];
            float av[8] = {a0.x, a0.y, a0.z, a0.w, a1.x, a1.y, a1.z, a1.w};
            float bv[8] = {b0.x, b0.y, b0.z, b0.w, b1.x, b1.y, b1.z, b1.w};
#pragma unroll
            for (int i = 0; i < 8; i++)
#pragma unroll
                for (int j = 0; j < 8; j++) acc[i][j] += av[i] * bv[j];
        }
        __syncthreads();
    }
#pragma unroll
    for (int i = 0; i < 8; i++) {
        float* c = C + (size_t)(m0 + ty * 8 + i) * N + n0 + tx * 8;
        *(float4*)c = make_float4(acc[i][0], acc[i][1], acc[i][2], acc[i][3]);
        *(float4*)(c + 4) = make_float4(acc[i][4], acc[i][5], acc[i][6], acc[i][7]);
    }

    // ---- attention epilogue: head = n0/64 + tx/8, cols (tx&7)*8..+7 within head ----
    int head = (n0 >> 6) + (tx >> 3);
    float asw[8], adw[8];
#pragma unroll
    for (int j = 0; j < 8; j++) {
        asw[j] = a_s[head * 64 + (tx & 7) * 8 + j];
        adw[j] = a_d[head * 64 + (tx & 7) * 8 + j];
    }
#pragma unroll
    for (int i = 0; i < 8; i++) {
        float pa = 0.f, pd = 0.f;
#pragma unroll
        for (int j = 0; j < 8; j++) { pa += acc[i][j] * asw[j]; pd += acc[i][j] * adw[j]; }
#pragma unroll
        for (int o = 4; o; o >>= 1) {
            pa += __shfl_down_sync(~0u, pa, o, 8);
            pd += __shfl_down_sync(~0u, pd, o, 8);
        }
        if ((tid & 7) == 0) {
            int rowg = m0 + ty * 8 + i;
            asn[rowg * 4 + head] = pa;
            adn[rowg * 4 + head] = pd;
        }
    }
}

// ---------------- padded-CSR build ----------------
__global__ void csr_build(const int* __restrict__ src, const int* __restrict__ dst,
                          const int* __restrict__ inv, int* __restrict__ deg,
                          int* __restrict__ csr, int nE) {
    int i = blockIdx.x * blockDim.x + threadIdx.x;
    if (i >= nE) return;
    int s = src[i], d = dst[i];
    if (inv) { s = inv[s]; d = inv[d]; if (s < 0 || d < 0) return; }
    int p = atomicAdd(&deg[d], 1);
    if (p < MAXDEG) csr[(size_t)d * MAXDEG + p] = s;
}

// ---------------- fused GAT gather: warp = (node, 128-feature half) ----------------
__global__ __launch_bounds__(256, 6) void gat_gather(
    const int* __restrict__ csr, const int* __restrict__ deg,
    const float* __restrict__ asn, const float* __restrict__ adn,
    const float* __restrict__ h, const float* __restrict__ bias,
    float* __restrict__ out, float* __restrict__ sums, int n, int upb) {
    __shared__ float ssum[512];
    __shared__ float4 sst[8][64];   // per-warp: (src*FD as int-bits, alpha0, alpha1, -)
    int t = threadIdx.x;
    ssum[t] = 0.f; ssum[t + 256] = 0.f;
    __syncthreads();
    int lane = t & 31, w = t >> 5;
    int half = (blockIdx.x * upb + w) & 1;   // invariant across iterations (upb even)
    int c = half * 128 + lane * 4;           // this lane's 4 features
    float4 bb = *(const float4*)&bias[c];
    float st[8];
#pragma unroll
    for (int i = 0; i < 8; i++) st[i] = 0.f;

    int base = blockIdx.x * upb;
    int end = base + upb; if (end > 2 * n) end = 2 * n;
    for (int u = base + w; u < end; u += 8) {
        int nd = u >> 1;
        float2 ad = *(const float2*)&adn[(size_t)nd * 4 + half * 2];
        int dg = deg[nd]; if (dg > 63) dg = 63;   // slot dg = self loop
        const int* row = csr + (size_t)nd * MAXDEG;
        // --- phase 1: per-lane slot -> parallel asn loads + exp (2 heads) ---
        int sA = (lane < dg) ? row[lane] : nd;
        int sB = (lane + 32 < dg) ? row[lane + 32] : nd;
        bool vA = (lane <= dg);
        bool vB = (lane + 32 <= dg);
        float2 aA = *(const float2*)&asn[(size_t)sA * 4 + half * 2];
        float2 aB = *(const float2*)&asn[(size_t)sB * 4 + half * 2];
        float lA0 = aA.x + ad.x, lA1 = aA.y + ad.y;
        float lB0 = aB.x + ad.x, lB1 = aB.y + ad.y;
        lA0 = lA0 > 0.f ? lA0 : 0.2f * lA0;  lB0 = lB0 > 0.f ? lB0 : 0.2f * lB0;
        lA1 = lA1 > 0.f ? lA1 : 0.2f * lA1;  lB1 = lB1 > 0.f ? lB1 : 0.2f * lB1;
        float pA0 = vA ? __expf(lA0) : 0.f, pA1 = vA ? __expf(lA1) : 0.f;
        float pB0 = vB ? __expf(lB0) : 0.f, pB1 = vB ? __expf(lB1) : 0.f;
        float d0 = pA0 + pB0, d1 = pA1 + pB1;
#pragma unroll
        for (int o = 16; o; o >>= 1) {
            d0 += __shfl_xor_sync(~0u, d0, o);
            d1 += __shfl_xor_sync(~0u, d1, o);
        }
        float r0 = 1.f / d0, r1 = 1.f / d1;
        __syncwarp();
        sst[w][lane]      = make_float4(__int_as_float(sA * FD), pA0 * r0, pA1 * r1, 0.f);
        sst[w][lane + 32] = make_float4(__int_as_float(sB * FD), pB0 * r0, pB1 * r1, 0.f);
        __syncwarp();
        // --- phase 2: pipelined feature gather (1 LDS.128 + 1 LDG.128 per edge) ---
        float4 a0 = make_float4(0, 0, 0, 0);
        int ne = dg + 1;
#pragma unroll 4
        for (int e = 0; e < ne; e++) {
            float4 gq = sst[w][e];
            int sofs = __float_as_int(gq.x);
            float p = (lane & 16) ? gq.z : gq.y;
            float4 v = *(const float4*)(h + sofs + c);
            a0.x += p * v.x; a0.y += p * v.y; a0.z += p * v.z; a0.w += p * v.w;
        }
        float o[4];
        o[0] = a0.x + bb.x; o[1] = a0.y + bb.y;
        o[2] = a0.z + bb.z; o[3] = a0.w + bb.w;
#pragma unroll
        for (int i = 0; i < 4; i++) {
            float v = o[i];
            v = 0.5f * v * (1.0f + erff(v * 0.70710678118654752f));
            o[i] = v;
            st[i] += v; st[4 + i] += v * v;
        }
        *(float4*)(out + (size_t)nd * FD + c) = make_float4(o[0], o[1], o[2], o[3]);
    }
#pragma unroll
    for (int i = 0; i < 4; i++) {
        atomicAdd(&ssum[c + i],       st[i]);
        atomicAdd(&ssum[256 + c + i], st[4 + i]);
    }
    __syncthreads();
    atomicAdd(&sums[t],       ssum[t]);
    atomicAdd(&sums[t + 256], ssum[t + 256]);
}

// ---------------- BN finalize: scale/shift + fused score weights ----------------
__global__ void bn_finalize(const float* __restrict__ sums, const float* __restrict__ g,
                            const float* __restrict__ be, const float* __restrict__ pw,
                            float* __restrict__ scale, float* __restrict__ shift,
                            float* __restrict__ w1a, float invn) {
    __shared__ float red[256];
    __shared__ float sc_s[256], sh_s[256];
    int f = threadIdx.x;
    float mean = sums[f] * invn;
    float var = sums[256 + f] * invn - mean * mean;
    float sc = g[f] * rsqrtf(var + 1e-5f);
    float sh = be[f] - mean * sc;
    scale[f] = sc; shift[f] = sh;
    sc_s[f] = sc; sh_s[f] = sh;
    float w = pw[f];
    red[f] = w * w;
    __syncthreads();
    for (int st = 128; st; st >>= 1) {
        if (f < st) red[f] += red[f + st];
        __syncthreads();
    }
    float pwn = w * rsqrtf(red[0]);
    w1a[f] = sc_s[f] * pwn;        // score weight on raw x
    __syncthreads();
    red[f] = sh_s[f] * pwn;        // score constant offset terms
    __syncthreads();
    for (int st = 128; st; st >>= 1) {
        if (f < st) red[f] += red[f + st];
        __syncthreads();
    }
    if (f == 0) w1a[256] = red[0];
}

// ---------------- pool score: dot(x, w1) + w0 (warp per node, no writeback) ----------------
__global__ void pool_score(const float* __restrict__ x, const float* __restrict__ w1a,
                           float* __restrict__ score, int n) {
    int gw = (blockIdx.x * blockDim.x + threadIdx.x) >> 5;
    int lane = threadIdx.x & 31;
    if (gw >= n) return;
    const float* row = x + (size_t)gw * FD;
    int c0 = lane * 4, c1 = c0 + 128;
    float4 v0 = *(const float4*)(row + c0), v1 = *(const float4*)(row + c1);
    float4 p0 = *(const float4*)&w1a[c0], p1 = *(const float4*)&w1a[c1];
    float s = v0.x * p0.x + v0.y * p0.y + v0.z * p0.z + v0.w * p0.w
            + v1.x * p1.x + v1.y * p1.y + v1.z * p1.z + v1.w * p1.w;
#pragma unroll
    for (int o = 16; o; o >>= 1) s += __shfl_down_sync(~0u, s, o);
    if (lane == 0) score[gw] = s + w1a[256];
}

// ---------------- per-graph top-k via bitonic sort (block per graph) ----------------
__global__ void topk_sort(const float* __restrict__ score, int npg, int k,
                          int* __restrict__ gidx, float* __restrict__ tv,
                          int* __restrict__ inv) {
    __shared__ float sv[1024];
    __shared__ int si[1024];
    int g = blockIdx.x, t = threadIdx.x, nt = blockDim.x;
    for (int e = t; e < npg; e += nt) { sv[e] = score[(size_t)g * npg + e]; si[e] = e; }
    __syncthreads();
    for (int kk = 2; kk <= npg; kk <<= 1) {
        for (int j = kk >> 1; j > 0; j >>= 1) {
            for (int e = t; e < npg; e += nt) {
                int p = e ^ j;
                if (p > e) {
                    bool desc = ((e & kk) == 0);
                    float ve = sv[e], vp = sv[p];
                    if (desc ? (ve < vp) : (ve > vp)) {
                        sv[e] = vp; sv[p] = ve;
                        int tmp = si[e]; si[e] = si[p]; si[p] = tmp;
                    }
                }
            }
            __syncthreads();
        }
    }
    for (int e = t; e < k; e += nt) {
        int pos = g * k + e;
        int node = g * npg + si[e];
        gidx[pos] = node;
        tv[pos] = tanhf(sv[e]);
        if (inv) inv[node] = pos;
    }
}

// ---------------- gather pooled rows, BN applied inline, scaled by tanh ----------------
__global__ void pool_gather(const float* __restrict__ x, const float* __restrict__ sc,
                            const float* __restrict__ sh, const int* __restrict__ gidx,
                            const float* __restrict__ tv, float* __restrict__ xp, int n2) {
    int i = blockIdx.x * blockDim.x + threadIdx.x;
    if (i >= n2 * 64) return;
    int row = i >> 6, c4 = (i & 63) * 4;
    float t = tv[row];
    int node = gidx[row];
    float4 v = *(const float4*)&x[(size_t)node * FD + c4];
    float4 s = *(const float4*)&sc[c4];
    float4 h = *(const float4*)&sh[c4];
    v.x = (v.x * s.x + h.x) * t; v.y = (v.y * s.y + h.y) * t;
    v.z = (v.z * s.z + h.z) * t; v.w = (v.w * s.w + h.w) * t;
    *(float4*)&xp[(size_t)row * FD + c4] = v;
}

// ---------------- readout stage 1: per (graph, chunk) partial max/sum ----------------
__global__ void readout_s1(const float* __restrict__ x, const float* __restrict__ sc,
                           const float* __restrict__ sh, const int* __restrict__ gidx,
                           const float* __restrict__ tv, int k, float* __restrict__ partial) {
    int g = blockIdx.x, c = blockIdx.y, f = threadIdx.x;
    int chunk = k / 8;
    int j0 = c * chunk;
    float mx = -1e30f, sm = 0.f;
    if (gidx) {
        float scf = sc[f], shf = sh[f];
        for (int j = j0; j < j0 + chunk; j++) {
            int node = gidx[g * k + j];
            float v = (x[(size_t)node * FD + f] * scf + shf) * tv[g * k + j];
            mx = fmaxf(mx, v);
            sm += v;
        }
    } else {
        for (int j = j0; j < j0 + chunk; j++) {
            float v = x[((size_t)g * k + j) * FD + f];
            mx = fmaxf(mx, v);
            sm += v;
        }
    }
    partial[((size_t)(g * 8 + c)) * 512 + f] = mx;
    partial[((size_t)(g * 8 + c)) * 512 + 256 + f] = sm;
}

// ---------------- readout stage 2 ----------------
__global__ void readout_s2(const float* __restrict__ partial, int k, float* __restrict__ xg) {
    int g = blockIdx.x, f = threadIdx.x;
    float mx = -1e30f, sm = 0.f;
    for (int c = 0; c < 8; c++) {
        mx = fmaxf(mx, partial[((size_t)(g * 8 + c)) * 512 + f]);
        sm += partial[((size_t)(g * 8 + c)) * 512 + 256 + f];
    }
    xg[(size_t)g * 512 + f] = mx;
    xg[(size_t)g * 512 + 256 + f] = sm / (float)k;
}

// ---------------- final linear: out = (x1+x2) @ Wl^T + bl ----------------
__global__ void final_linear(const float* __restrict__ x1g, const float* __restrict__ x2g,
                             const float* __restrict__ Wl, const float* __restrict__ bl,
                             float* __restrict__ out) {
    __shared__ float xr[512];
    int b = blockIdx.x, t = threadIdx.x;
    xr[t] = x1g[(size_t)b * 512 + t] + x2g[(size_t)b * 512 + t];
    xr[t + 256] = x1g[(size_t)b * 512 + 256 + t] + x2g[(size_t)b * 512 + 256 + t];
    __syncthreads();
    float acc = bl[t];
    const float* w = Wl + (size_t)t * 512;
    for (int kk = 0; kk < 512; kk++) acc += xr[kk] * w[kk];
    out[(size_t)b * 256 + t] = acc;
}

// ---------------- host launcher ----------------
extern "C" void kernel_launch(void* const* d_in, const int* in_sizes, int n_in,
                              void* d_out, int out_size) {
    const float* x    = (const float*)d_in[0];
    const int*   ei   = (const int*)d_in[1];
    const int*   src  = ei;
    const int*   dst  = ei + ED;
    const float* W1   = (const float*)d_in[3];
    const float* as1  = (const float*)d_in[4];
    const float* ad1  = (const float*)d_in[5];
    const float* b1   = (const float*)d_in[6];
    const float* g1   = (const float*)d_in[7];
    const float* be1  = (const float*)d_in[8];
    const float* pw1  = (const float*)d_in[9];
    const float* W2   = (const float*)d_in[10];
    const float* as2  = (const float*)d_in[11];
    const float* ad2  = (const float*)d_in[12];
    const float* b2   = (const float*)d_in[13];
    const float* g2   = (const float*)d_in[14];
    const float* be2  = (const float*)d_in[15];
    const float* pw2  = (const float*)d_in[16];
    const float* Wl   = (const float*)d_in[17];
    const float* bl   = (const float*)d_in[18];
    float* out = (float*)d_out;

    float* fb = nullptr;
    int*   ib = nullptr;
    cudaGetSymbolAddress((void**)&fb, g_f);
    cudaGetSymbolAddress((void**)&ib, g_i);

    float* h1    = fb + O_H1;
    float* out1  = fb + O_OUT1;
    float* asn1  = fb + O_ASN1;
    float* adn1  = fb + O_ADN1;
    float* bns1  = fb + O_BNS1;
    float* sc1   = fb + O_SC1;
    float* sh1   = fb + O_SH1;
    float* w1a   = fb + O_W1A;
    float* score1= fb + O_SCORE1;
    float* tanh1 = fb + O_TANH1;
    float* xp1   = fb + O_XP1;
    float* x1g   = fb + O_X1G;
    float* part  = fb + O_PART;
    float* part2 = fb + O_PART2;
    float* h2    = fb + O_H2;
    float* out2  = fb + O_OUT2;
    float* asn2  = fb + O_ASN2;
    float* adn2  = fb + O_ADN2;
    float* bns2  = fb + O_BNS2;
    float* sc2   = fb + O_SC2;
    float* sh2   = fb + O_SH2;
    float* w2a   = fb + O_W2A;
    float* score2= fb + O_SCORE2;
    float* tanh2 = fb + O_TANH2;
    float* x2g   = fb + O_X2G;
    int* gidx1 = ib + IO_GIDX1;
    int* inv1  = ib + IO_INV1;
    int* gidx2 = ib + IO_GIDX2;
    int* deg1  = ib + IO_DEG1;
    int* csr1  = ib + IO_CSR1;
    int* deg2  = ib + IO_DEG2;
    int* csr2  = ib + IO_CSR2;

    static cudaStream_t s2 = nullptr;
    static cudaEvent_t ev0, ev1, ev2, ev3, ev4, ev5;
    if (!s2) {
        cudaStreamCreateWithFlags(&s2, cudaStreamNonBlocking);
        cudaEventCreateWithFlags(&ev0, cudaEventDisableTiming);
        cudaEventCreateWithFlags(&ev1, cudaEventDisableTiming);
        cudaEventCreateWithFlags(&ev2, cudaEventDisableTiming);
        cudaEventCreateWithFlags(&ev3, cudaEventDisableTiming);
        cudaEventCreateWithFlags(&ev4, cudaEventDisableTiming);
        cudaEventCreateWithFlags(&ev5, cudaEventDisableTiming);
    }

    // fork: side stream does memsets + csr_build1 while main does sgemm1
    cudaEventRecord(ev0, 0);
    cudaStreamWaitEvent(s2, ev0, 0);
    cudaMemsetAsync(bns1, 0, 512 * sizeof(float), s2);
    cudaMemsetAsync(bns2, 0, 512 * sizeof(float), s2);
    cudaMemsetAsync(deg1, 0, (size_t)NN * sizeof(int), s2);
    cudaMemsetAsync(deg2, 0, (size_t)N2 * sizeof(int), s2);
    cudaMemsetAsync(inv1, 0xFF, (size_t)NN * sizeof(int), s2);
    csr_build<<<(ED + 255) / 256, 256, 0, s2>>>(src, dst, nullptr, deg1, csr1, ED);
    cudaEventRecord(ev1, s2);

    // ---- layer 1 (main stream) ----
    sgemm_attn<<<dim3(FD / 128, NN / 128), 256>>>(x, W1, h1, as1, ad1, asn1, adn1, NN, FD, INDIM);
    cudaStreamWaitEvent(0, ev1, 0);
    gat_gather<<<2048, 256>>>(csr1, deg1, asn1, adn1, h1, b1, out1, bns1, NN, (2 * NN) / 2048);
    bn_finalize<<<1, 256>>>(bns1, g1, be1, pw1, sc1, sh1, w1a, 1.0f / NN);
    pool_score<<<NN / 8, 256>>>(out1, w1a, score1, NN);
    topk_sort<<<BT, NPG / 2>>>(score1, NPG, KP1, gidx1, tanh1, inv1);
    cudaEventRecord(ev2, 0);

    // side stream: csr_build2 (needs inv1 only)
    cudaStreamWaitEvent(s2, ev2, 0);
    csr_build<<<(ED + 255) / 256, 256, 0, s2>>>(src, dst, inv1, deg2, csr2, ED);
    cudaEventRecord(ev3, s2);

    pool_gather<<<(N2 * 64 + 255) / 256, 256>>>(out1, sc1, sh1, gidx1, tanh1, xp1, N2);
    cudaEventRecord(ev4, 0);

    // side stream: layer-1 readout (needs xp1)
    cudaStreamWaitEvent(s2, ev4, 0);
    readout_s1<<<dim3(BT, 8), 256, 0, s2>>>(xp1, nullptr, nullptr, nullptr, nullptr, KP1, part);
    readout_s2<<<BT, 256, 0, s2>>>(part, KP1, x1g);
    cudaEventRecord(ev5, s2);

    // ---- layer 2 (main stream) ----
    sgemm_attn<<<dim3(FD / 128, N2 / 128), 256>>>(xp1, W2, h2, as2, ad2, asn2, adn2, N2, FD, FD);
    cudaStreamWaitEvent(0, ev3, 0);
    gat_gather<<<1024, 256>>>(csr2, deg2, asn2, adn2, h2, b2, out2, bns2, N2, (2 * N2) / 1024);
    bn_finalize<<<1, 256>>>(bns2, g2, be2, pw2, sc2, sh2, w2a, 1.0f / N2);
    pool_score<<<N2 / 8, 256>>>(out2, w2a, score2, N2);
    topk_sort<<<BT, KP1 / 2>>>(score2, KP1, KP2, gidx2, tanh2, nullptr);
    readout_s1<<<dim3(BT, 8), 256>>>(out2, sc2, sh2, gidx2, tanh2, KP2, part2);
    readout_s2<<<BT, 256>>>(part2, KP2, x2g);

    // ---- final (join side stream) ----
    cudaStreamWaitEvent(0, ev5, 0);
    final_linear<<<BT, 256>>>(x1g, x2g, Wl, bl, out);
}

// round 7
// speedup vs baseline: 1.5027x; 1.0045x over previous
#include <cuda_runtime.h>
#include <math.h>

// ---------------- problem constants ----------------
constexpr int NN   = 32768;    // total nodes layer1
constexpr int ED   = 262144;   // edges
constexpr int FD   = 256;      // feature dim (4 heads x 64)
constexpr int BT   = 32;       // graphs
constexpr int NPG  = 1024;
constexpr int KP1  = 512;
constexpr int KP2  = 256;
constexpr int N2   = BT * KP1; // 16384 pooled nodes after pool1
constexpr int INDIM = 128;
constexpr int MAXDEG = 64;     // padded CSR width

// ---------------- scratch layout (floats) ----------------
constexpr size_t O_H1    = 0;
constexpr size_t O_OUT1  = O_H1   + (size_t)NN * FD;
constexpr size_t O_ASN1  = O_OUT1 + (size_t)NN * FD;
constexpr size_t O_ADN1  = O_ASN1 + (size_t)NN * 4;
constexpr size_t O_BNS1  = O_ADN1 + (size_t)NN * 4;   // 512
constexpr size_t O_BNS2  = O_BNS1 + 512;              // 512 (adjacent -> one memset)
constexpr size_t O_SC1   = O_BNS2 + 512;
constexpr size_t O_SH1   = O_SC1  + 256;
constexpr size_t O_W1A   = O_SH1  + 256;   // 256 + 1
constexpr size_t O_SCORE1= O_W1A  + 260;
constexpr size_t O_TANH1 = O_SCORE1 + NN;
constexpr size_t O_XP1   = O_TANH1  + N2;
constexpr size_t O_PART  = O_XP1    + (size_t)N2 * FD;
constexpr size_t O_PART2 = O_PART   + (size_t)BT * 8 * 512;
constexpr size_t O_H2    = O_PART2  + (size_t)BT * 8 * 512;
constexpr size_t O_OUT2  = O_H2     + (size_t)N2 * FD;
constexpr size_t O_ASN2  = O_OUT2   + (size_t)N2 * FD;
constexpr size_t O_ADN2  = O_ASN2   + (size_t)N2 * 4;
constexpr size_t O_SC2   = O_ADN2   + (size_t)N2 * 4;
constexpr size_t O_SH2   = O_SC2    + 256;
constexpr size_t O_W2A   = O_SH2    + 256;
constexpr size_t O_SCORE2= O_W2A    + 260;
constexpr size_t O_TANH2 = O_SCORE2 + N2;
constexpr size_t F_TOTAL = O_TANH2  + (size_t)BT * KP2;

__device__ float g_f[F_TOTAL];

constexpr size_t IO_GIDX1 = 0;
constexpr size_t IO_INV1  = IO_GIDX1 + N2;
constexpr size_t IO_GIDX2 = IO_INV1  + NN;
constexpr size_t IO_CSR1  = IO_GIDX2 + (size_t)BT * KP2;
constexpr size_t IO_CSR2  = IO_CSR1  + (size_t)NN * MAXDEG;
constexpr size_t IO_DEG1  = IO_CSR2  + (size_t)N2 * MAXDEG;  // deg1|deg2|cnt adjacent
constexpr size_t IO_DEG2  = IO_DEG1  + NN;
constexpr size_t IO_CNT   = IO_DEG2  + N2;
constexpr size_t I_TOTAL  = IO_CNT   + 8;

__device__ int g_i[I_TOTAL];

// ---------------- SGEMM + fused attention-score epilogue ----------------
__global__ __launch_bounds__(256) void sgemm_attn(const float* __restrict__ A,
                                                  const float* __restrict__ B,
                                                  float* __restrict__ C,
                                                  const float* __restrict__ a_s,
                                                  const float* __restrict__ a_d,
                                                  float* __restrict__ asn,
                                                  float* __restrict__ adn,
                                                  int M, int N, int K) {
    __shared__ float As[8][132];
    __shared__ float Bs[8][132];
    int tid = threadIdx.x;
    int tx = tid & 15, ty = tid >> 4;
    int m0 = blockIdx.y * 128, n0 = blockIdx.x * 128;
    int arow = tid >> 1, ac4 = (tid & 1) * 4;
    int brow = tid >> 5, bc4 = (tid & 31) * 4;
    float acc[8][8];
#pragma unroll
    for (int i = 0; i < 8; i++)
#pragma unroll
        for (int j = 0; j < 8; j++) acc[i][j] = 0.f;

    const float* Aptr = A + (size_t)(m0 + arow) * K + ac4;
    const float* Bptr = B + (size_t)brow * N + n0 + bc4;

    float4 pa4 = *(const float4*)(Aptr);
    float4 pb4 = *(const float4*)(Bptr);

    for (int k0 = 0; k0 < K; k0 += 8) {
        As[ac4 + 0][arow] = pa4.x; As[ac4 + 1][arow] = pa4.y;
        As[ac4 + 2][arow] = pa4.z; As[ac4 + 3][arow] = pa4.w;
        *(float4*)&Bs[brow][bc4] = pb4;
        __syncthreads();
        if (k0 + 8 < K) {
            pa4 = *(const float4*)(Aptr + k0 + 8);
            pb4 = *(const float4*)(Bptr + (size_t)(k0 + 8) * N);
        }
#pragma unroll
        for (int kk = 0; kk < 8; kk++) {
            float4 a0 = *(float4*)&As[kk][ty * 8], a1 = *(float4*)&As[kk][ty * 8 + 4];
            float4 b0 = *(float4*)&Bs[kk][tx * 8], b1 = *(float4*)&Bs[kk][tx * 8 + 4];
            float av[8] = {a0.x, a0.y, a0.z, a0.w, a1.x, a1.y, a1.z, a1.w};
            float bv[8] = {b0.x, b0.y, b0.z, b0.w, b1.x, b1.y, b1.z, b1.w};
#pragma unroll
            for (int i = 0; i < 8; i++)
#pragma unroll
                for (int j = 0; j < 8; j++) acc[i][j] += av[i] * bv[j];
        }
        __syncthreads();
    }
#pragma unroll
    for (int i = 0; i < 8; i++) {
        float* c = C + (size_t)(m0 + ty * 8 + i) * N + n0 + tx * 8;
        *(float4*)c = make_float4(acc[i][0], acc[i][1], acc[i][2], acc[i][3]);
        *(float4*)(c + 4) = make_float4(acc[i][4], acc[i][5], acc[i][6], acc[i][7]);
    }

    // ---- attention epilogue ----
    int head = (n0 >> 6) + (tx >> 3);
    float asw[8], adw[8];
#pragma unroll
    for (int j = 0; j < 8; j++) {
        asw[j] = a_s[head * 64 + (tx & 7) * 8 + j];
        adw[j] = a_d[head * 64 + (tx & 7) * 8 + j];
    }
#pragma unroll
    for (int i = 0; i < 8; i++) {
        float pa = 0.f, pd = 0.f;
#pragma unroll
        for (int j = 0; j < 8; j++) { pa += acc[i][j] * asw[j]; pd += acc[i][j] * adw[j]; }
#pragma unroll
        for (int o = 4; o; o >>= 1) {
            pa += __shfl_down_sync(~0u, pa, o, 8);
            pd += __shfl_down_sync(~0u, pd, o, 8);
        }
        if ((tid & 7) == 0) {
            int rowg = m0 + ty * 8 + i;
            asn[rowg * 4 + head] = pa;
            adn[rowg * 4 + head] = pd;
        }
    }
}

// ---------------- padded-CSR build ----------------
__global__ void csr_build(const int* __restrict__ src, const int* __restrict__ dst,
                          const int* __restrict__ inv, int* __restrict__ deg,
                          int* __restrict__ csr, int nE) {
    int i = blockIdx.x * blockDim.x + threadIdx.x;
    if (i >= nE) return;
    int s = src[i], d = dst[i];
    if (inv) { s = inv[s]; d = inv[d]; if (s < 0 || d < 0) return; }
    int p = atomicAdd(&deg[d], 1);
    if (p < MAXDEG) csr[(size_t)d * MAXDEG + p] = s;
}

// ---------------- fused GAT gather + BN-finalize tail (last-block pattern) ----------------
__global__ __launch_bounds__(256, 6) void gat_gather(
    const int* __restrict__ csr, const int* __restrict__ deg,
    const float* __restrict__ asn, const float* __restrict__ adn,
    const float* __restrict__ h, const float* __restrict__ bias,
    float* __restrict__ out, float* __restrict__ sums, int n, int upb,
    const float* __restrict__ gw, const float* __restrict__ be,
    const float* __restrict__ pw, float* __restrict__ scale,
    float* __restrict__ shift, float* __restrict__ w1a, float invn,
    int* __restrict__ counter) {
    __shared__ float ssum[512];
    __shared__ float4 sst[8][64];   // per-warp: (src*FD bits, alpha0, alpha1, -)
    __shared__ int lastFlag;
    int t = threadIdx.x;
    ssum[t] = 0.f; ssum[t + 256] = 0.f;
    __syncthreads();
    int lane = t & 31, w = t >> 5;
    int half = (blockIdx.x * upb + w) & 1;   // invariant (upb even)
    int c = half * 128 + lane * 4;
    float4 bb = *(const float4*)&bias[c];
    float st[8];
#pragma unroll
    for (int i = 0; i < 8; i++) st[i] = 0.f;

    int base = blockIdx.x * upb;
    int end = base + upb; if (end > 2 * n) end = 2 * n;
    for (int u = base + w; u < end; u += 8) {
        int nd = u >> 1;
        float2 ad = *(const float2*)&adn[(size_t)nd * 4 + half * 2];
        int dg = deg[nd]; if (dg > 63) dg = 63;
        const int* row = csr + (size_t)nd * MAXDEG;
        int sA = (lane < dg) ? row[lane] : nd;
        int sB = (lane + 32 < dg) ? row[lane + 32] : nd;
        bool vA = (lane <= dg);
        bool vB = (lane + 32 <= dg);
        float2 aA = *(const float2*)&asn[(size_t)sA * 4 + half * 2];
        float2 aB = *(const float2*)&asn[(size_t)sB * 4 + half * 2];
        float lA0 = aA.x + ad.x, lA1 = aA.y + ad.y;
        float lB0 = aB.x + ad.x, lB1 = aB.y + ad.y;
        lA0 = lA0 > 0.f ? lA0 : 0.2f * lA0;  lB0 = lB0 > 0.f ? lB0 : 0.2f * lB0;
        lA1 = lA1 > 0.f ? lA1 : 0.2f * lA1;  lB1 = lB1 > 0.f ? lB1 : 0.2f * lB1;
        float pA0 = vA ? __expf(lA0) : 0.f, pA1 = vA ? __expf(lA1) : 0.f;
        float pB0 = vB ? __expf(lB0) : 0.f, pB1 = vB ? __expf(lB1) : 0.f;
        float d0 = pA0 + pB0, d1 = pA1 + pB1;
#pragma unroll
        for (int o = 16; o; o >>= 1) {
            d0 += __shfl_xor_sync(~0u, d0, o);
            d1 += __shfl_xor_sync(~0u, d1, o);
        }
        float r0 = 1.f / d0, r1 = 1.f / d1;
        __syncwarp();
        sst[w][lane]      = make_float4(__int_as_float(sA * FD), pA0 * r0, pA1 * r1, 0.f);
        sst[w][lane + 32] = make_float4(__int_as_float(sB * FD), pB0 * r0, pB1 * r1, 0.f);
        __syncwarp();
        float4 a0 = make_float4(0, 0, 0, 0);
        int ne = dg + 1;
#pragma unroll 4
        for (int e = 0; e < ne; e++) {
            float4 gq = sst[w][e];
            int sofs = __float_as_int(gq.x);
            float p = (lane & 16) ? gq.z : gq.y;
            float4 v = *(const float4*)(h + sofs + c);
            a0.x += p * v.x; a0.y += p * v.y; a0.z += p * v.z; a0.w += p * v.w;
        }
        float o[4];
        o[0] = a0.x + bb.x; o[1] = a0.y + bb.y;
        o[2] = a0.z + bb.z; o[3] = a0.w + bb.w;
#pragma unroll
        for (int i = 0; i < 4; i++) {
            float v = o[i];
            v = 0.5f * v * (1.0f + erff(v * 0.70710678118654752f));
            o[i] = v;
            st[i] += v; st[4 + i] += v * v;
        }
        *(float4*)(out + (size_t)nd * FD + c) = make_float4(o[0], o[1], o[2], o[3]);
    }
#pragma unroll
    for (int i = 0; i < 4; i++) {
        atomicAdd(&ssum[c + i],       st[i]);
        atomicAdd(&ssum[256 + c + i], st[4 + i]);
    }
    __syncthreads();
    atomicAdd(&sums[t],       ssum[t]);
    atomicAdd(&sums[t + 256], ssum[t + 256]);
    __threadfence();
    __syncthreads();
    if (t == 0) lastFlag = (atomicAdd(counter, 1) == (int)gridDim.x - 1) ? 1 : 0;
    __syncthreads();
    if (!lastFlag) return;

    // ---- BN finalize (one block; sums complete & L2-coherent) ----
    float* red = ssum;                 // reuse smem
    float* scs = (float*)sst;          // 256
    float* shs = scs + 256;            // 256
    int f = t;
    float mean = __ldcg(&sums[f]) * invn;
    float var  = __ldcg(&sums[256 + f]) * invn - mean * mean;
    float sc = gw[f] * rsqrtf(var + 1e-5f);
    float sh = be[f] - mean * sc;
    scale[f] = sc; shift[f] = sh;
    scs[f] = sc; shs[f] = sh;
    float pwf = pw[f];
    red[f] = pwf * pwf;
    __syncthreads();
    for (int s = 128; s; s >>= 1) {
        if (f < s) red[f] += red[f + s];
        __syncthreads();
    }
    float pwn = pwf * rsqrtf(red[0]);
    w1a[f] = scs[f] * pwn;
    __syncthreads();
    red[f] = shs[f] * pwn;
    __syncthreads();
    for (int s = 128; s; s >>= 1) {
        if (f < s) red[f] += red[f + s];
        __syncthreads();
    }
    if (f == 0) w1a[256] = red[0];
}

// ---------------- pool score: dot(x, w1) + w0 ----------------
__global__ void pool_score(const float* __restrict__ x, const float* __restrict__ w1a,
                           float* __restrict__ score, int n) {
    int gw = (blockIdx.x * blockDim.x + threadIdx.x) >> 5;
    int lane = threadIdx.x & 31;
    if (gw >= n) return;
    const float* row = x + (size_t)gw * FD;
    int c0 = lane * 4, c1 = c0 + 128;
    float4 v0 = *(const float4*)(row + c0), v1 = *(const float4*)(row + c1);
    float4 p0 = *(const float4*)&w1a[c0], p1 = *(const float4*)&w1a[c1];
    float s = v0.x * p0.x + v0.y * p0.y + v0.z * p0.z + v0.w * p0.w
            + v1.x * p1.x + v1.y * p1.y + v1.z * p1.z + v1.w * p1.w;
#pragma unroll
    for (int o = 16; o; o >>= 1) s += __shfl_down_sync(~0u, s, o);
    if (lane == 0) score[gw] = s + w1a[256];
}

// ---------------- per-graph top-k via bitonic sort ----------------
__global__ void topk_sort(const float* __restrict__ score, int npg, int k,
                          int* __restrict__ gidx, float* __restrict__ tv,
                          int* __restrict__ inv) {
    __shared__ float sv[1024];
    __shared__ int si[1024];
    int g = blockIdx.x, t = threadIdx.x, nt = blockDim.x;
    for (int e = t; e < npg; e += nt) { sv[e] = score[(size_t)g * npg + e]; si[e] = e; }
    __syncthreads();
    for (int kk = 2; kk <= npg; kk <<= 1) {
        for (int j = kk >> 1; j > 0; j >>= 1) {
            for (int e = t; e < npg; e += nt) {
                int p = e ^ j;
                if (p > e) {
                    bool desc = ((e & kk) == 0);
                    float ve = sv[e], vp = sv[p];
                    if (desc ? (ve < vp) : (ve > vp)) {
                        sv[e] = vp; sv[p] = ve;
                        int tmp = si[e]; si[e] = si[p]; si[p] = tmp;
                    }
                }
            }
            __syncthreads();
        }
    }
    for (int e = t; e < k; e += nt) {
        int pos = g * k + e;
        int node = g * npg + si[e];
        gidx[pos] = node;
        tv[pos] = tanhf(sv[e]);
        if (inv) inv[node] = pos;
    }
}

// ---------------- gather pooled rows, BN inline, scaled by tanh ----------------
__global__ void pool_gather(const float* __restrict__ x, const float* __restrict__ sc,
                            const float* __restrict__ sh, const int* __restrict__ gidx,
                            const float* __restrict__ tv, float* __restrict__ xp, int n2) {
    int i = blockIdx.x * blockDim.x + threadIdx.x;
    if (i >= n2 * 64) return;
    int row = i >> 6, c4 = (i & 63) * 4;
    float t = tv[row];
    int node = gidx[row];
    float4 v = *(const float4*)&x[(size_t)node * FD + c4];
    float4 s = *(const float4*)&sc[c4];
    float4 h = *(const float4*)&sh[c4];
    v.x = (v.x * s.x + h.x) * t; v.y = (v.y * s.y + h.y) * t;
    v.z = (v.z * s.z + h.z) * t; v.w = (v.w * s.w + h.w) * t;
    *(float4*)&xp[(size_t)row * FD + c4] = v;
}

// ---------------- readout stage 1: per (graph, chunk) partial max/sum ----------------
__global__ void readout_s1(const float* __restrict__ x, const float* __restrict__ sc,
                           const float* __restrict__ sh, const int* __restrict__ gidx,
                           const float* __restrict__ tv, int k, float* __restrict__ partial) {
    int g = blockIdx.x, c = blockIdx.y, f = threadIdx.x;
    int chunk = k / 8;
    int j0 = c * chunk;
    float mx = -1e30f, sm = 0.f;
    if (gidx) {
        float scf = sc[f], shf = sh[f];
        for (int j = j0; j < j0 + chunk; j++) {
            int node = gidx[g * k + j];
            float v = (x[(size_t)node * FD + f] * scf + shf) * tv[g * k + j];
            mx = fmaxf(mx, v);
            sm += v;
        }
    } else {
        for (int j = j0; j < j0 + chunk; j++) {
            float v = x[((size_t)g * k + j) * FD + f];
            mx = fmaxf(mx, v);
            sm += v;
        }
    }
    partial[((size_t)(g * 8 + c)) * 512 + f] = mx;
    partial[((size_t)(g * 8 + c)) * 512 + 256 + f] = sm;
}

// ---------------- final: reduce both partials + linear ----------------
__global__ void final_linear(const float* __restrict__ part, const float* __restrict__ part2,
                             const float* __restrict__ Wl, const float* __restrict__ bl,
                             float* __restrict__ out) {
    __shared__ float xr[512];
    int b = blockIdx.x, t = threadIdx.x;
    float mx1 = -1e30f, sm1 = 0.f, mx2 = -1e30f, sm2 = 0.f;
#pragma unroll
    for (int c = 0; c < 8; c++) {
        size_t o1 = ((size_t)(b * 8 + c)) * 512;
        mx1 = fmaxf(mx1, part[o1 + t]);  sm1 += part[o1 + 256 + t];
        mx2 = fmaxf(mx2, part2[o1 + t]); sm2 += part2[o1 + 256 + t];
    }
    xr[t]       = mx1 + mx2;
    xr[t + 256] = sm1 / (float)KP1 + sm2 / (float)KP2;
    __syncthreads();
    float acc = bl[t];
    const float* w = Wl + (size_t)t * 512;
    for (int kk = 0; kk < 512; kk++) acc += xr[kk] * w[kk];
    out[(size_t)b * 256 + t] = acc;
}

// ---------------- host launcher ----------------
extern "C" void kernel_launch(void* const* d_in, const int* in_sizes, int n_in,
                              void* d_out, int out_size) {
    const float* x    = (const float*)d_in[0];
    const int*   ei   = (const int*)d_in[1];
    const int*   src  = ei;
    const int*   dst  = ei + ED;
    const float* W1   = (const float*)d_in[3];
    const float* as1  = (const float*)d_in[4];
    const float* ad1  = (const float*)d_in[5];
    const float* b1   = (const float*)d_in[6];
    const float* g1   = (const float*)d_in[7];
    const float* be1  = (const float*)d_in[8];
    const float* pw1  = (const float*)d_in[9];
    const float* W2   = (const float*)d_in[10];
    const float* as2  = (const float*)d_in[11];
    const float* ad2  = (const float*)d_in[12];
    const float* b2   = (const float*)d_in[13];
    const float* g2   = (const float*)d_in[14];
    const float* be2  = (const float*)d_in[15];
    const float* pw2  = (const float*)d_in[16];
    const float* Wl   = (const float*)d_in[17];
    const float* bl   = (const float*)d_in[18];
    float* out = (float*)d_out;

    float* fb = nullptr;
    int*   ib = nullptr;
    cudaGetSymbolAddress((void**)&fb, g_f);
    cudaGetSymbolAddress((void**)&ib, g_i);

    float* h1    = fb + O_H1;
    float* out1  = fb + O_OUT1;
    float* asn1  = fb + O_ASN1;
    float* adn1  = fb + O_ADN1;
    float* bns1  = fb + O_BNS1;
    float* bns2  = fb + O_BNS2;
    float* sc1   = fb + O_SC1;
    float* sh1   = fb + O_SH1;
    float* w1a   = fb + O_W1A;
    float* score1= fb + O_SCORE1;
    float* tanh1 = fb + O_TANH1;
    float* xp1   = fb + O_XP1;
    float* part  = fb + O_PART;
    float* part2 = fb + O_PART2;
    float* h2    = fb + O_H2;
    float* out2  = fb + O_OUT2;
    float* asn2  = fb + O_ASN2;
    float* adn2  = fb + O_ADN2;
    float* sc2   = fb + O_SC2;
    float* sh2   = fb + O_SH2;
    float* w2a   = fb + O_W2A;
    float* score2= fb + O_SCORE2;
    float* tanh2 = fb + O_TANH2;
    int* gidx1 = ib + IO_GIDX1;
    int* inv1  = ib + IO_INV1;
    int* gidx2 = ib + IO_GIDX2;
    int* csr1  = ib + IO_CSR1;
    int* csr2  = ib + IO_CSR2;
    int* deg1  = ib + IO_DEG1;
    int* deg2  = ib + IO_DEG2;
    int* cnt1  = ib + IO_CNT;
    int* cnt2  = ib + IO_CNT + 1;

    static cudaStream_t s2 = nullptr;
    static cudaEvent_t ev0, ev1, ev2, ev3, ev4, ev5;
    if (!s2) {
        cudaStreamCreateWithFlags(&s2, cudaStreamNonBlocking);
        cudaEventCreateWithFlags(&ev0, cudaEventDisableTiming);
        cudaEventCreateWithFlags(&ev1, cudaEventDisableTiming);
        cudaEventCreateWithFlags(&ev2, cudaEventDisableTiming);
        cudaEventCreateWithFlags(&ev3, cudaEventDisableTiming);
        cudaEventCreateWithFlags(&ev4, cudaEventDisableTiming);
        cudaEventCreateWithFlags(&ev5, cudaEventDisableTiming);
    }

    // fork: side stream does memsets + csr_build1 while main does sgemm1
    cudaEventRecord(ev0, 0);
    cudaStreamWaitEvent(s2, ev0, 0);
    cudaMemsetAsync(bns1, 0, 1024 * sizeof(float), s2);                    // bns1|bns2
    cudaMemsetAsync(deg1, 0, (size_t)(NN + N2 + 8) * sizeof(int), s2);     // deg1|deg2|cnt
    cudaMemsetAsync(inv1, 0xFF, (size_t)NN * sizeof(int), s2);
    csr_build<<<(ED + 255) / 256, 256, 0, s2>>>(src, dst, nullptr, deg1, csr1, ED);
    cudaEventRecord(ev1, s2);

    // ---- layer 1 (main stream) ----
    sgemm_attn<<<dim3(FD / 128, NN / 128), 256>>>(x, W1, h1, as1, ad1, asn1, adn1, NN, FD, INDIM);
    cudaStreamWaitEvent(0, ev1, 0);
    gat_gather<<<2048, 256>>>(csr1, deg1, asn1, adn1, h1, b1, out1, bns1, NN, (2 * NN) / 2048,
                              g1, be1, pw1, sc1, sh1, w1a, 1.0f / NN, cnt1);
    pool_score<<<NN / 8, 256>>>(out1, w1a, score1, NN);
    topk_sort<<<BT, NPG / 2>>>(score1, NPG, KP1, gidx1, tanh1, inv1);
    cudaEventRecord(ev2, 0);

    // side stream: csr_build2 (needs inv1 only)
    cudaStreamWaitEvent(s2, ev2, 0);
    csr_build<<<(ED + 255) / 256, 256, 0, s2>>>(src, dst, inv1, deg2, csr2, ED);
    cudaEventRecord(ev3, s2);

    pool_gather<<<(N2 * 64 + 255) / 256, 256>>>(out1, sc1, sh1, gidx1, tanh1, xp1, N2);
    cudaEventRecord(ev4, 0);

    // side stream: layer-1 readout partials (needs xp1)
    cudaStreamWaitEvent(s2, ev4, 0);
    readout_s1<<<dim3(BT, 8), 256, 0, s2>>>(xp1, nullptr, nullptr, nullptr, nullptr, KP1, part);
    cudaEventRecord(ev5, s2);

    // ---- layer 2 (main stream) ----
    sgemm_attn<<<dim3(FD / 128, N2 / 128), 256>>>(xp1, W2, h2, as2, ad2, asn2, adn2, N2, FD, FD);
    cudaStreamWaitEvent(0, ev3, 0);
    gat_gather<<<1024, 256>>>(csr2, deg2, asn2, adn2, h2, b2, out2, bns2, N2, (2 * N2) / 1024,
                              g2, be2, pw2, sc2, sh2, w2a, 1.0f / N2, cnt2);
    pool_score<<<N2 / 8, 256>>>(out2, w2a, score2, N2);
    topk_sort<<<BT, KP1 / 2>>>(score2, KP1, KP2, gidx2, tanh2, nullptr);
    readout_s1<<<dim3(BT, 8), 256>>>(out2, sc2, sh2, gidx2, tanh2, KP2, part2);

    // ---- final (join side stream) ----
    cudaStreamWaitEvent(0, ev5, 0);
    final_linear<<<BT, 256>>>(part, part2, Wl, bl, out);
}

// round 8
// speedup vs baseline: 1.5115x; 1.0059x over previous
#include <cuda_runtime.h>
#include <math.h>

// ---------------- problem constants ----------------
constexpr int NN   = 32768;    // total nodes layer1
constexpr int ED   = 262144;   // edges
constexpr int FD   = 256;      // feature dim (4 heads x 64)
constexpr int BT   = 32;       // graphs
constexpr int NPG  = 1024;
constexpr int KP1  = 512;
constexpr int KP2  = 256;
constexpr int N2   = BT * KP1; // 16384 pooled nodes after pool1
constexpr int INDIM = 128;
constexpr int MAXDEG = 64;     // padded CSR width

// ---------------- scratch layout (floats) ----------------
constexpr size_t O_H1    = 0;
constexpr size_t O_OUT1  = O_H1   + (size_t)NN * FD;
constexpr size_t O_ASN1  = O_OUT1 + (size_t)NN * FD;
constexpr size_t O_ADN1  = O_ASN1 + (size_t)NN * 4;
constexpr size_t O_BNS1  = O_ADN1 + (size_t)NN * 4;   // 512
constexpr size_t O_BNS2  = O_BNS1 + 512;              // 512 (adjacent -> one memset)
constexpr size_t O_SC1   = O_BNS2 + 512;
constexpr size_t O_SH1   = O_SC1  + 256;
constexpr size_t O_W1A   = O_SH1  + 256;   // 256 + 1
constexpr size_t O_SCORE1= O_W1A  + 260;
constexpr size_t O_TANH1 = O_SCORE1 + NN;
constexpr size_t O_XP1   = O_TANH1  + N2;
constexpr size_t O_PART  = O_XP1    + (size_t)N2 * FD;
constexpr size_t O_PART2 = O_PART   + (size_t)BT * 8 * 512;
constexpr size_t O_H2    = O_PART2  + (size_t)BT * 8 * 512;
constexpr size_t O_OUT2  = O_H2     + (size_t)N2 * FD;
constexpr size_t O_ASN2  = O_OUT2   + (size_t)N2 * FD;
constexpr size_t O_ADN2  = O_ASN2   + (size_t)N2 * 4;
constexpr size_t O_SC2   = O_ADN2   + (size_t)N2 * 4;
constexpr size_t O_SH2   = O_SC2    + 256;
constexpr size_t O_W2A   = O_SH2    + 256;
constexpr size_t O_SCORE2= O_W2A    + 260;
constexpr size_t O_TANH2 = O_SCORE2 + N2;
constexpr size_t F_TOTAL = O_TANH2  + (size_t)BT * KP2;

__device__ float g_f[F_TOTAL];

constexpr size_t IO_GIDX1 = 0;
constexpr size_t IO_INV1  = IO_GIDX1 + N2;
constexpr size_t IO_GIDX2 = IO_INV1  + NN;
constexpr size_t IO_CSR1  = IO_GIDX2 + (size_t)BT * KP2;
constexpr size_t IO_CSR2  = IO_CSR1  + (size_t)NN * MAXDEG;
constexpr size_t IO_DEG1  = IO_CSR2  + (size_t)N2 * MAXDEG;  // deg1|deg2|cnt adjacent
constexpr size_t IO_DEG2  = IO_DEG1  + NN;
constexpr size_t IO_CNT   = IO_DEG2  + N2;
constexpr size_t I_TOTAL  = IO_CNT   + 8;

__device__ int g_i[I_TOTAL];

// ---------------- tf32 helpers ----------------
__device__ __forceinline__ unsigned f2tf(float x) {
    unsigned r;
    asm("cvt.rna.tf32.f32 %0, %1;" : "=r"(r) : "f"(x));
    return r;
}
__device__ __forceinline__ void split_tf(float x, float& hi, float& lo) {
    unsigned hb = f2tf(x);
    hi = __uint_as_float(hb);
    lo = __uint_as_float(f2tf(x - hi));
}
__device__ __forceinline__ void mma_tf32(float c[4], const unsigned a[4],
                                         unsigned b0, unsigned b1) {
    asm volatile(
        "mma.sync.aligned.m16n8k8.row.col.f32.tf32.tf32.f32 "
        "{%0,%1,%2,%3}, {%4,%5,%6,%7}, {%8,%9}, {%0,%1,%2,%3};"
        : "+f"(c[0]), "+f"(c[1]), "+f"(c[2]), "+f"(c[3])
        : "r"(a[0]), "r"(a[1]), "r"(a[2]), "r"(a[3]), "r"(b0), "r"(b1));
}

// ---------------- tf32 GEMM (3xTF32) + fused attention-score epilogue ----------------
// C[MxN] = A[MxK] @ B[KxN].  CTA tile 128x128, warps 4(M)x2(N), warp tile 32x64.
// Warp's 64 N-cols = exactly one head -> attn dots from register acc.
__global__ __launch_bounds__(256) void sgemm_tf32_attn(
    const float* __restrict__ A, const float* __restrict__ B, float* __restrict__ C,
    const float* __restrict__ a_s, const float* __restrict__ a_d,
    float* __restrict__ asn, float* __restrict__ adn, int M, int N, int K) {
    __shared__ float Ah[16][136], Al[16][136];
    __shared__ float Bh[16][136], Bl[16][136];
    int tid = threadIdx.x, lane = tid & 31, w = tid >> 5;
    int wm = (w >> 1) * 32, wn = (w & 1) * 64;
    int g = lane >> 2, l4 = lane & 3;
    int m0 = blockIdx.y * 128, n0 = blockIdx.x * 128;

    float c[2][8][4];
#pragma unroll
    for (int fm = 0; fm < 2; fm++)
#pragma unroll
        for (int nf = 0; nf < 8; nf++)
#pragma unroll
            for (int i = 0; i < 4; i++) c[fm][nf][i] = 0.f;

    // loaders: A thread -> row tid&127, 8 cols at (tid>>7)*8; B thread -> k row tid>>4, 8 cols at (tid&15)*8
    int arow = tid & 127, acol = (tid >> 7) * 8;
    int brow = tid >> 4, bcol = (tid & 15) * 8;
    const float* Ap = A + (size_t)(m0 + arow) * K + acol;
    const float* Bp = B + (size_t)brow * N + n0 + bcol;

    float4 ra0 = *(const float4*)(Ap);
    float4 ra1 = *(const float4*)(Ap + 4);
    float4 rb0 = *(const float4*)(Bp);
    float4 rb1 = *(const float4*)(Bp + 4);

    for (int k0 = 0; k0 < K; k0 += 16) {
        // split + store A (transposed k-major)
        float hi, lo;
        split_tf(ra0.x, hi, lo); Ah[acol + 0][arow] = hi; Al[acol + 0][arow] = lo;
        split_tf(ra0.y, hi, lo); Ah[acol + 1][arow] = hi; Al[acol + 1][arow] = lo;
        split_tf(ra0.z, hi, lo); Ah[acol + 2][arow] = hi; Al[acol + 2][arow] = lo;
        split_tf(ra0.w, hi, lo); Ah[acol + 3][arow] = hi; Al[acol + 3][arow] = lo;
        split_tf(ra1.x, hi, lo); Ah[acol + 4][arow] = hi; Al[acol + 4][arow] = lo;
        split_tf(ra1.y, hi, lo); Ah[acol + 5][arow] = hi; Al[acol + 5][arow] = lo;
        split_tf(ra1.z, hi, lo); Ah[acol + 6][arow] = hi; Al[acol + 6][arow] = lo;
        split_tf(ra1.w, hi, lo); Ah[acol + 7][arow] = hi; Al[acol + 7][arow] = lo;
        // split + store B (natural k x n)
        float4 h4, lo4;
        split_tf(rb0.x, h4.x, lo4.x); split_tf(rb0.y, h4.y, lo4.y);
        split_tf(rb0.z, h4.z, lo4.z); split_tf(rb0.w, h4.w, lo4.w);
        *(float4*)&Bh[brow][bcol] = h4; *(float4*)&Bl[brow][bcol] = lo4;
        split_tf(rb1.x, h4.x, lo4.x); split_tf(rb1.y, h4.y, lo4.y);
        split_tf(rb1.z, h4.z, lo4.z); split_tf(rb1.w, h4.w, lo4.w);
        *(float4*)&Bh[brow][bcol + 4] = h4; *(float4*)&Bl[brow][bcol + 4] = lo4;
        __syncthreads();
        if (k0 + 16 < K) {
            ra0 = *(const float4*)(Ap + k0 + 16);
            ra1 = *(const float4*)(Ap + k0 + 20);
            rb0 = *(const float4*)(Bp + (size_t)(k0 + 16) * N);
            rb1 = *(const float4*)(Bp + (size_t)(k0 + 16) * N + 4);
        }
#pragma unroll
        for (int kk = 0; kk < 16; kk += 8) {
            unsigned ah[2][4], al[2][4];
#pragma unroll
            for (int fm = 0; fm < 2; fm++) {
                int r = wm + fm * 16;
                ah[fm][0] = __float_as_uint(Ah[kk + l4][r + g]);
                ah[fm][1] = __float_as_uint(Ah[kk + l4][r + g + 8]);
                ah[fm][2] = __float_as_uint(Ah[kk + l4 + 4][r + g]);
                ah[fm][3] = __float_as_uint(Ah[kk + l4 + 4][r + g + 8]);
                al[fm][0] = __float_as_uint(Al[kk + l4][r + g]);
                al[fm][1] = __float_as_uint(Al[kk + l4][r + g + 8]);
                al[fm][2] = __float_as_uint(Al[kk + l4 + 4][r + g]);
                al[fm][3] = __float_as_uint(Al[kk + l4 + 4][r + g + 8]);
            }
#pragma unroll
            for (int nf = 0; nf < 8; nf++) {
                int nc = wn + nf * 8 + g;
                unsigned bh0 = __float_as_uint(Bh[kk + l4][nc]);
                unsigned bh1 = __float_as_uint(Bh[kk + l4 + 4][nc]);
                unsigned bl0 = __float_as_uint(Bl[kk + l4][nc]);
                unsigned bl1 = __float_as_uint(Bl[kk + l4 + 4][nc]);
#pragma unroll
                for (int fm = 0; fm < 2; fm++) {
                    mma_tf32(c[fm][nf], ah[fm], bh0, bh1);
                    mma_tf32(c[fm][nf], al[fm], bh0, bh1);
                    mma_tf32(c[fm][nf], ah[fm], bl0, bl1);
                }
            }
        }
        __syncthreads();
    }

    // ---- store C ----
#pragma unroll
    for (int fm = 0; fm < 2; fm++) {
        int r0 = m0 + wm + fm * 16 + g;
#pragma unroll
        for (int nf = 0; nf < 8; nf++) {
            int col = n0 + wn + nf * 8 + 2 * l4;
            *(float2*)&C[(size_t)r0 * N + col]       = make_float2(c[fm][nf][0], c[fm][nf][1]);
            *(float2*)&C[(size_t)(r0 + 8) * N + col] = make_float2(c[fm][nf][2], c[fm][nf][3]);
        }
    }

    // ---- attention epilogue: head = n0/64 + (w&1) ----
    int head = (n0 >> 6) + (w & 1);
    float asw0[8], asw1[8], adw0[8], adw1[8];
#pragma unroll
    for (int nf = 0; nf < 8; nf++) {
        int col = head * 64 + nf * 8 + 2 * l4;
        asw0[nf] = a_s[col]; asw1[nf] = a_s[col + 1];
        adw0[nf] = a_d[col]; adw1[nf] = a_d[col + 1];
    }
#pragma unroll
    for (int fm = 0; fm < 2; fm++) {
        float pa0 = 0.f, pa1 = 0.f, pd0 = 0.f, pd1 = 0.f;
#pragma unroll
        for (int nf = 0; nf < 8; nf++) {
            pa0 += c[fm][nf][0] * asw0[nf] + c[fm][nf][1] * asw1[nf];
            pa1 += c[fm][nf][2] * asw0[nf] + c[fm][nf][3] * asw1[nf];
            pd0 += c[fm][nf][0] * adw0[nf] + c[fm][nf][1] * adw1[nf];
            pd1 += c[fm][nf][2] * adw0[nf] + c[fm][nf][3] * adw1[nf];
        }
#pragma unroll
        for (int o = 1; o <= 2; o <<= 1) {
            pa0 += __shfl_xor_sync(~0u, pa0, o);
            pa1 += __shfl_xor_sync(~0u, pa1, o);
            pd0 += __shfl_xor_sync(~0u, pd0, o);
            pd1 += __shfl_xor_sync(~0u, pd1, o);
        }
        if (l4 == 0) {
            int r0 = m0 + wm + fm * 16 + g;
            asn[r0 * 4 + head] = pa0; asn[(r0 + 8) * 4 + head] = pa1;
            adn[r0 * 4 + head] = pd0; adn[(r0 + 8) * 4 + head] = pd1;
        }
    }
}

// ---------------- padded-CSR build ----------------
__global__ void csr_build(const int* __restrict__ src, const int* __restrict__ dst,
                          const int* __restrict__ inv, int* __restrict__ deg,
                          int* __restrict__ csr, int nE) {
    int i = blockIdx.x * blockDim.x + threadIdx.x;
    if (i >= nE) return;
    int s = src[i], d = dst[i];
    if (inv) { s = inv[s]; d = inv[d]; if (s < 0 || d < 0) return; }
    int p = atomicAdd(&deg[d], 1);
    if (p < MAXDEG) csr[(size_t)d * MAXDEG + p] = s;
}

// ---------------- fused GAT gather + BN-finalize tail (last-block pattern) ----------------
__global__ __launch_bounds__(256, 6) void gat_gather(
    const int* __restrict__ csr, const int* __restrict__ deg,
    const float* __restrict__ asn, const float* __restrict__ adn,
    const float* __restrict__ h, const float* __restrict__ bias,
    float* __restrict__ out, float* __restrict__ sums, int n, int upb,
    const float* __restrict__ gw, const float* __restrict__ be,
    const float* __restrict__ pw, float* __restrict__ scale,
    float* __restrict__ shift, float* __restrict__ w1a, float invn,
    int* __restrict__ counter) {
    __shared__ float ssum[512];
    __shared__ float4 sst[8][64];
    __shared__ int lastFlag;
    int t = threadIdx.x;
    ssum[t] = 0.f; ssum[t + 256] = 0.f;
    __syncthreads();
    int lane = t & 31, w = t >> 5;
    int half = (blockIdx.x * upb + w) & 1;
    int c = half * 128 + lane * 4;
    float4 bb = *(const float4*)&bias[c];
    float st[8];
#pragma unroll
    for (int i = 0; i < 8; i++) st[i] = 0.f;

    int base = blockIdx.x * upb;
    int end = base + upb; if (end > 2 * n) end = 2 * n;
    for (int u = base + w; u < end; u += 8) {
        int nd = u >> 1;
        float2 ad = *(const float2*)&adn[(size_t)nd * 4 + half * 2];
        int dg = deg[nd]; if (dg > 63) dg = 63;
        const int* row = csr + (size_t)nd * MAXDEG;
        int sA = (lane < dg) ? row[lane] : nd;
        int sB = (lane + 32 < dg) ? row[lane + 32] : nd;
        bool vA = (lane <= dg);
        bool vB = (lane + 32 <= dg);
        float2 aA = *(const float2*)&asn[(size_t)sA * 4 + half * 2];
        float2 aB = *(const float2*)&asn[(size_t)sB * 4 + half * 2];
        float lA0 = aA.x + ad.x, lA1 = aA.y + ad.y;
        float lB0 = aB.x + ad.x, lB1 = aB.y + ad.y;
        lA0 = lA0 > 0.f ? lA0 : 0.2f * lA0;  lB0 = lB0 > 0.f ? lB0 : 0.2f * lB0;
        lA1 = lA1 > 0.f ? lA1 : 0.2f * lA1;  lB1 = lB1 > 0.f ? lB1 : 0.2f * lB1;
        float pA0 = vA ? __expf(lA0) : 0.f, pA1 = vA ? __expf(lA1) : 0.f;
        float pB0 = vB ? __expf(lB0) : 0.f, pB1 = vB ? __expf(lB1) : 0.f;
        float d0 = pA0 + pB0, d1 = pA1 + pB1;
#pragma unroll
        for (int o = 16; o; o >>= 1) {
            d0 += __shfl_xor_sync(~0u, d0, o);
            d1 += __shfl_xor_sync(~0u, d1, o);
        }
        float r0 = 1.f / d0, r1 = 1.f / d1;
        __syncwarp();
        sst[w][lane]      = make_float4(__int_as_float(sA * FD), pA0 * r0, pA1 * r1, 0.f);
        sst[w][lane + 32] = make_float4(__int_as_float(sB * FD), pB0 * r0, pB1 * r1, 0.f);
        __syncwarp();
        float4 a0 = make_float4(0, 0, 0, 0);
        int ne = dg + 1;
#pragma unroll 4
        for (int e = 0; e < ne; e++) {
            float4 gq = sst[w][e];
            int sofs = __float_as_int(gq.x);
            float p = (lane & 16) ? gq.z : gq.y;
            float4 v = *(const float4*)(h + sofs + c);
            a0.x += p * v.x; a0.y += p * v.y; a0.z += p * v.z; a0.w += p * v.w;
        }
        float o[4];
        o[0] = a0.x + bb.x; o[1] = a0.y + bb.y;
        o[2] = a0.z + bb.z; o[3] = a0.w + bb.w;
#pragma unroll
        for (int i = 0; i < 4; i++) {
            float v = o[i];
            v = 0.5f * v * (1.0f + erff(v * 0.70710678118654752f));
            o[i] = v;
            st[i] += v; st[4 + i] += v * v;
        }
        *(float4*)(out + (size_t)nd * FD + c) = make_float4(o[0], o[1], o[2], o[3]);
    }
#pragma unroll
    for (int i = 0; i < 4; i++) {
        atomicAdd(&ssum[c + i],       st[i]);
        atomicAdd(&ssum[256 + c + i], st[4 + i]);
    }
    __syncthreads();
    atomicAdd(&sums[t],       ssum[t]);
    atomicAdd(&sums[t + 256], ssum[t + 256]);
    __threadfence();
    __syncthreads();
    if (t == 0) lastFlag = (atomicAdd(counter, 1) == (int)gridDim.x - 1) ? 1 : 0;
    __syncthreads();
    if (!lastFlag) return;

    // ---- BN finalize (one block; sums complete & L2-coherent) ----
    float* red = ssum;
    float* scs = (float*)sst;
    float* shs = scs + 256;
    int f = t;
    float mean = __ldcg(&sums[f]) * invn;
    float var  = __ldcg(&sums[256 + f]) * invn - mean * mean;
    float sc = gw[f] * rsqrtf(var + 1e-5f);
    float sh = be[f] - mean * sc;
    scale[f] = sc; shift[f] = sh;
    scs[f] = sc; shs[f] = sh;
    float pwf = pw[f];
    red[f] = pwf * pwf;
    __syncthreads();
    for (int s = 128; s; s >>= 1) {
        if (f < s) red[f] += red[f + s];
        __syncthreads();
    }
    float pwn = pwf * rsqrtf(red[0]);
    w1a[f] = scs[f] * pwn;
    __syncthreads();
    red[f] = shs[f] * pwn;
    __syncthreads();
    for (int s = 128; s; s >>= 1) {
        if (f < s) red[f] += red[f + s];
        __syncthreads();
    }
    if (f == 0) w1a[256] = red[0];
}

// ---------------- pool score: dot(x, w1) + w0 ----------------
__global__ void pool_score(const float* __restrict__ x, const float* __restrict__ w1a,
                           float* __restrict__ score, int n) {
    int gw = (blockIdx.x * blockDim.x + threadIdx.x) >> 5;
    int lane = threadIdx.x & 31;
    if (gw >= n) return;
    const float* row = x + (size_t)gw * FD;
    int c0 = lane * 4, c1 = c0 + 128;
    float4 v0 = *(const float4*)(row + c0), v1 = *(const float4*)(row + c1);
    float4 p0 = *(const float4*)&w1a[c0], p1 = *(const float4*)&w1a[c1];
    float s = v0.x * p0.x + v0.y * p0.y + v0.z * p0.z + v0.w * p0.w
            + v1.x * p1.x + v1.y * p1.y + v1.z * p1.z + v1.w * p1.w;
#pragma unroll
    for (int o = 16; o; o >>= 1) s += __shfl_down_sync(~0u, s, o);
    if (lane == 0) score[gw] = s + w1a[256];
}

// ---------------- per-graph top-k via bitonic sort ----------------
__global__ void topk_sort(const float* __restrict__ score, int npg, int k,
                          int* __restrict__ gidx, float* __restrict__ tv,
                          int* __restrict__ inv) {
    __shared__ float sv[1024];
    __shared__ int si[1024];
    int g = blockIdx.x, t = threadIdx.x, nt = blockDim.x;
    for (int e = t; e < npg; e += nt) { sv[e] = score[(size_t)g * npg + e]; si[e] = e; }
    __syncthreads();
    for (int kk = 2; kk <= npg; kk <<= 1) {
        for (int j = kk >> 1; j > 0; j >>= 1) {
            for (int e = t; e < npg; e += nt) {
                int p = e ^ j;
                if (p > e) {
                    bool desc = ((e & kk) == 0);
                    float ve = sv[e], vp = sv[p];
                    if (desc ? (ve < vp) : (ve > vp)) {
                        sv[e] = vp; sv[p] = ve;
                        int tmp = si[e]; si[e] = si[p]; si[p] = tmp;
                    }
                }
            }
            __syncthreads();
        }
    }
    for (int e = t; e < k; e += nt) {
        int pos = g * k + e;
        int node = g * npg + si[e];
        gidx[pos] = node;
        tv[pos] = tanhf(sv[e]);
        if (inv) inv[node] = pos;
    }
}

// ---------------- gather pooled rows, BN inline, scaled by tanh ----------------
__global__ void pool_gather(const float* __restrict__ x, const float* __restrict__ sc,
                            const float* __restrict__ sh, const int* __restrict__ gidx,
                            const float* __restrict__ tv, float* __restrict__ xp, int n2) {
    int i = blockIdx.x * blockDim.x + threadIdx.x;
    if (i >= n2 * 64) return;
    int row = i >> 6, c4 = (i & 63) * 4;
    float t = tv[row];
    int node = gidx[row];
    float4 v = *(const float4*)&x[(size_t)node * FD + c4];
    float4 s = *(const float4*)&sc[c4];
    float4 h = *(const float4*)&sh[c4];
    v.x = (v.x * s.x + h.x) * t; v.y = (v.y * s.y + h.y) * t;
    v.z = (v.z * s.z + h.z) * t; v.w = (v.w * s.w + h.w) * t;
    *(float4*)&xp[(size_t)row * FD + c4] = v;
}

// ---------------- readout stage 1: per (graph, chunk) partial max/sum ----------------
__global__ void readout_s1(const float* __restrict__ x, const float* __restrict__ sc,
                           const float* __restrict__ sh, const int* __restrict__ gidx,
                           const float* __restrict__ tv, int k, float* __restrict__ partial) {
    int g = blockIdx.x, c = blockIdx.y, f = threadIdx.x;
    int chunk = k / 8;
    int j0 = c * chunk;
    float mx = -1e30f, sm = 0.f;
    if (gidx) {
        float scf = sc[f], shf = sh[f];
        for (int j = j0; j < j0 + chunk; j++) {
            int node = gidx[g * k + j];
            float v = (x[(size_t)node * FD + f] * scf + shf) * tv[g * k + j];
            mx = fmaxf(mx, v);
            sm += v;
        }
    } else {
        for (int j = j0; j < j0 + chunk; j++) {
            float v = x[((size_t)g * k + j) * FD + f];
            mx = fmaxf(mx, v);
            sm += v;
        }
    }
    partial[((size_t)(g * 8 + c)) * 512 + f] = mx;
    partial[((size_t)(g * 8 + c)) * 512 + 256 + f] = sm;
}

// ---------------- final: reduce both partials + linear ----------------
__global__ void final_linear(const float* __restrict__ part, const float* __restrict__ part2,
                             const float* __restrict__ Wl, const float* __restrict__ bl,
                             float* __restrict__ out) {
    __shared__ float xr[512];
    int b = blockIdx.x, t = threadIdx.x;
    float mx1 = -1e30f, sm1 = 0.f, mx2 = -1e30f, sm2 = 0.f;
#pragma unroll
    for (int c = 0; c < 8; c++) {
        size_t o1 = ((size_t)(b * 8 + c)) * 512;
        mx1 = fmaxf(mx1, part[o1 + t]);  sm1 += part[o1 + 256 + t];
        mx2 = fmaxf(mx2, part2[o1 + t]); sm2 += part2[o1 + 256 + t];
    }
    xr[t]       = mx1 + mx2;
    xr[t + 256] = sm1 / (float)KP1 + sm2 / (float)KP2;
    __syncthreads();
    float acc = bl[t];
    const float* w = Wl + (size_t)t * 512;
    for (int kk = 0; kk < 512; kk++) acc += xr[kk] * w[kk];
    out[(size_t)b * 256 + t] = acc;
}

// ---------------- host launcher ----------------
extern "C" void kernel_launch(void* const* d_in, const int* in_sizes, int n_in,
                              void* d_out, int out_size) {
    const float* x    = (const float*)d_in[0];
    const int*   ei   = (const int*)d_in[1];
    const int*   src  = ei;
    const int*   dst  = ei + ED;
    const float* W1   = (const float*)d_in[3];
    const float* as1  = (const float*)d_in[4];
    const float* ad1  = (const float*)d_in[5];
    const float* b1   = (const float*)d_in[6];
    const float* g1   = (const float*)d_in[7];
    const float* be1  = (const float*)d_in[8];
    const float* pw1  = (const float*)d_in[9];
    const float* W2   = (const float*)d_in[10];
    const float* as2  = (const float*)d_in[11];
    const float* ad2  = (const float*)d_in[12];
    const float* b2   = (const float*)d_in[13];
    const float* g2   = (const float*)d_in[14];
    const float* be2  = (const float*)d_in[15];
    const float* pw2  = (const float*)d_in[16];
    const float* Wl   = (const float*)d_in[17];
    const float* bl   = (const float*)d_in[18];
    float* out = (float*)d_out;

    float* fb = nullptr;
    int*   ib = nullptr;
    cudaGetSymbolAddress((void**)&fb, g_f);
    cudaGetSymbolAddress((void**)&ib, g_i);

    float* h1    = fb + O_H1;
    float* out1  = fb + O_OUT1;
    float* asn1  = fb + O_ASN1;
    float* adn1  = fb + O_ADN1;
    float* bns1  = fb + O_BNS1;
    float* bns2  = fb + O_BNS2;
    float* sc1   = fb + O_SC1;
    float* sh1   = fb + O_SH1;
    float* w1a   = fb + O_W1A;
    float* score1= fb + O_SCORE1;
    float* tanh1 = fb + O_TANH1;
    float* xp1   = fb + O_XP1;
    float* part  = fb + O_PART;
    float* part2 = fb + O_PART2;
    float* h2    = fb + O_H2;
    float* out2  = fb + O_OUT2;
    float* asn2  = fb + O_ASN2;
    float* adn2  = fb + O_ADN2;
    float* sc2   = fb + O_SC2;
    float* sh2   = fb + O_SH2;
    float* w2a   = fb + O_W2A;
    float* score2= fb + O_SCORE2;
    float* tanh2 = fb + O_TANH2;
    int* gidx1 = ib + IO_GIDX1;
    int* inv1  = ib + IO_INV1;
    int* gidx2 = ib + IO_GIDX2;
    int* csr1  = ib + IO_CSR1;
    int* csr2  = ib + IO_CSR2;
    int* deg1  = ib + IO_DEG1;
    int* deg2  = ib + IO_DEG2;
    int* cnt1  = ib + IO_CNT;
    int* cnt2  = ib + IO_CNT + 1;

    static cudaStream_t s2 = nullptr;
    static cudaEvent_t ev0, ev1, ev2, ev3, ev4, ev5;
    if (!s2) {
        cudaStreamCreateWithFlags(&s2, cudaStreamNonBlocking);
        cudaEventCreateWithFlags(&ev0, cudaEventDisableTiming);
        cudaEventCreateWithFlags(&ev1, cudaEventDisableTiming);
        cudaEventCreateWithFlags(&ev2, cudaEventDisableTiming);
        cudaEventCreateWithFlags(&ev3, cudaEventDisableTiming);
        cudaEventCreateWithFlags(&ev4, cudaEventDisableTiming);
        cudaEventCreateWithFlags(&ev5, cudaEventDisableTiming);
    }

    // fork: side stream does memsets + csr_build1 while main does sgemm1
    cudaEventRecord(ev0, 0);
    cudaStreamWaitEvent(s2, ev0, 0);
    cudaMemsetAsync(bns1, 0, 1024 * sizeof(float), s2);                    // bns1|bns2
    cudaMemsetAsync(deg1, 0, (size_t)(NN + N2 + 8) * sizeof(int), s2);     // deg1|deg2|cnt
    cudaMemsetAsync(inv1, 0xFF, (size_t)NN * sizeof(int), s2);
    csr_build<<<(ED + 255) / 256, 256, 0, s2>>>(src, dst, nullptr, deg1, csr1, ED);
    cudaEventRecord(ev1, s2);

    // ---- layer 1 (main stream) ----
    sgemm_tf32_attn<<<dim3(FD / 128, NN / 128), 256>>>(x, W1, h1, as1, ad1, asn1, adn1, NN, FD, INDIM);
    cudaStreamWaitEvent(0, ev1, 0);
    gat_gather<<<2048, 256>>>(csr1, deg1, asn1, adn1, h1, b1, out1, bns1, NN, (2 * NN) / 2048,
                              g1, be1, pw1, sc1, sh1, w1a, 1.0f / NN, cnt1);
    pool_score<<<NN / 8, 256>>>(out1, w1a, score1, NN);
    topk_sort<<<BT, NPG / 2>>>(score1, NPG, KP1, gidx1, tanh1, inv1);
    cudaEventRecord(ev2, 0);

    // side stream: csr_build2 (needs inv1 only)
    cudaStreamWaitEvent(s2, ev2, 0);
    csr_build<<<(ED + 255) / 256, 256, 0, s2>>>(src, dst, inv1, deg2, csr2, ED);
    cudaEventRecord(ev3, s2);

    pool_gather<<<(N2 * 64 + 255) / 256, 256>>>(out1, sc1, sh1, gidx1, tanh1, xp1, N2);
    cudaEventRecord(ev4, 0);

    // side stream: layer-1 readout partials (needs xp1)
    cudaStreamWaitEvent(s2, ev4, 0);
    readout_s1<<<dim3(BT, 8), 256, 0, s2>>>(xp1, nullptr, nullptr, nullptr, nullptr, KP1, part);
    cudaEventRecord(ev5, s2);

    // ---- layer 2 (main stream) ----
    sgemm_tf32_attn<<<dim3(FD / 128, N2 / 128), 256>>>(xp1, W2, h2, as2, ad2, asn2, adn2, N2, FD, FD);
    cudaStreamWaitEvent(0, ev3, 0);
    gat_gather<<<1024, 256>>>(csr2, deg2, asn2, adn2, h2, b2, out2, bns2, N2, (2 * N2) / 1024,
                              g2, be2, pw2, sc2, sh2, w2a, 1.0f / N2, cnt2);
    pool_score<<<N2 / 8, 256>>>(out2, w2a, score2, N2);
    topk_sort<<<BT, KP1 / 2>>>(score2, KP1, KP2, gidx2, tanh2, nullptr);
    readout_s1<<<dim3(BT, 8), 256>>>(out2, sc2, sh2, gidx2, tanh2, KP2, part2);

    // ---- final (join side stream) ----
    cudaStreamWaitEvent(0, ev5, 0);
    final_linear<<<BT, 256>>>(part, part2, Wl, bl, out);
}

// round 9
// speedup vs baseline: 1.6172x; 1.0699x over previous
#include <cuda_runtime.h>
#include <math.h>

// ---------------- problem constants ----------------
constexpr int NN   = 32768;    // total nodes layer1
constexpr int ED   = 262144;   // edges
constexpr int FD   = 256;      // feature dim (4 heads x 64)
constexpr int BT   = 32;       // graphs
constexpr int NPG  = 1024;
constexpr int KP1  = 512;
constexpr int KP2  = 256;
constexpr int N2   = BT * KP1; // 16384 pooled nodes after pool1
constexpr int INDIM = 128;
constexpr int MAXDEG = 64;     // padded CSR width

// ---------------- scratch layout (floats) ----------------
constexpr size_t O_H1    = 0;
constexpr size_t O_OUT1  = O_H1   + (size_t)NN * FD;
constexpr size_t O_ASN1  = O_OUT1 + (size_t)NN * FD;
constexpr size_t O_ADN1  = O_ASN1 + (size_t)NN * 4;
constexpr size_t O_BNS1  = O_ADN1 + (size_t)NN * 4;   // 512
constexpr size_t O_BNS2  = O_BNS1 + 512;              // 512 (adjacent -> one memset)
constexpr size_t O_SC1   = O_BNS2 + 512;
constexpr size_t O_SH1   = O_SC1  + 256;
constexpr size_t O_W1A   = O_SH1  + 256;   // 256 + 1
constexpr size_t O_SCORE1= O_W1A  + 260;
constexpr size_t O_TANH1 = O_SCORE1 + NN;
constexpr size_t O_PART  = O_TANH1  + N2;
constexpr size_t O_PART2 = O_PART   + (size_t)BT * 8 * 512;
constexpr size_t O_H2    = O_PART2  + (size_t)BT * 8 * 512;
constexpr size_t O_OUT2  = O_H2     + (size_t)N2 * FD;
constexpr size_t O_ASN2  = O_OUT2   + (size_t)N2 * FD;
constexpr size_t O_ADN2  = O_ASN2   + (size_t)N2 * 4;
constexpr size_t O_SC2   = O_ADN2   + (size_t)N2 * 4;
constexpr size_t O_SH2   = O_SC2    + 256;
constexpr size_t O_W2A   = O_SH2    + 256;
constexpr size_t O_SCORE2= O_W2A    + 260;
constexpr size_t O_TANH2 = O_SCORE2 + N2;
constexpr size_t F_TOTAL = O_TANH2  + (size_t)BT * KP2;

__device__ float g_f[F_TOTAL];

constexpr size_t IO_GIDX1 = 0;
constexpr size_t IO_INV1  = IO_GIDX1 + N2;
constexpr size_t IO_GIDX2 = IO_INV1  + NN;
constexpr size_t IO_CSR1  = IO_GIDX2 + (size_t)BT * KP2;
constexpr size_t IO_CSR2  = IO_CSR1  + (size_t)NN * MAXDEG;
constexpr size_t IO_DEG1  = IO_CSR2  + (size_t)N2 * MAXDEG;  // deg1|deg2|cnt adjacent
constexpr size_t IO_DEG2  = IO_DEG1  + NN;
constexpr size_t IO_CNT   = IO_DEG2  + N2;
constexpr size_t I_TOTAL  = IO_CNT   + 8;

__device__ int g_i[I_TOTAL];

// ---------------- tf32 helpers ----------------
__device__ __forceinline__ unsigned f2tf(float x) {
    unsigned r;
    asm("cvt.rna.tf32.f32 %0, %1;" : "=r"(r) : "f"(x));
    return r;
}
__device__ __forceinline__ void split_tf(float x, float& hi, float& lo) {
    unsigned hb = f2tf(x);
    hi = __uint_as_float(hb);
    lo = __uint_as_float(f2tf(x - hi));
}
__device__ __forceinline__ void mma_tf32(float c[4], const unsigned a[4],
                                         unsigned b0, unsigned b1) {
    asm volatile(
        "mma.sync.aligned.m16n8k8.row.col.f32.tf32.tf32.f32 "
        "{%0,%1,%2,%3}, {%4,%5,%6,%7}, {%8,%9}, {%0,%1,%2,%3};"
        : "+f"(c[0]), "+f"(c[1]), "+f"(c[2]), "+f"(c[3])
        : "r"(a[0]), "r"(a[1]), "r"(a[2]), "r"(a[3]), "r"(b0), "r"(b1));
}

// ---------------- tf32 GEMM (3xTF32) + fused attention epilogue + optional A-gather ----------------
// C[MxN] = A'[MxK] @ B[KxN] where A'[r] = gidx_a ? (A[gidx_a[r]]*asc+ash)*atv[r] : A[r].
__global__ __launch_bounds__(256) void sgemm_tf32_attn(
    const float* __restrict__ A, const float* __restrict__ B, float* __restrict__ C,
    const float* __restrict__ a_s, const float* __restrict__ a_d,
    float* __restrict__ asn, float* __restrict__ adn, int M, int N, int K,
    const int* __restrict__ gidx_a, const float* __restrict__ asc,
    const float* __restrict__ ash, const float* __restrict__ atv) {
    __shared__ float Ah[16][136], Al[16][136];
    __shared__ float Bh[16][136], Bl[16][136];
    int tid = threadIdx.x, lane = tid & 31, w = tid >> 5;
    int wm = (w >> 1) * 32, wn = (w & 1) * 64;
    int g = lane >> 2, l4 = lane & 3;
    int m0 = blockIdx.y * 128, n0 = blockIdx.x * 128;

    float c[2][8][4];
#pragma unroll
    for (int fm = 0; fm < 2; fm++)
#pragma unroll
        for (int nf = 0; nf < 8; nf++)
#pragma unroll
            for (int i = 0; i < 4; i++) c[fm][nf][i] = 0.f;

    int arow = tid & 127, acol = (tid >> 7) * 8;
    int brow = tid >> 4, bcol = (tid & 15) * 8;
    int srow = m0 + arow;
    float tval = 1.f;
    if (gidx_a) { tval = atv[srow]; srow = gidx_a[srow]; }
    const float* Ap = A + (size_t)srow * K + acol;
    const float* Bp = B + (size_t)brow * N + n0 + bcol;

    float4 ra0 = *(const float4*)(Ap);
    float4 ra1 = *(const float4*)(Ap + 4);
    float4 rb0 = *(const float4*)(Bp);
    float4 rb1 = *(const float4*)(Bp + 4);

    for (int k0 = 0; k0 < K; k0 += 16) {
        if (gidx_a) {   // apply BN+tanh to this tile's A columns (k0+acol..)
            float4 s0 = *(const float4*)&asc[k0 + acol];
            float4 s1 = *(const float4*)&asc[k0 + acol + 4];
            float4 h0 = *(const float4*)&ash[k0 + acol];
            float4 h1 = *(const float4*)&ash[k0 + acol + 4];
            ra0.x = (ra0.x * s0.x + h0.x) * tval; ra0.y = (ra0.y * s0.y + h0.y) * tval;
            ra0.z = (ra0.z * s0.z + h0.z) * tval; ra0.w = (ra0.w * s0.w + h0.w) * tval;
            ra1.x = (ra1.x * s1.x + h1.x) * tval; ra1.y = (ra1.y * s1.y + h1.y) * tval;
            ra1.z = (ra1.z * s1.z + h1.z) * tval; ra1.w = (ra1.w * s1.w + h1.w) * tval;
        }
        float hi, lo;
        split_tf(ra0.x, hi, lo); Ah[acol + 0][arow] = hi; Al[acol + 0][arow] = lo;
        split_tf(ra0.y, hi, lo); Ah[acol + 1][arow] = hi; Al[acol + 1][arow] = lo;
        split_tf(ra0.z, hi, lo); Ah[acol + 2][arow] = hi; Al[acol + 2][arow] = lo;
        split_tf(ra0.w, hi, lo); Ah[acol + 3][arow] = hi; Al[acol + 3][arow] = lo;
        split_tf(ra1.x, hi, lo); Ah[acol + 4][arow] = hi; Al[acol + 4][arow] = lo;
        split_tf(ra1.y, hi, lo); Ah[acol + 5][arow] = hi; Al[acol + 5][arow] = lo;
        split_tf(ra1.z, hi, lo); Ah[acol + 6][arow] = hi; Al[acol + 6][arow] = lo;
        split_tf(ra1.w, hi, lo); Ah[acol + 7][arow] = hi; Al[acol + 7][arow] = lo;
        float4 h4, lo4;
        split_tf(rb0.x, h4.x, lo4.x); split_tf(rb0.y, h4.y, lo4.y);
        split_tf(rb0.z, h4.z, lo4.z); split_tf(rb0.w, h4.w, lo4.w);
        *(float4*)&Bh[brow][bcol] = h4; *(float4*)&Bl[brow][bcol] = lo4;
        split_tf(rb1.x, h4.x, lo4.x); split_tf(rb1.y, h4.y, lo4.y);
        split_tf(rb1.z, h4.z, lo4.z); split_tf(rb1.w, h4.w, lo4.w);
        *(float4*)&Bh[brow][bcol + 4] = h4; *(float4*)&Bl[brow][bcol + 4] = lo4;
        __syncthreads();
        if (k0 + 16 < K) {
            ra0 = *(const float4*)(Ap + k0 + 16);
            ra1 = *(const float4*)(Ap + k0 + 20);
            rb0 = *(const float4*)(Bp + (size_t)(k0 + 16) * N);
            rb1 = *(const float4*)(Bp + (size_t)(k0 + 16) * N + 4);
        }
#pragma unroll
        for (int kk = 0; kk < 16; kk += 8) {
            unsigned ah[2][4], al[2][4];
#pragma unroll
            for (int fm = 0; fm < 2; fm++) {
                int r = wm + fm * 16;
                ah[fm][0] = __float_as_uint(Ah[kk + l4][r + g]);
                ah[fm][1] = __float_as_uint(Ah[kk + l4][r + g + 8]);
                ah[fm][2] = __float_as_uint(Ah[kk + l4 + 4][r + g]);
                ah[fm][3] = __float_as_uint(Ah[kk + l4 + 4][r + g + 8]);
                al[fm][0] = __float_as_uint(Al[kk + l4][r + g]);
                al[fm][1] = __float_as_uint(Al[kk + l4][r + g + 8]);
                al[fm][2] = __float_as_uint(Al[kk + l4 + 4][r + g]);
                al[fm][3] = __float_as_uint(Al[kk + l4 + 4][r + g + 8]);
            }
#pragma unroll
            for (int nf = 0; nf < 8; nf++) {
                int nc = wn + nf * 8 + g;
                unsigned bh0 = __float_as_uint(Bh[kk + l4][nc]);
                unsigned bh1 = __float_as_uint(Bh[kk + l4 + 4][nc]);
                unsigned bl0 = __float_as_uint(Bl[kk + l4][nc]);
                unsigned bl1 = __float_as_uint(Bl[kk + l4 + 4][nc]);
#pragma unroll
                for (int fm = 0; fm < 2; fm++) {
                    mma_tf32(c[fm][nf], ah[fm], bh0, bh1);
                    mma_tf32(c[fm][nf], al[fm], bh0, bh1);
                    mma_tf32(c[fm][nf], ah[fm], bl0, bl1);
                }
            }
        }
        __syncthreads();
    }

#pragma unroll
    for (int fm = 0; fm < 2; fm++) {
        int r0 = m0 + wm + fm * 16 + g;
#pragma unroll
        for (int nf = 0; nf < 8; nf++) {
            int col = n0 + wn + nf * 8 + 2 * l4;
            *(float2*)&C[(size_t)r0 * N + col]       = make_float2(c[fm][nf][0], c[fm][nf][1]);
            *(float2*)&C[(size_t)(r0 + 8) * N + col] = make_float2(c[fm][nf][2], c[fm][nf][3]);
        }
    }

    int head = (n0 >> 6) + (w & 1);
    float asw0[8], asw1[8], adw0[8], adw1[8];
#pragma unroll
    for (int nf = 0; nf < 8; nf++) {
        int col = head * 64 + nf * 8 + 2 * l4;
        asw0[nf] = a_s[col]; asw1[nf] = a_s[col + 1];
        adw0[nf] = a_d[col]; adw1[nf] = a_d[col + 1];
    }
#pragma unroll
    for (int fm = 0; fm < 2; fm++) {
        float pa0 = 0.f, pa1 = 0.f, pd0 = 0.f, pd1 = 0.f;
#pragma unroll
        for (int nf = 0; nf < 8; nf++) {
            pa0 += c[fm][nf][0] * asw0[nf] + c[fm][nf][1] * asw1[nf];
            pa1 += c[fm][nf][2] * asw0[nf] + c[fm][nf][3] * asw1[nf];
            pd0 += c[fm][nf][0] * adw0[nf] + c[fm][nf][1] * adw1[nf];
            pd1 += c[fm][nf][2] * adw0[nf] + c[fm][nf][3] * adw1[nf];
        }
#pragma unroll
        for (int o = 1; o <= 2; o <<= 1) {
            pa0 += __shfl_xor_sync(~0u, pa0, o);
            pa1 += __shfl_xor_sync(~0u, pa1, o);
            pd0 += __shfl_xor_sync(~0u, pd0, o);
            pd1 += __shfl_xor_sync(~0u, pd1, o);
        }
        if (l4 == 0) {
            int r0 = m0 + wm + fm * 16 + g;
            asn[r0 * 4 + head] = pa0; asn[(r0 + 8) * 4 + head] = pa1;
            adn[r0 * 4 + head] = pd0; adn[(r0 + 8) * 4 + head] = pd1;
        }
    }
}

// ---------------- padded-CSR build ----------------
__global__ void csr_build(const int* __restrict__ src, const int* __restrict__ dst,
                          const int* __restrict__ inv, int* __restrict__ deg,
                          int* __restrict__ csr, int nE) {
    int i = blockIdx.x * blockDim.x + threadIdx.x;
    if (i >= nE) return;
    int s = src[i], d = dst[i];
    if (inv) { s = inv[s]; d = inv[d]; if (s < 0 || d < 0) return; }
    int p = atomicAdd(&deg[d], 1);
    if (p < MAXDEG) csr[(size_t)d * MAXDEG + p] = s;
}

// ---------------- fused GAT gather + BN-finalize tail (last-block pattern) ----------------
__global__ __launch_bounds__(256, 6) void gat_gather(
    const int* __restrict__ csr, const int* __restrict__ deg,
    const float* __restrict__ asn, const float* __restrict__ adn,
    const float* __restrict__ h, const float* __restrict__ bias,
    float* __restrict__ out, float* __restrict__ sums, int n, int upb,
    const float* __restrict__ gw, const float* __restrict__ be,
    const float* __restrict__ pw, float* __restrict__ scale,
    float* __restrict__ shift, float* __restrict__ w1a, float invn,
    int* __restrict__ counter) {
    __shared__ float ssum[512];
    __shared__ float4 sst[8][64];
    __shared__ int lastFlag;
    int t = threadIdx.x;
    ssum[t] = 0.f; ssum[t + 256] = 0.f;
    __syncthreads();
    int lane = t & 31, w = t >> 5;
    int half = (blockIdx.x * upb + w) & 1;
    int c = half * 128 + lane * 4;
    float4 bb = *(const float4*)&bias[c];
    float st[8];
#pragma unroll
    for (int i = 0; i < 8; i++) st[i] = 0.f;

    int base = blockIdx.x * upb;
    int end = base + upb; if (end > 2 * n) end = 2 * n;
    for (int u = base + w; u < end; u += 8) {
        int nd = u >> 1;
        float2 ad = *(const float2*)&adn[(size_t)nd * 4 + half * 2];
        int dg = deg[nd]; if (dg > 63) dg = 63;
        const int* row = csr + (size_t)nd * MAXDEG;
        int sA = (lane < dg) ? row[lane] : nd;
        int sB = (lane + 32 < dg) ? row[lane + 32] : nd;
        bool vA = (lane <= dg);
        bool vB = (lane + 32 <= dg);
        float2 aA = *(const float2*)&asn[(size_t)sA * 4 + half * 2];
        float2 aB = *(const float2*)&asn[(size_t)sB * 4 + half * 2];
        float lA0 = aA.x + ad.x, lA1 = aA.y + ad.y;
        float lB0 = aB.x + ad.x, lB1 = aB.y + ad.y;
        lA0 = lA0 > 0.f ? lA0 : 0.2f * lA0;  lB0 = lB0 > 0.f ? lB0 : 0.2f * lB0;
        lA1 = lA1 > 0.f ? lA1 : 0.2f * lA1;  lB1 = lB1 > 0.f ? lB1 : 0.2f * lB1;
        float pA0 = vA ? __expf(lA0) : 0.f, pA1 = vA ? __expf(lA1) : 0.f;
        float pB0 = vB ? __expf(lB0) : 0.f, pB1 = vB ? __expf(lB1) : 0.f;
        float d0 = pA0 + pB0, d1 = pA1 + pB1;
#pragma unroll
        for (int o = 16; o; o >>= 1) {
            d0 += __shfl_xor_sync(~0u, d0, o);
            d1 += __shfl_xor_sync(~0u, d1, o);
        }
        float r0 = 1.f / d0, r1 = 1.f / d1;
        __syncwarp();
        sst[w][lane]      = make_float4(__int_as_float(sA * FD), pA0 * r0, pA1 * r1, 0.f);
        sst[w][lane + 32] = make_float4(__int_as_float(sB * FD), pB0 * r0, pB1 * r1, 0.f);
        __syncwarp();
        float4 a0 = make_float4(0, 0, 0, 0);
        int ne = dg + 1;
#pragma unroll 4
        for (int e = 0; e < ne; e++) {
            float4 gq = sst[w][e];
            int sofs = __float_as_int(gq.x);
            float p = (lane & 16) ? gq.z : gq.y;
            float4 v = *(const float4*)(h + sofs + c);
            a0.x += p * v.x; a0.y += p * v.y; a0.z += p * v.z; a0.w += p * v.w;
        }
        float o[4];
        o[0] = a0.x + bb.x; o[1] = a0.y + bb.y;
        o[2] = a0.z + bb.z; o[3] = a0.w + bb.w;
#pragma unroll
        for (int i = 0; i < 4; i++) {
            float v = o[i];
            v = 0.5f * v * (1.0f + erff(v * 0.70710678118654752f));
            o[i] = v;
            st[i] += v; st[4 + i] += v * v;
        }
        *(float4*)(out + (size_t)nd * FD + c) = make_float4(o[0], o[1], o[2], o[3]);
    }
#pragma unroll
    for (int i = 0; i < 4; i++) {
        atomicAdd(&ssum[c + i],       st[i]);
        atomicAdd(&ssum[256 + c + i], st[4 + i]);
    }
    __syncthreads();
    atomicAdd(&sums[t],       ssum[t]);
    atomicAdd(&sums[t + 256], ssum[t + 256]);
    __threadfence();
    __syncthreads();
    if (t == 0) lastFlag = (atomicAdd(counter, 1) == (int)gridDim.x - 1) ? 1 : 0;
    __syncthreads();
    if (!lastFlag) return;

    float* red = ssum;
    float* scs = (float*)sst;
    float* shs = scs + 256;
    int f = t;
    float mean = __ldcg(&sums[f]) * invn;
    float var  = __ldcg(&sums[256 + f]) * invn - mean * mean;
    float sc = gw[f] * rsqrtf(var + 1e-5f);
    float sh = be[f] - mean * sc;
    scale[f] = sc; shift[f] = sh;
    scs[f] = sc; shs[f] = sh;
    float pwf = pw[f];
    red[f] = pwf * pwf;
    __syncthreads();
    for (int s = 128; s; s >>= 1) {
        if (f < s) red[f] += red[f + s];
        __syncthreads();
    }
    float pwn = pwf * rsqrtf(red[0]);
    w1a[f] = scs[f] * pwn;
    __syncthreads();
    red[f] = shs[f] * pwn;
    __syncthreads();
    for (int s = 128; s; s >>= 1) {
        if (f < s) red[f] += red[f + s];
        __syncthreads();
    }
    if (f == 0) w1a[256] = red[0];
}

// ---------------- pool score: dot(x, w1) + w0 ----------------
__global__ void pool_score(const float* __restrict__ x, const float* __restrict__ w1a,
                           float* __restrict__ score, int n) {
    int gw = (blockIdx.x * blockDim.x + threadIdx.x) >> 5;
    int lane = threadIdx.x & 31;
    if (gw >= n) return;
    const float* row = x + (size_t)gw * FD;
    int c0 = lane * 4, c1 = c0 + 128;
    float4 v0 = *(const float4*)(row + c0), v1 = *(const float4*)(row + c1);
    float4 p0 = *(const float4*)&w1a[c0], p1 = *(const float4*)&w1a[c1];
    float s = v0.x * p0.x + v0.y * p0.y + v0.z * p0.z + v0.w * p0.w
            + v1.x * p1.x + v1.y * p1.y + v1.z * p1.z + v1.w * p1.w;
#pragma unroll
    for (int o = 16; o; o >>= 1) s += __shfl_down_sync(~0u, s, o);
    if (lane == 0) score[gw] = s + w1a[256];
}

// ---------------- per-graph top-k via radix kth-element select (set semantics) ----------------
__global__ __launch_bounds__(512) void topk_select(
    const float* __restrict__ score, int npg, int k,
    int* __restrict__ gidx, float* __restrict__ tv, int* __restrict__ inv) {
    __shared__ int cnt, ctrG, ctrE;
    int g = blockIdx.x, t = threadIdx.x;
    const float* sg = score + (size_t)g * npg;
    int e0 = t, e1 = t + 512;
    unsigned k0 = 0, k1 = 0;
    float f0 = 0.f, f1 = 0.f;
    bool v0 = (e0 < npg), v1 = (e1 < npg);
    if (v0) {
        f0 = sg[e0];
        unsigned u = __float_as_uint(f0);
        k0 = (u & 0x80000000u) ? ~u : (u | 0x80000000u);
    }
    if (v1) {
        f1 = sg[e1];
        unsigned u = __float_as_uint(f1);
        k1 = (u & 0x80000000u) ? ~u : (u | 0x80000000u);
    }
    unsigned prefix = 0;
    for (int bit = 31; bit >= 0; bit--) {
        unsigned cand = prefix | (1u << bit);
        if (t == 0) cnt = 0;
        __syncthreads();
        int c = (int)(v0 && k0 >= cand) + (int)(v1 && k1 >= cand);
#pragma unroll
        for (int o = 16; o; o >>= 1) c += __shfl_down_sync(~0u, c, o);
        if ((t & 31) == 0 && c) atomicAdd(&cnt, c);
        __syncthreads();
        if (cnt >= k) prefix = cand;
        __syncthreads();
    }
    // count strictly greater than kth value
    if (t == 0) cnt = 0;
    __syncthreads();
    {
        int c = (int)(v0 && k0 > prefix) + (int)(v1 && k1 > prefix);
#pragma unroll
        for (int o = 16; o; o >>= 1) c += __shfl_down_sync(~0u, c, o);
        if ((t & 31) == 0 && c) atomicAdd(&cnt, c);
    }
    if (t == 0) { ctrG = 0; ctrE = 0; }
    __syncthreads();
    int m = cnt, r = k - m;
#pragma unroll
    for (int q = 0; q < 2; q++) {
        bool vv = q ? v1 : v0;
        if (!vv) continue;
        int e = q ? e1 : e0;
        unsigned kk = q ? k1 : k0;
        float fv = q ? f1 : f0;
        int pos = -1;
        if (kk > prefix) pos = atomicAdd(&ctrG, 1);
        else if (kk == prefix) {
            int j = atomicAdd(&ctrE, 1);
            if (j < r) pos = m + j;
        }
        if (pos >= 0) {
            int gp = g * k + pos;
            int node = g * npg + e;
            gidx[gp] = node;
            tv[gp] = tanhf(fv);
            if (inv) inv[node] = gp;
        }
    }
}

// ---------------- readout stage 1: per (graph, chunk) partial max/sum ----------------
__global__ void readout_s1(const float* __restrict__ x, const float* __restrict__ sc,
                           const float* __restrict__ sh, const int* __restrict__ gidx,
                           const float* __restrict__ tv, int k, float* __restrict__ partial) {
    int g = blockIdx.x, c = blockIdx.y, f = threadIdx.x;
    int chunk = k / 8;
    int j0 = c * chunk;
    float mx = -1e30f, sm = 0.f;
    float scf = sc[f], shf = sh[f];
    for (int j = j0; j < j0 + chunk; j++) {
        int node = gidx[g * k + j];
        float v = (x[(size_t)node * FD + f] * scf + shf) * tv[g * k + j];
        mx = fmaxf(mx, v);
        sm += v;
    }
    partial[((size_t)(g * 8 + c)) * 512 + f] = mx;
    partial[((size_t)(g * 8 + c)) * 512 + 256 + f] = sm;
}

// ---------------- final: reduce both partials + linear ----------------
__global__ void final_linear(const float* __restrict__ part, const float* __restrict__ part2,
                             const float* __restrict__ Wl, const float* __restrict__ bl,
                             float* __restrict__ out) {
    __shared__ float xr[512];
    int b = blockIdx.x, t = threadIdx.x;
    float mx1 = -1e30f, sm1 = 0.f, mx2 = -1e30f, sm2 = 0.f;
#pragma unroll
    for (int c = 0; c < 8; c++) {
        size_t o1 = ((size_t)(b * 8 + c)) * 512;
        mx1 = fmaxf(mx1, part[o1 + t]);  sm1 += part[o1 + 256 + t];
        mx2 = fmaxf(mx2, part2[o1 + t]); sm2 += part2[o1 + 256 + t];
    }
    xr[t]       = mx1 + mx2;
    xr[t + 256] = sm1 / (float)KP1 + sm2 / (float)KP2;
    __syncthreads();
    float acc = bl[t];
    const float* w = Wl + (size_t)t * 512;
    for (int kk = 0; kk < 512; kk++) acc += xr[kk] * w[kk];
    out[(size_t)b * 256 + t] = acc;
}

// ---------------- host launcher ----------------
extern "C" void kernel_launch(void* const* d_in, const int* in_sizes, int n_in,
                              void* d_out, int out_size) {
    const float* x    = (const float*)d_in[0];
    const int*   ei   = (const int*)d_in[1];
    const int*   src  = ei;
    const int*   dst  = ei + ED;
    const float* W1   = (const float*)d_in[3];
    const float* as1  = (const float*)d_in[4];
    const float* ad1  = (const float*)d_in[5];
    const float* b1   = (const float*)d_in[6];
    const float* g1   = (const float*)d_in[7];
    const float* be1  = (const float*)d_in[8];
    const float* pw1  = (const float*)d_in[9];
    const float* W2   = (const float*)d_in[10];
    const float* as2  = (const float*)d_in[11];
    const float* ad2  = (const float*)d_in[12];
    const float* b2   = (const float*)d_in[13];
    const float* g2   = (const float*)d_in[14];
    const float* be2  = (const float*)d_in[15];
    const float* pw2  = (const float*)d_in[16];
    const float* Wl   = (const float*)d_in[17];
    const float* bl   = (const float*)d_in[18];
    float* out = (float*)d_out;

    float* fb = nullptr;
    int*   ib = nullptr;
    cudaGetSymbolAddress((void**)&fb, g_f);
    cudaGetSymbolAddress((void**)&ib, g_i);

    float* h1    = fb + O_H1;
    float* out1  = fb + O_OUT1;
    float* asn1  = fb + O_ASN1;
    float* adn1  = fb + O_ADN1;
    float* bns1  = fb + O_BNS1;
    float* bns2  = fb + O_BNS2;
    float* sc1   = fb + O_SC1;
    float* sh1   = fb + O_SH1;
    float* w1a   = fb + O_W1A;
    float* score1= fb + O_SCORE1;
    float* tanh1 = fb + O_TANH1;
    float* part  = fb + O_PART;
    float* part2 = fb + O_PART2;
    float* h2    = fb + O_H2;
    float* out2  = fb + O_OUT2;
    float* asn2  = fb + O_ASN2;
    float* adn2  = fb + O_ADN2;
    float* sc2   = fb + O_SC2;
    float* sh2   = fb + O_SH2;
    float* w2a   = fb + O_W2A;
    float* score2= fb + O_SCORE2;
    float* tanh2 = fb + O_TANH2;
    int* gidx1 = ib + IO_GIDX1;
    int* inv1  = ib + IO_INV1;
    int* gidx2 = ib + IO_GIDX2;
    int* csr1  = ib + IO_CSR1;
    int* csr2  = ib + IO_CSR2;
    int* deg1  = ib + IO_DEG1;
    int* deg2  = ib + IO_DEG2;
    int* cnt1  = ib + IO_CNT;
    int* cnt2  = ib + IO_CNT + 1;

    static cudaStream_t s2 = nullptr;
    static cudaEvent_t ev0, ev1, ev2, ev3, ev5;
    if (!s2) {
        cudaStreamCreateWithFlags(&s2, cudaStreamNonBlocking);
        cudaEventCreateWithFlags(&ev0, cudaEventDisableTiming);
        cudaEventCreateWithFlags(&ev1, cudaEventDisableTiming);
        cudaEventCreateWithFlags(&ev2, cudaEventDisableTiming);
        cudaEventCreateWithFlags(&ev3, cudaEventDisableTiming);
        cudaEventCreateWithFlags(&ev5, cudaEventDisableTiming);
    }

    // fork: side stream does memsets + csr_build1 while main does sgemm1
    cudaEventRecord(ev0, 0);
    cudaStreamWaitEvent(s2, ev0, 0);
    cudaMemsetAsync(bns1, 0, 1024 * sizeof(float), s2);                    // bns1|bns2
    cudaMemsetAsync(deg1, 0, (size_t)(NN + N2 + 8) * sizeof(int), s2);     // deg1|deg2|cnt
    cudaMemsetAsync(inv1, 0xFF, (size_t)NN * sizeof(int), s2);
    csr_build<<<(ED + 255) / 256, 256, 0, s2>>>(src, dst, nullptr, deg1, csr1, ED);
    cudaEventRecord(ev1, s2);

    // ---- layer 1 (main stream) ----
    sgemm_tf32_attn<<<dim3(FD / 128, NN / 128), 256>>>(x, W1, h1, as1, ad1, asn1, adn1,
                                                       NN, FD, INDIM, nullptr, nullptr, nullptr, nullptr);
    cudaStreamWaitEvent(0, ev1, 0);
    gat_gather<<<2048, 256>>>(csr1, deg1, asn1, adn1, h1, b1, out1, bns1, NN, (2 * NN) / 2048,
                              g1, be1, pw1, sc1, sh1, w1a, 1.0f / NN, cnt1);
    pool_score<<<NN / 8, 256>>>(out1, w1a, score1, NN);
    topk_select<<<BT, 512>>>(score1, NPG, KP1, gidx1, tanh1, inv1);
    cudaEventRecord(ev2, 0);

    // side stream: csr_build2 + layer-1 readout (both need only topk1 results)
    cudaStreamWaitEvent(s2, ev2, 0);
    csr_build<<<(ED + 255) / 256, 256, 0, s2>>>(src, dst, inv1, deg2, csr2, ED);
    cudaEventRecord(ev3, s2);
    readout_s1<<<dim3(BT, 8), 256, 0, s2>>>(out1, sc1, sh1, gidx1, tanh1, KP1, part);
    cudaEventRecord(ev5, s2);

    // ---- layer 2 (main stream): sgemm reads pooled rows via gidx with BN+tanh inline ----
    sgemm_tf32_attn<<<dim3(FD / 128, N2 / 128), 256>>>(out1, W2, h2, as2, ad2, asn2, adn2,
                                                       N2, FD, FD, gidx1, sc1, sh1, tanh1);
    cudaStreamWaitEvent(0, ev3, 0);
    gat_gather<<<1024, 256>>>(csr2, deg2, asn2, adn2, h2, b2, out2, bns2, N2, (2 * N2) / 1024,
                              g2, be2, pw2, sc2, sh2, w2a, 1.0f / N2, cnt2);
    pool_score<<<N2 / 8, 256>>>(out2, w2a, score2, N2);
    topk_select<<<BT, 512>>>(score2, KP1, KP2, gidx2, tanh2, nullptr);
    readout_s1<<<dim3(BT, 8), 256>>>(out2, sc2, sh2, gidx2, tanh2, KP2, part2);

    // ---- final (join side stream) ----
    cudaStreamWaitEvent(0, ev5, 0);
    final_linear<<<BT, 256>>>(part, part2, Wl, bl, out);
}

// round 13
// speedup vs baseline: 1.6707x; 1.0331x over previous
#include <cuda_runtime.h>
#include <math.h>

// ---------------- problem constants ----------------
constexpr int NN   = 32768;    // total nodes layer1
constexpr int ED   = 262144;   // edges
constexpr int FD   = 256;      // feature dim (4 heads x 64)
constexpr int BT   = 32;       // graphs
constexpr int NPG  = 1024;
constexpr int KP1  = 512;
constexpr int KP2  = 256;
constexpr int N2   = BT * KP1; // 16384 pooled nodes after pool1
constexpr int INDIM = 128;
constexpr int MAXDEG = 64;     // padded CSR width

// ---------------- scratch layout (floats) ----------------
constexpr size_t O_H1    = 0;
constexpr size_t O_OUT1  = O_H1   + (size_t)NN * FD;
constexpr size_t O_ASN1  = O_OUT1 + (size_t)NN * FD;
constexpr size_t O_ADN1  = O_ASN1 + (size_t)NN * 4;
constexpr size_t O_BNS1  = O_ADN1 + (size_t)NN * 4;   // 512
constexpr size_t O_BNS2  = O_BNS1 + 512;              // 512 (adjacent -> one memset)
constexpr size_t O_SC1   = O_BNS2 + 512;
constexpr size_t O_SH1   = O_SC1  + 256;
constexpr size_t O_W1A   = O_SH1  + 256;   // 256 + 1
constexpr size_t O_SCORE1= O_W1A  + 260;
constexpr size_t O_TANH1 = O_SCORE1 + NN;
constexpr size_t O_PART  = O_TANH1  + N2;
constexpr size_t O_PART2 = O_PART   + (size_t)BT * 8 * 512;
constexpr size_t O_H2    = O_PART2  + (size_t)BT * 8 * 512;
constexpr size_t O_OUT2  = O_H2     + (size_t)N2 * FD;
constexpr size_t O_ASN2  = O_OUT2   + (size_t)N2 * FD;
constexpr size_t O_ADN2  = O_ASN2   + (size_t)N2 * 4;
constexpr size_t O_SC2   = O_ADN2   + (size_t)N2 * 4;
constexpr size_t O_SH2   = O_SC2    + 256;
constexpr size_t O_W2A   = O_SH2    + 256;
constexpr size_t O_SCORE2= O_W2A    + 260;
constexpr size_t O_TANH2 = O_SCORE2 + N2;
constexpr size_t F_TOTAL = O_TANH2  + (size_t)BT * KP2;

__device__ float g_f[F_TOTAL];

constexpr size_t IO_GIDX1 = 0;
constexpr size_t IO_INV1  = IO_GIDX1 + N2;
constexpr size_t IO_GIDX2 = IO_INV1  + NN;
constexpr size_t IO_CSR1  = IO_GIDX2 + (size_t)BT * KP2;
constexpr size_t IO_CSR2  = IO_CSR1  + (size_t)NN * MAXDEG;
constexpr size_t IO_DEG1  = IO_CSR2  + (size_t)N2 * MAXDEG;  // deg1|deg2|cnt adjacent
constexpr size_t IO_DEG2  = IO_DEG1  + NN;
constexpr size_t IO_CNT   = IO_DEG2  + N2;
constexpr size_t I_TOTAL  = IO_CNT   + 8;

__device__ int g_i[I_TOTAL];

// ---------------- tf32 helpers ----------------
__device__ __forceinline__ unsigned f2tf(float x) {
    unsigned r;
    asm("cvt.rna.tf32.f32 %0, %1;" : "=r"(r) : "f"(x));
    return r;
}
__device__ __forceinline__ void split_tf(float x, float& hi, float& lo) {
    unsigned hb = f2tf(x);
    hi = __uint_as_float(hb);
    lo = __uint_as_float(f2tf(x - hi));
}
__device__ __forceinline__ void mma_tf32(float c[4], const unsigned a[4],
                                         unsigned b0, unsigned b1) {
    asm volatile(
        "mma.sync.aligned.m16n8k8.row.col.f32.tf32.tf32.f32 "
        "{%0,%1,%2,%3}, {%4,%5,%6,%7}, {%8,%9}, {%0,%1,%2,%3};"
        : "+f"(c[0]), "+f"(c[1]), "+f"(c[2]), "+f"(c[3])
        : "r"(a[0]), "r"(a[1]), "r"(a[2]), "r"(a[3]), "r"(b0), "r"(b1));
}

// ---------------- tf32 GEMM (3xTF32) + fused attention epilogue + optional A-gather ----------------
__global__ __launch_bounds__(256) void sgemm_tf32_attn(
    const float* __restrict__ A, const float* __restrict__ B, float* __restrict__ C,
    const float* __restrict__ a_s, const float* __restrict__ a_d,
    float* __restrict__ asn, float* __restrict__ adn, int M, int N, int K,
    const int* __restrict__ gidx_a, const float* __restrict__ asc,
    const float* __restrict__ ash, const float* __restrict__ atv) {
    __shared__ float Ah[16][136], Al[16][136];
    __shared__ float Bh[16][136], Bl[16][136];
    int tid = threadIdx.x, lane = tid & 31, w = tid >> 5;
    int wm = (w >> 1) * 32, wn = (w & 1) * 64;
    int g = lane >> 2, l4 = lane & 3;
    int m0 = blockIdx.y * 128, n0 = blockIdx.x * 128;

    float c[2][8][4];
#pragma unroll
    for (int fm = 0; fm < 2; fm++)
#pragma unroll
        for (int nf = 0; nf < 8; nf++)
#pragma unroll
            for (int i = 0; i < 4; i++) c[fm][nf][i] = 0.f;

    int arow = tid & 127, acol = (tid >> 7) * 8;
    int brow = tid >> 4, bcol = (tid & 15) * 8;
    int srow = m0 + arow;
    float tval = 1.f;
    if (gidx_a) { tval = atv[srow]; srow = gidx_a[srow]; }
    const float* Ap = A + (size_t)srow * K + acol;
    const float* Bp = B + (size_t)brow * N + n0 + bcol;

    float4 ra0 = *(const float4*)(Ap);
    float4 ra1 = *(const float4*)(Ap + 4);
    float4 rb0 = *(const float4*)(Bp);
    float4 rb1 = *(const float4*)(Bp + 4);

    for (int k0 = 0; k0 < K; k0 += 16) {
        if (gidx_a) {   // apply BN+tanh to this tile's A columns
            float4 s0 = *(const float4*)&asc[k0 + acol];
            float4 s1 = *(const float4*)&asc[k0 + acol + 4];
            float4 h0 = *(const float4*)&ash[k0 + acol];
            float4 h1 = *(const float4*)&ash[k0 + acol + 4];
            ra0.x = (ra0.x * s0.x + h0.x) * tval; ra0.y = (ra0.y * s0.y + h0.y) * tval;
            ra0.z = (ra0.z * s0.z + h0.z) * tval; ra0.w = (ra0.w * s0.w + h0.w) * tval;
            ra1.x = (ra1.x * s1.x + h1.x) * tval; ra1.y = (ra1.y * s1.y + h1.y) * tval;
            ra1.z = (ra1.z * s1.z + h1.z) * tval; ra1.w = (ra1.w * s1.w + h1.w) * tval;
        }
        float hi, lo;
        split_tf(ra0.x, hi, lo); Ah[acol + 0][arow] = hi; Al[acol + 0][arow] = lo;
        split_tf(ra0.y, hi, lo); Ah[acol + 1][arow] = hi; Al[acol + 1][arow] = lo;
        split_tf(ra0.z, hi, lo); Ah[acol + 2][arow] = hi; Al[acol + 2][arow] = lo;
        split_tf(ra0.w, hi, lo); Ah[acol + 3][arow] = hi; Al[acol + 3][arow] = lo;
        split_tf(ra1.x, hi, lo); Ah[acol + 4][arow] = hi; Al[acol + 4][arow] = lo;
        split_tf(ra1.y, hi, lo); Ah[acol + 5][arow] = hi; Al[acol + 5][arow] = lo;
        split_tf(ra1.z, hi, lo); Ah[acol + 6][arow] = hi; Al[acol + 6][arow] = lo;
        split_tf(ra1.w, hi, lo); Ah[acol + 7][arow] = hi; Al[acol + 7][arow] = lo;
        float4 h4, lo4;
        split_tf(rb0.x, h4.x, lo4.x); split_tf(rb0.y, h4.y, lo4.y);
        split_tf(rb0.z, h4.z, lo4.z); split_tf(rb0.w, h4.w, lo4.w);
        *(float4*)&Bh[brow][bcol] = h4; *(float4*)&Bl[brow][bcol] = lo4;
        split_tf(rb1.x, h4.x, lo4.x); split_tf(rb1.y, h4.y, lo4.y);
        split_tf(rb1.z, h4.z, lo4.z); split_tf(rb1.w, h4.w, lo4.w);
        *(float4*)&Bh[brow][bcol + 4] = h4; *(float4*)&Bl[brow][bcol + 4] = lo4;
        __syncthreads();
        if (k0 + 16 < K) {
            ra0 = *(const float4*)(Ap + k0 + 16);
            ra1 = *(const float4*)(Ap + k0 + 20);
            rb0 = *(const float4*)(Bp + (size_t)(k0 + 16) * N);
            rb1 = *(const float4*)(Bp + (size_t)(k0 + 16) * N + 4);
        }
#pragma unroll
        for (int kk = 0; kk < 16; kk += 8) {
            unsigned ah[2][4], al[2][4];
#pragma unroll
            for (int fm = 0; fm < 2; fm++) {
                int r = wm + fm * 16;
                ah[fm][0] = __float_as_uint(Ah[kk + l4][r + g]);
                ah[fm][1] = __float_as_uint(Ah[kk + l4][r + g + 8]);
                ah[fm][2] = __float_as_uint(Ah[kk + l4 + 4][r + g]);
                ah[fm][3] = __float_as_uint(Ah[kk + l4 + 4][r + g + 8]);
                al[fm][0] = __float_as_uint(Al[kk + l4][r + g]);
                al[fm][1] = __float_as_uint(Al[kk + l4][r + g + 8]);
                al[fm][2] = __float_as_uint(Al[kk + l4 + 4][r + g]);
                al[fm][3] = __float_as_uint(Al[kk + l4 + 4][r + g + 8]);
            }
#pragma unroll
            for (int nf = 0; nf < 8; nf++) {
                int nc = wn + nf * 8 + g;
                unsigned bh0 = __float_as_uint(Bh[kk + l4][nc]);
                unsigned bh1 = __float_as_uint(Bh[kk + l4 + 4][nc]);
                unsigned bl0 = __float_as_uint(Bl[kk + l4][nc]);
                unsigned bl1 = __float_as_uint(Bl[kk + l4 + 4][nc]);
#pragma unroll
                for (int fm = 0; fm < 2; fm++) {
                    mma_tf32(c[fm][nf], ah[fm], bh0, bh1);
                    mma_tf32(c[fm][nf], al[fm], bh0, bh1);
                    mma_tf32(c[fm][nf], ah[fm], bl0, bl1);
                }
            }
        }
        __syncthreads();
    }

#pragma unroll
    for (int fm = 0; fm < 2; fm++) {
        int r0 = m0 + wm + fm * 16 + g;
#pragma unroll
        for (int nf = 0; nf < 8; nf++) {
            int col = n0 + wn + nf * 8 + 2 * l4;
            *(float2*)&C[(size_t)r0 * N + col]       = make_float2(c[fm][nf][0], c[fm][nf][1]);
            *(float2*)&C[(size_t)(r0 + 8) * N + col] = make_float2(c[fm][nf][2], c[fm][nf][3]);
        }
    }

    int head = (n0 >> 6) + (w & 1);
    float asw0[8], asw1[8], adw0[8], adw1[8];
#pragma unroll
    for (int nf = 0; nf < 8; nf++) {
        int col = head * 64 + nf * 8 + 2 * l4;
        asw0[nf] = a_s[col]; asw1[nf] = a_s[col + 1];
        adw0[nf] = a_d[col]; adw1[nf] = a_d[col + 1];
    }
#pragma unroll
    for (int fm = 0; fm < 2; fm++) {
        float pa0 = 0.f, pa1 = 0.f, pd0 = 0.f, pd1 = 0.f;
#pragma unroll
        for (int nf = 0; nf < 8; nf++) {
            pa0 += c[fm][nf][0] * asw0[nf] + c[fm][nf][1] * asw1[nf];
            pa1 += c[fm][nf][2] * asw0[nf] + c[fm][nf][3] * asw1[nf];
            pd0 += c[fm][nf][0] * adw0[nf] + c[fm][nf][1] * adw1[nf];
            pd1 += c[fm][nf][2] * adw0[nf] + c[fm][nf][3] * adw1[nf];
        }
#pragma unroll
        for (int o = 1; o <= 2; o <<= 1) {
            pa0 += __shfl_xor_sync(~0u, pa0, o);
            pa1 += __shfl_xor_sync(~0u, pa1, o);
            pd0 += __shfl_xor_sync(~0u, pd0, o);
            pd1 += __shfl_xor_sync(~0u, pd1, o);
        }
        if (l4 == 0) {
            int r0 = m0 + wm + fm * 16 + g;
            asn[r0 * 4 + head] = pa0; asn[(r0 + 8) * 4 + head] = pa1;
            adn[r0 * 4 + head] = pd0; adn[(r0 + 8) * 4 + head] = pd1;
        }
    }
}

// ---------------- padded-CSR build ----------------
__global__ void csr_build(const int* __restrict__ src, const int* __restrict__ dst,
                          const int* __restrict__ inv, int* __restrict__ deg,
                          int* __restrict__ csr, int nE) {
    int i = blockIdx.x * blockDim.x + threadIdx.x;
    if (i >= nE) return;
    int s = src[i], d = dst[i];
    if (inv) { s = inv[s]; d = inv[d]; if (s < 0 || d < 0) return; }
    int p = atomicAdd(&deg[d], 1);
    if (p < MAXDEG) csr[(size_t)d * MAXDEG + p] = s;
}

// ---------------- fused GAT gather + BN-finalize tail (last-block pattern) ----------------
__global__ __launch_bounds__(256, 6) void gat_gather(
    const int* __restrict__ csr, const int* __restrict__ deg,
    const float* __restrict__ asn, const float* __restrict__ adn,
    const float* __restrict__ h, const float* __restrict__ bias,
    float* __restrict__ out, float* __restrict__ sums, int n, int upb,
    const float* __restrict__ gw, const float* __restrict__ be,
    const float* __restrict__ pw, float* __restrict__ scale,
    float* __restrict__ shift, float* __restrict__ w1a, float invn,
    int* __restrict__ counter) {
    __shared__ float ssum[512];
    __shared__ float4 sst[8][64];
    __shared__ int lastFlag;
    int t = threadIdx.x;
    ssum[t] = 0.f; ssum[t + 256] = 0.f;
    __syncthreads();
    int lane = t & 31, w = t >> 5;
    int half = (blockIdx.x * upb + w) & 1;
    int c = half * 128 + lane * 4;
    float4 bb = *(const float4*)&bias[c];
    float st[8];
#pragma unroll
    for (int i = 0; i < 8; i++) st[i] = 0.f;

    int base = blockIdx.x * upb;
    int end = base + upb; if (end > 2 * n) end = 2 * n;
    for (int u = base + w; u < end; u += 8) {
        int nd = u >> 1;
        float2 ad = *(const float2*)&adn[(size_t)nd * 4 + half * 2];
        int dg = deg[nd]; if (dg > 63) dg = 63;
        const int* row = csr + (size_t)nd * MAXDEG;
        int sA = (lane < dg) ? row[lane] : nd;
        int sB = (lane + 32 < dg) ? row[lane + 32] : nd;
        bool vA = (lane <= dg);
        bool vB = (lane + 32 <= dg);
        float2 aA = *(const float2*)&asn[(size_t)sA * 4 + half * 2];
        float2 aB = *(const float2*)&asn[(size_t)sB * 4 + half * 2];
        float lA0 = aA.x + ad.x, lA1 = aA.y + ad.y;
        float lB0 = aB.x + ad.x, lB1 = aB.y + ad.y;
        lA0 = lA0 > 0.f ? lA0 : 0.2f * lA0;  lB0 = lB0 > 0.f ? lB0 : 0.2f * lB0;
        lA1 = lA1 > 0.f ? lA1 : 0.2f * lA1;  lB1 = lB1 > 0.f ? lB1 : 0.2f * lB1;
        float pA0 = vA ? __expf(lA0) : 0.f, pA1 = vA ? __expf(lA1) : 0.f;
        float pB0 = vB ? __expf(lB0) : 0.f, pB1 = vB ? __expf(lB1) : 0.f;
        float d0 = pA0 + pB0, d1 = pA1 + pB1;
#pragma unroll
        for (int o = 16; o; o >>= 1) {
            d0 += __shfl_xor_sync(~0u, d0, o);
            d1 += __shfl_xor_sync(~0u, d1, o);
        }
        float r0 = 1.f / d0, r1 = 1.f / d1;
        __syncwarp();
        sst[w][lane]      = make_float4(__int_as_float(sA * FD), pA0 * r0, pA1 * r1, 0.f);
        sst[w][lane + 32] = make_float4(__int_as_float(sB * FD), pB0 * r0, pB1 * r1, 0.f);
        __syncwarp();
        float4 a0 = make_float4(0, 0, 0, 0);
        int ne = dg + 1;
#pragma unroll 4
        for (int e = 0; e < ne; e++) {
            float4 gq = sst[w][e];
            int sofs = __float_as_int(gq.x);
            float p = (lane & 16) ? gq.z : gq.y;
            float4 v = *(const float4*)(h + sofs + c);
            a0.x += p * v.x; a0.y += p * v.y; a0.z += p * v.z; a0.w += p * v.w;
        }
        float o[4];
        o[0] = a0.x + bb.x; o[1] = a0.y + bb.y;
        o[2] = a0.z + bb.z; o[3] = a0.w + bb.w;
#pragma unroll
        for (int i = 0; i < 4; i++) {
            float v = o[i];
            v = 0.5f * v * (1.0f + erff(v * 0.70710678118654752f));
            o[i] = v;
            st[i] += v; st[4 + i] += v * v;
        }
        *(float4*)(out + (size_t)nd * FD + c) = make_float4(o[0], o[1], o[2], o[3]);
    }
#pragma unroll
    for (int i = 0; i < 4; i++) {
        atomicAdd(&ssum[c + i],       st[i]);
        atomicAdd(&ssum[256 + c + i], st[4 + i]);
    }
    __syncthreads();
    atomicAdd(&sums[t],       ssum[t]);
    atomicAdd(&sums[t + 256], ssum[t + 256]);
    __threadfence();
    __syncthreads();
    if (t == 0) lastFlag = (atomicAdd(counter, 1) == (int)gridDim.x - 1) ? 1 : 0;
    __syncthreads();
    if (!lastFlag) return;

    float* red = ssum;
    float* scs = (float*)sst;
    float* shs = scs + 256;
    int f = t;
    float mean = __ldcg(&sums[f]) * invn;
    float var  = __ldcg(&sums[256 + f]) * invn - mean * mean;
    float sc = gw[f] * rsqrtf(var + 1e-5f);
    float sh = be[f] - mean * sc;
    scale[f] = sc; shift[f] = sh;
    scs[f] = sc; shs[f] = sh;
    float pwf = pw[f];
    red[f] = pwf * pwf;
    __syncthreads();
    for (int s = 128; s; s >>= 1) {
        if (f < s) red[f] += red[f + s];
        __syncthreads();
    }
    float pwn = pwf * rsqrtf(red[0]);
    w1a[f] = scs[f] * pwn;
    __syncthreads();
    red[f] = shs[f] * pwn;
    __syncthreads();
    for (int s = 128; s; s >>= 1) {
        if (f < s) red[f] += red[f + s];
        __syncthreads();
    }
    if (f == 0) w1a[256] = red[0];
}

// ---------------- pool score: dot(x, w1) + w0, 4 nodes per warp ----------------
__global__ void pool_score(const float* __restrict__ x, const float* __restrict__ w1a,
                           float* __restrict__ score, int n) {
    int wbase = ((blockIdx.x * blockDim.x + threadIdx.x) >> 5) * 4;
    int lane = threadIdx.x & 31;
    if (wbase >= n) return;
    int c0 = lane * 4, c1 = c0 + 128;
    float4 p0 = *(const float4*)&w1a[c0], p1 = *(const float4*)&w1a[c1];
    float w0 = w1a[256];
    float s[4];
#pragma unroll
    for (int i = 0; i < 4; i++) {
        const float* row = x + (size_t)(wbase + i) * FD;
        float4 v0 = *(const float4*)(row + c0), v1 = *(const float4*)(row + c1);
        s[i] = v0.x * p0.x + v0.y * p0.y + v0.z * p0.z + v0.w * p0.w
             + v1.x * p1.x + v1.y * p1.y + v1.z * p1.z + v1.w * p1.w;
    }
#pragma unroll
    for (int o = 16; o; o >>= 1) {
        s[0] += __shfl_down_sync(~0u, s[0], o);
        s[1] += __shfl_down_sync(~0u, s[1], o);
        s[2] += __shfl_down_sync(~0u, s[2], o);
        s[3] += __shfl_down_sync(~0u, s[3], o);
    }
    if (lane == 0) {
#pragma unroll
        for (int i = 0; i < 4; i++) score[wbase + i] = s[i] + w0;
    }
}

// ---------------- per-graph top-k: 4-pass 8-bit histogram radix select ----------------
__global__ __launch_bounds__(512) void topk_select(
    const float* __restrict__ score, int npg, int k,
    int* __restrict__ gidx, float* __restrict__ tv, int* __restrict__ inv) {
    __shared__ int hist[256];
    __shared__ int sred[16];
    __shared__ unsigned s_prefix;
    __shared__ int s_kneed, s_m;
    __shared__ int ctrG, ctrE;
    int g = blockIdx.x, t = threadIdx.x;
    int lane = t & 31, wid = t >> 5;
    const float* sg = score + (size_t)g * npg;
    int e0 = t, e1 = t + 512;
    bool v0 = (e0 < npg), v1 = (e1 < npg);
    float f0 = v0 ? sg[e0] : 0.f, f1 = v1 ? sg[e1] : 0.f;
    unsigned k0 = 0, k1 = 0;
    if (v0) { unsigned u = __float_as_uint(f0); k0 = (u & 0x80000000u) ? ~u : (u | 0x80000000u); }
    if (v1) { unsigned u = __float_as_uint(f1); k1 = (u & 0x80000000u) ? ~u : (u | 0x80000000u); }
    if (t == 0) { s_prefix = 0; s_kneed = k; }

    for (int shift = 24; shift >= 0; shift -= 8) {
        for (int i = t; i < 256; i += 512) hist[i] = 0;
        __syncthreads();
        unsigned pfx = s_prefix;
        int kneed = s_kneed;
        unsigned mask_hi = (shift == 24) ? 0u : (0xFFFFFFFFu << (shift + 8));
        if (v0 && ((k0 ^ pfx) & mask_hi) == 0) atomicAdd(&hist[(k0 >> shift) & 255], 1);
        if (v1 && ((k1 ^ pfx) & mask_hi) == 0) atomicAdd(&hist[(k1 >> shift) & 255], 1);
        __syncthreads();
        if (wid == 0) {
            int bbase = 255 - lane * 8;
            int cb[8];
            int s = 0;
#pragma unroll
            for (int j = 0; j < 8; j++) { cb[j] = hist[bbase - j]; s += cb[j]; }
            // exclusive prefix (descending bin order) across lanes
            int incl = s;
            for (int o = 1; o < 32; o <<= 1) {
                int v = __shfl_up_sync(~0u, incl, o);
                if (lane >= o) incl += v;
            }
            int excl = incl - s;
            bool has = (excl < kneed) && (kneed <= excl + s);
            if (has) {
                int cum = excl, found = -1, rem = 0;
#pragma unroll
                for (int j = 0; j < 8; j++) {
                    if (found < 0 && cum + cb[j] >= kneed) { found = bbase - j; rem = kneed - cum; }
                    cum += cb[j];
                }
                s_prefix = pfx | ((unsigned)found << shift);
                s_kneed = rem;
            }
        }
        __syncthreads();
    }
    unsigned kth = s_prefix;

    // count strictly greater (ballot-based)
    {
        int cc = __popc(__ballot_sync(~0u, v0 && k0 > kth))
               + __popc(__ballot_sync(~0u, v1 && k1 > kth));
        if (lane == 0) sred[wid] = cc;
    }
    __syncthreads();
    if (t == 0) {
        int mm = 0;
        for (int i = 0; i < 16; i++) mm += sred[i];
        s_m = mm; ctrG = 0; ctrE = 0;
    }
    __syncthreads();
    int m = s_m, r = k - m;

    // compaction: warp-aggregated positions (arbitrary order within the set)
#pragma unroll
    for (int q = 0; q < 2; q++) {
        bool vv = q ? v1 : v0;
        int e = q ? e1 : e0;
        unsigned kk = q ? k1 : k0;
        float fv = q ? f1 : f0;
        bool selG = vv && kk > kth;
        bool selE = vv && kk == kth;
        unsigned mG = __ballot_sync(~0u, selG);
        unsigned mE = __ballot_sync(~0u, selE);
        int baseG = 0, baseE = 0;
        if (lane == 0) {
            if (mG) baseG = atomicAdd(&ctrG, __popc(mG));
            if (mE) baseE = atomicAdd(&ctrE, __popc(mE));
        }
        baseG = __shfl_sync(~0u, baseG, 0);
        baseE = __shfl_sync(~0u, baseE, 0);
        unsigned lmask = (1u << lane) - 1u;
        int pos = -1;
        if (selG) pos = baseG + __popc(mG & lmask);
        else if (selE) {
            int j = baseE + __popc(mE & lmask);
            if (j < r) pos = m + j;
        }
        if (pos >= 0) {
            int gp = g * k + pos;
            int node = g * npg + e;
            gidx[gp] = node;
            tv[gp] = tanhf(fv);
            if (inv) inv[node] = gp;
        }
    }
}

// ---------------- readout stage 1: per (graph, chunk) partial max/sum ----------------
__global__ void readout_s1(const float* __restrict__ x, const float* __restrict__ sc,
                           const float* __restrict__ sh, const int* __restrict__ gidx,
                           const float* __restrict__ tv, int k, float* __restrict__ partial) {
    int g = blockIdx.x, c = blockIdx.y, f = threadIdx.x;
    int chunk = k / 8;
    int j0 = c * chunk;
    float mx = -1e30f, sm = 0.f;
    float scf = sc[f], shf = sh[f];
    for (int j = j0; j < j0 + chunk; j++) {
        int node = gidx[g * k + j];
        float v = (x[(size_t)node * FD + f] * scf + shf) * tv[g * k + j];
        mx = fmaxf(mx, v);
        sm += v;
    }
    partial[((size_t)(g * 8 + c)) * 512 + f] = mx;
    partial[((size_t)(g * 8 + c)) * 512 + 256 + f] = sm;
}

// ---------------- final: reduce both partials + linear ----------------
__global__ void final_linear(const float* __restrict__ part, const float* __restrict__ part2,
                             const float* __restrict__ Wl, const float* __restrict__ bl,
                             float* __restrict__ out) {
    __shared__ float xr[512];
    int b = blockIdx.x, t = threadIdx.x;
    float mx1 = -1e30f, sm1 = 0.f, mx2 = -1e30f, sm2 = 0.f;
#pragma unroll
    for (int c = 0; c < 8; c++) {
        size_t o1 = ((size_t)(b * 8 + c)) * 512;
        mx1 = fmaxf(mx1, part[o1 + t]);  sm1 += part[o1 + 256 + t];
        mx2 = fmaxf(mx2, part2[o1 + t]); sm2 += part2[o1 + 256 + t];
    }
    xr[t]       = mx1 + mx2;
    xr[t + 256] = sm1 / (float)KP1 + sm2 / (float)KP2;
    __syncthreads();
    float acc = bl[t];
    const float* w = Wl + (size_t)t * 512;
    for (int kk = 0; kk < 512; kk++) acc += xr[kk] * w[kk];
    out[(size_t)b * 256 + t] = acc;
}

// ---------------- host launcher ----------------
extern "C" void kernel_launch(void* const* d_in, const int* in_sizes, int n_in,
                              void* d_out, int out_size) {
    const float* x    = (const float*)d_in[0];
    const int*   ei   = (const int*)d_in[1];
    const int*   src  = ei;
    const int*   dst  = ei + ED;
    const float* W1   = (const float*)d_in[3];
    const float* as1  = (const float*)d_in[4];
    const float* ad1  = (const float*)d_in[5];
    const float* b1   = (const float*)d_in[6];
    const float* g1   = (const float*)d_in[7];
    const float* be1  = (const float*)d_in[8];
    const float* pw1  = (const float*)d_in[9];
    const float* W2   = (const float*)d_in[10];
    const float* as2  = (const float*)d_in[11];
    const float* ad2  = (const float*)d_in[12];
    const float* b2   = (const float*)d_in[13];
    const float* g2   = (const float*)d_in[14];
    const float* be2  = (const float*)d_in[15];
    const float* pw2  = (const float*)d_in[16];
    const float* Wl   = (const float*)d_in[17];
    const float* bl   = (const float*)d_in[18];
    float* out = (float*)d_out;

    float* fb = nullptr;
    int*   ib = nullptr;
    cudaGetSymbolAddress((void**)&fb, g_f);
    cudaGetSymbolAddress((void**)&ib, g_i);

    float* h1    = fb + O_H1;
    float* out1  = fb + O_OUT1;
    float* asn1  = fb + O_ASN1;
    float* adn1  = fb + O_ADN1;
    float* bns1  = fb + O_BNS1;
    float* bns2  = fb + O_BNS2;
    float* sc1   = fb + O_SC1;
    float* sh1   = fb + O_SH1;
    float* w1a   = fb + O_W1A;
    float* score1= fb + O_SCORE1;
    float* tanh1 = fb + O_TANH1;
    float* part  = fb + O_PART;
    float* part2 = fb + O_PART2;
    float* h2    = fb + O_H2;
    float* out2  = fb + O_OUT2;
    float* asn2  = fb + O_ASN2;
    float* adn2  = fb + O_ADN2;
    float* sc2   = fb + O_SC2;
    float* sh2   = fb + O_SH2;
    float* w2a   = fb + O_W2A;
    float* score2= fb + O_SCORE2;
    float* tanh2 = fb + O_TANH2;
    int* gidx1 = ib + IO_GIDX1;
    int* inv1  = ib + IO_INV1;
    int* gidx2 = ib + IO_GIDX2;
    int* csr1  = ib + IO_CSR1;
    int* csr2  = ib + IO_CSR2;
    int* deg1  = ib + IO_DEG1;
    int* deg2  = ib + IO_DEG2;
    int* cnt1  = ib + IO_CNT;
    int* cnt2  = ib + IO_CNT + 1;

    static cudaStream_t s2 = nullptr;
    static cudaEvent_t ev0, ev1, ev2, ev3, ev5;
    if (!s2) {
        cudaStreamCreateWithFlags(&s2, cudaStreamNonBlocking);
        cudaEventCreateWithFlags(&ev0, cudaEventDisableTiming);
        cudaEventCreateWithFlags(&ev1, cudaEventDisableTiming);
        cudaEventCreateWithFlags(&ev2, cudaEventDisableTiming);
        cudaEventCreateWithFlags(&ev3, cudaEventDisableTiming);
        cudaEventCreateWithFlags(&ev5, cudaEventDisableTiming);
    }

    // fork: side stream does memsets + csr_build1 while main does sgemm1
    cudaEventRecord(ev0, 0);
    cudaStreamWaitEvent(s2, ev0, 0);
    cudaMemsetAsync(bns1, 0, 1024 * sizeof(float), s2);                    // bns1|bns2
    cudaMemsetAsync(deg1, 0, (size_t)(NN + N2 + 8) * sizeof(int), s2);     // deg1|deg2|cnt
    cudaMemsetAsync(inv1, 0xFF, (size_t)NN * sizeof(int), s2);
    csr_build<<<(ED + 255) / 256, 256, 0, s2>>>(src, dst, nullptr, deg1, csr1, ED);
    cudaEventRecord(ev1, s2);

    // ---- layer 1 (main stream) ----
    sgemm_tf32_attn<<<dim3(FD / 128, NN / 128), 256>>>(x, W1, h1, as1, ad1, asn1, adn1,
                                                       NN, FD, INDIM, nullptr, nullptr, nullptr, nullptr);
    cudaStreamWaitEvent(0, ev1, 0);
    gat_gather<<<2048, 256>>>(csr1, deg1, asn1, adn1, h1, b1, out1, bns1, NN, (2 * NN) / 2048,
                              g1, be1, pw1, sc1, sh1, w1a, 1.0f / NN, cnt1);
    pool_score<<<NN / 32, 256>>>(out1, w1a, score1, NN);
    topk_select<<<BT, 512>>>(score1, NPG, KP1, gidx1, tanh1, inv1);
    cudaEventRecord(ev2, 0);

    // side stream: csr_build2 + layer-1 readout (both need only topk1 results)
    cudaStreamWaitEvent(s2, ev2, 0);
    csr_build<<<(ED + 255) / 256, 256, 0, s2>>>(src, dst, inv1, deg2, csr2, ED);
    cudaEventRecord(ev3, s2);
    readout_s1<<<dim3(BT, 8), 256, 0, s2>>>(out1, sc1, sh1, gidx1, tanh1, KP1, part);
    cudaEventRecord(ev5, s2);

    // ---- layer 2 (main stream): sgemm reads pooled rows via gidx with BN+tanh inline ----
    sgemm_tf32_attn<<<dim3(FD / 128, N2 / 128), 256>>>(out1, W2, h2, as2, ad2, asn2, adn2,
                                                       N2, FD, FD, gidx1, sc1, sh1, tanh1);
    cudaStreamWaitEvent(0, ev3, 0);
    gat_gather<<<1024, 256>>>(csr2, deg2, asn2, adn2, h2, b2, out2, bns2, N2, (2 * N2) / 1024,
                              g2, be2, pw2, sc2, sh2, w2a, 1.0f / N2, cnt2);
    pool_score<<<N2 / 32, 256>>>(out2, w2a, score2, N2);
    topk_select<<<BT, 512>>>(score2, KP1, KP2, gidx2, tanh2, nullptr);
    readout_s1<<<dim3(BT, 8), 256>>>(out2, sc2, sh2, gidx2, tanh2, KP2, part2);

    // ---- final (join side stream) ----
    cudaStreamWaitEvent(0, ev5, 0);
    final_linear<<<BT, 256>>>(part, part2, Wl, bl, out);
}